// round 4
// baseline (speedup 1.0000x reference)
#include <cuda_runtime.h>

typedef unsigned long long ull;

#define NTOK 48
#define DM   128
#define TS   132
#define SS   49

// ---- kernel A smem (floats) ----
#define SM_TGT  0            // 48*132 = 6336
#define SM_P    6336         // 64*49  = 3136
#define SM_S2   9472         // 64*132 = 8448
#define A_SMEM_FLOATS 17920
#define A_SMEM_BYTES  (A_SMEM_FLOATS*4)   // 71680

// ---- kernel B smem (floats) ----
#define GB 8                 // batches per CTA
#define BROWS 64             // GB*8
#define SMB_XA  0            // 64*132 = 8448
#define SMB_X   8448
#define SMB_N   16896
#define SMB_W   25344        // 128*128 = 16384
#define SMB_Q   41728        // 8*128 = 1024
#define SMB_CB  42752        // 5*128 = 640
#define B_SMEM_FLOATS 43392
#define B_SMEM_BYTES  (B_SMEM_FLOATS*4)   // 173568

#define MAXB 16384

// ---------------- device-global precomputed / scratch --------
__device__ __align__(16) float g_weff[64 * DM];
__device__ __align__(16) float g_WvT [DM * DM];
__device__ __align__(16) float g_WpT [DM * DM];
__device__ __align__(16) float g_Wf1T[DM * DM];
__device__ __align__(16) float g_Wf2T[DM * DM];
__device__ __align__(16) float g_xatt[(size_t)MAXB * 8 * DM];

// ---------------- packed fp32x2 helpers ----------------
__device__ __forceinline__ void ffma2(ull& d, ull a, ull b) {
    asm("fma.rn.f32x2 %0, %1, %2, %0;" : "+l"(d) : "l"(a), "l"(b));
}
__device__ __forceinline__ ull dup2(float x) {
    ull r; asm("mov.b64 %0, {%1, %1};" : "=l"(r) : "f"(x)); return r;
}
__device__ __forceinline__ void unpack2(ull v, float& lo, float& hi) {
    asm("mov.b64 {%0, %1}, %2;" : "=f"(lo), "=f"(hi) : "l"(v));
}
__device__ __forceinline__ float hsum2(ull v) {
    float lo, hi; unpack2(v, lo, hi); return lo + hi;
}

// =====================================================================
// Prologue, 5 blocks: block 0 = LN->q0->weff; blocks 1-4 = transposes.
// =====================================================================
__global__ void k_pre(const float* __restrict__ q, const float* __restrict__ g1,
                      const float* __restrict__ b1, const float* __restrict__ Wq,
                      const float* __restrict__ bq, const float* __restrict__ Wk,
                      const float* __restrict__ Wv, const float* __restrict__ Wp,
                      const float* __restrict__ Wf1, const float* __restrict__ Wf2)
{
    const int tid = threadIdx.x;
    if (blockIdx.x == 0) {
        __shared__ float qn[8][DM];
        __shared__ float q0s[8][DM];
        const int w = tid >> 5, lane = tid & 31;

        // LN: warp w handles query row w
        {
            float4 v = *(const float4*)(q + w*DM + lane*4);
            float s  = v.x + v.y + v.z + v.w;
            float sq = v.x*v.x + v.y*v.y + v.z*v.z + v.w*v.w;
            #pragma unroll
            for (int o = 16; o > 0; o >>= 1) {
                s  += __shfl_xor_sync(0xffffffffu, s,  o);
                sq += __shfl_xor_sync(0xffffffffu, sq, o);
            }
            float m  = s * (1.f/DM);
            float var = sq * (1.f/DM) - m*m;
            float rs = rsqrtf(var + 1e-5f);
            const int c = lane*4;
            qn[w][c+0] = (v.x - m)*rs*g1[c+0] + b1[c+0];
            qn[w][c+1] = (v.y - m)*rs*g1[c+1] + b1[c+1];
            qn[w][c+2] = (v.z - m)*rs*g1[c+2] + b1[c+2];
            qn[w][c+3] = (v.w - m)*rs*g1[c+3] + b1[c+3];
        }
        __syncthreads();

        // q0 = qn @ Wq^T + bq
        for (int o = tid; o < 8*DM; o += 256) {
            int r = o >> 7, c = o & 127;
            float a = bq[c];
            const float4* wr = (const float4*)(Wq + c*DM);
            #pragma unroll 8
            for (int t4 = 0; t4 < 32; t4++) {
                float4 ww = wr[t4];
                a += qn[r][t4*4+0]*ww.x + qn[r][t4*4+1]*ww.y
                   + qn[r][t4*4+2]*ww.z + qn[r][t4*4+3]*ww.w;
            }
            q0s[r][c] = a;
        }
        __syncthreads();

        // weff[p][t] = 0.25 * sum_d q0[r][h*16+d] * Wk[h*16+d][t]
        for (int o = tid; o < 64*DM; o += 256) {
            int p = o >> 7, t = o & 127;
            int r = p >> 3, h = p & 7;
            float a = 0.f;
            #pragma unroll
            for (int d = 0; d < 16; d++)
                a += q0s[r][h*16 + d] * Wk[(h*16 + d)*DM + t];
            g_weff[o] = 0.25f * a;
        }
    } else {
        // transpose matrix (blockIdx.x-1) via 32x32 smem tiles
        const float* src; float* dst;
        switch (blockIdx.x) {
            case 1: src = Wv;  dst = g_WvT;  break;
            case 2: src = Wp;  dst = g_WpT;  break;
            case 3: src = Wf1; dst = g_Wf1T; break;
            default: src = Wf2; dst = g_Wf2T; break;
        }
        __shared__ float tile[32][33];
        const int tx = tid & 31, ty0 = tid >> 5;
        for (int t = 0; t < 16; t++) {
            const int ti = t >> 2, tj = t & 3;
            #pragma unroll
            for (int k = 0; k < 4; k++) {
                int ty = ty0 + k*8;
                tile[ty][tx] = src[(ti*32+ty)*DM + tj*32 + tx];
            }
            __syncthreads();
            #pragma unroll
            for (int k = 0; k < 4; k++) {
                int ty = ty0 + k*8;
                dst[(tj*32+ty)*DM + ti*32 + tx] = tile[tx][ty];
            }
            __syncthreads();
        }
    }
}

// =====================================================================
// Kernel A: one CTA per batch. scores -> softmax -> S2 -> head-sliced Wv.
// =====================================================================
__global__ __launch_bounds__(256, 3)
void k_attn(const float* __restrict__ tgt, const float* __restrict__ bv)
{
    extern __shared__ float sm[];
    const int tid = threadIdx.x;
    const int b   = blockIdx.x;

    // -------- stage tgt[b] --------
    {
        const float4* t4 = (const float4*)(tgt + (size_t)b * (NTOK*DM));
        #pragma unroll
        for (int k = 0; k < 6; k++) {
            int i = tid + k*256;
            float4 v = t4[i];
            int r = i >> 5, c = (i & 31) << 2;
            *(float4*)(sm + SM_TGT + r*TS + c) = v;
        }
    }
    __syncthreads();

    // -------- scores (windowed) --------
    if (tid < 128) {
        const int pa = (tid >> 4) * 2;
        const int jt = (tid & 15) * 3;
        const ulonglong2* w0 = (const ulonglong2*)(g_weff + pa*DM);
        const ulonglong2* w1 = (const ulonglong2*)(g_weff + (pa+1)*DM);
        const ulonglong2* t0 = (const ulonglong2*)(sm + SM_TGT + (jt+0)*TS);
        const ulonglong2* t1 = (const ulonglong2*)(sm + SM_TGT + (jt+1)*TS);
        const ulonglong2* t2 = (const ulonglong2*)(sm + SM_TGT + (jt+2)*TS);
        ull acc[2][3] = {};
        #pragma unroll 4
        for (int d = 0; d < 32; d++) {
            ulonglong2 a0 = w0[d], a1 = w1[d];
            ulonglong2 c0 = t0[d], c1 = t1[d], c2 = t2[d];
            ffma2(acc[0][0], a0.x, c0.x); ffma2(acc[0][0], a0.y, c0.y);
            ffma2(acc[0][1], a0.x, c1.x); ffma2(acc[0][1], a0.y, c1.y);
            ffma2(acc[0][2], a0.x, c2.x); ffma2(acc[0][2], a0.y, c2.y);
            ffma2(acc[1][0], a1.x, c0.x); ffma2(acc[1][0], a1.y, c0.y);
            ffma2(acc[1][1], a1.x, c1.x); ffma2(acc[1][1], a1.y, c1.y);
            ffma2(acc[1][2], a1.x, c2.x); ffma2(acc[1][2], a1.y, c2.y);
        }
        #pragma unroll
        for (int a = 0; a < 2; a++)
            #pragma unroll
            for (int c = 0; c < 3; c++)
                sm[SM_P + (pa+a)*SS + jt + c] = hsum2(acc[a][c]);
    } else if (tid < 224) {
        const int t2i = tid - 128;
        const int p   = 16 + (t2i >> 2) * 2;
        const int mg  = t2i & 3;
        const int r   = p >> 3, wi = r - 2;
        const int hw  = (wi/3)*4, ww = (wi%3)*2;
        const int m0  = mg*2;
        const int j0  = (hw + mg)*6 + ww;
        const ulonglong2* w0 = (const ulonglong2*)(g_weff + p*DM);
        const ulonglong2* w1 = (const ulonglong2*)(g_weff + (p+1)*DM);
        const ulonglong2* t0 = (const ulonglong2*)(sm + SM_TGT + (j0+0)*TS);
        const ulonglong2* t1 = (const ulonglong2*)(sm + SM_TGT + (j0+1)*TS);
        ull acc[2][2] = {};
        #pragma unroll 4
        for (int d = 0; d < 32; d++) {
            ulonglong2 a0 = w0[d], a1 = w1[d];
            ulonglong2 c0 = t0[d], c1 = t1[d];
            ffma2(acc[0][0], a0.x, c0.x); ffma2(acc[0][0], a0.y, c0.y);
            ffma2(acc[0][1], a0.x, c1.x); ffma2(acc[0][1], a0.y, c1.y);
            ffma2(acc[1][0], a1.x, c0.x); ffma2(acc[1][0], a1.y, c0.y);
            ffma2(acc[1][1], a1.x, c1.x); ffma2(acc[1][1], a1.y, c1.y);
        }
        sm[SM_P + p*SS     + m0    ] = hsum2(acc[0][0]);
        sm[SM_P + p*SS     + m0 + 1] = hsum2(acc[0][1]);
        sm[SM_P + (p+1)*SS + m0    ] = hsum2(acc[1][0]);
        sm[SM_P + (p+1)*SS + m0 + 1] = hsum2(acc[1][1]);
    }
    __syncthreads();

    // -------- softmax per pair (compact rows) --------
    if (tid < 64) {
        const int n = (tid < 16) ? 48 : 8;
        float* row = sm + SM_P + tid*SS;
        float mx = -1e30f;
        for (int j = 0; j < n; j++) mx = fmaxf(mx, row[j]);
        float sum = 0.f;
        for (int j = 0; j < n; j++) { float e = expf(row[j] - mx); row[j] = e; sum += e; }
        float inv = 1.f / sum;
        for (int j = 0; j < n; j++) row[j] *= inv;
    }
    __syncthreads();

    // -------- S2 = P @ tgt (windowed weighted token sums) --------
    if (tid < 128) {
        const int pi = tid >> 3;             // 0..15
        const int ch = (tid & 7) * 16;
        ull acc[8] = {};
        const float* pr = sm + SM_P + pi*SS;
        for (int j = 0; j < 48; j++) {
            ull pj = dup2(pr[j]);
            const ulonglong2* tr = (const ulonglong2*)(sm + SM_TGT + j*TS + ch);
            ulonglong2 u0 = tr[0], u1 = tr[1], u2 = tr[2], u3 = tr[3];
            ffma2(acc[0], pj, u0.x); ffma2(acc[1], pj, u0.y);
            ffma2(acc[2], pj, u1.x); ffma2(acc[3], pj, u1.y);
            ffma2(acc[4], pj, u2.x); ffma2(acc[5], pj, u2.y);
            ffma2(acc[6], pj, u3.x); ffma2(acc[7], pj, u3.y);
        }
        ull* o = (ull*)(sm + SM_S2 + pi*TS + ch);
        #pragma unroll
        for (int k = 0; k < 8; k++) o[k] = acc[k];
    } else {
        const int t2i = tid - 128;
        #pragma unroll
        for (int u = 0; u < 3; u++) {
            const int p  = 16 + u*16 + (t2i >> 3);
            const int ch = (t2i & 7) * 16;
            const int r  = p >> 3, wi = r - 2;
            const int hw = (wi/3)*4, ww = (wi%3)*2;
            ull acc[8] = {};
            const float* pr = sm + SM_P + p*SS;
            #pragma unroll
            for (int m = 0; m < 8; m++) {
                const int j = (hw + (m>>1))*6 + ww + (m&1);
                ull pj = dup2(pr[m]);
                const ulonglong2* tr = (const ulonglong2*)(sm + SM_TGT + j*TS + ch);
                ulonglong2 u0 = tr[0], u1 = tr[1], u2 = tr[2], u3 = tr[3];
                ffma2(acc[0], pj, u0.x); ffma2(acc[1], pj, u0.y);
                ffma2(acc[2], pj, u1.x); ffma2(acc[3], pj, u1.y);
                ffma2(acc[4], pj, u2.x); ffma2(acc[5], pj, u2.y);
                ffma2(acc[6], pj, u3.x); ffma2(acc[7], pj, u3.y);
            }
            ull* o = (ull*)(sm + SM_S2 + p*TS + ch);
            #pragma unroll
            for (int k = 0; k < 8; k++) o[k] = acc[k];
        }
    }
    __syncthreads();

    // -------- x_att: warp = head h; x_att[r][h*16+c] = WvT-slice . S2[r*8+h] + bv
    // Lane (r, cq): cooperative S2 load (conflict-free) + shfl broadcast.
    {
        const int h    = tid >> 5;
        const int lane = tid & 31;
        const int r    = lane >> 2;
        const int cq   = lane & 3;
        const int col  = h*16 + cq*4;
        const float* s2row = sm + SM_S2 + (r*8 + h)*TS;
        ull a01 = 0ull, a23 = 0ull;
        #pragma unroll 4
        for (int t4 = 0; t4 < 32; t4++) {
            float myv = s2row[t4*4 + cq];       // banks (4h+4t4+cq): conflict-free
            #pragma unroll
            for (int k = 0; k < 4; k++) {
                float f = __shfl_sync(0xffffffffu, myv, (lane & 28) + k);
                ulonglong2 w2 = *(const ulonglong2*)(g_WvT + (t4*4+k)*DM + col);
                ull fd = dup2(f);
                ffma2(a01, fd, w2.x); ffma2(a23, fd, w2.y);
            }
        }
        float4 o; unpack2(a01, o.x, o.y); unpack2(a23, o.z, o.w);
        float4 bv4 = *(const float4*)(bv + col);
        o.x += bv4.x; o.y += bv4.y; o.z += bv4.z; o.w += bv4.w;
        *(float4*)(g_xatt + ((size_t)b*8 + r)*DM + col) = o;
    }
}

// =====================================================================
// Kernel B: GB batches per CTA. Wp + residual + LN + FFN.
// =====================================================================
__device__ __forceinline__ void gemm64(const float* __restrict__ A,
                                       const float* __restrict__ W,
                                       int w, int lane, ull acc[8][2])
{
    const int r0  = w * 8;
    const int col = lane * 4;
    for (int k4 = 0; k4 < 32; k4++) {
        float4 a[8];
        #pragma unroll
        for (int r = 0; r < 8; r++)
            a[r] = *(const float4*)(A + (r0+r)*TS + k4*4);
        ulonglong2 b0 = *(const ulonglong2*)(W + (k4*4+0)*DM + col);
        ulonglong2 b1 = *(const ulonglong2*)(W + (k4*4+1)*DM + col);
        ulonglong2 b2 = *(const ulonglong2*)(W + (k4*4+2)*DM + col);
        ulonglong2 b3 = *(const ulonglong2*)(W + (k4*4+3)*DM + col);
        #pragma unroll
        for (int r = 0; r < 8; r++) {
            ffma2(acc[r][0], dup2(a[r].x), b0.x); ffma2(acc[r][1], dup2(a[r].x), b0.y);
            ffma2(acc[r][0], dup2(a[r].y), b1.x); ffma2(acc[r][1], dup2(a[r].y), b1.y);
            ffma2(acc[r][0], dup2(a[r].z), b2.x); ffma2(acc[r][1], dup2(a[r].z), b2.y);
            ffma2(acc[r][0], dup2(a[r].w), b3.x); ffma2(acc[r][1], dup2(a[r].w), b3.y);
        }
    }
}

__global__ __launch_bounds__(256, 1)
void k_ffn(const float* __restrict__ query, const float* __restrict__ bp,
           const float* __restrict__ g2, const float* __restrict__ b2,
           const float* __restrict__ bf1, const float* __restrict__ bf2,
           float* __restrict__ out, int Bn)
{
    extern __shared__ float sm[];
    const int tid  = threadIdx.x;
    const int w    = tid >> 5;
    const int lane = tid & 31;
    const int col  = lane * 4;
    const int b0   = blockIdx.x * GB;
    const int rows_valid = (Bn - b0 >= GB) ? BROWS : (Bn - b0) * 8;

    {
        const float4* src = (const float4*)(g_xatt + (size_t)b0 * 8 * DM);
        #pragma unroll
        for (int k = 0; k < 8; k++) {
            int i = tid + k*256;
            int r = i >> 5, c4 = (i & 31) << 2;
            float4 v = (r < rows_valid) ? src[i] : make_float4(0.f,0.f,0.f,0.f);
            *(float4*)(sm + SMB_XA + r*TS + c4) = v;
        }
        const float4* wsrc = (const float4*)g_WpT;
        float4* wdst = (float4*)(sm + SMB_W);
        #pragma unroll
        for (int k = 0; k < 16; k++) wdst[tid + k*256] = wsrc[tid + k*256];
        ((float4*)(sm + SMB_Q))[tid] = ((const float4*)query)[tid];
        if (tid < 128) {
            sm[SMB_CB +       tid] = bp [tid];
            sm[SMB_CB + 128 + tid] = g2 [tid];
            sm[SMB_CB + 256 + tid] = b2 [tid];
            sm[SMB_CB + 384 + tid] = bf1[tid];
            sm[SMB_CB + 512 + tid] = bf2[tid];
        }
    }
    __syncthreads();

    // GEMM1: x = query + x_att @ WpT + bp
    {
        ull acc[8][2] = {};
        gemm64(sm + SMB_XA, sm + SMB_W, w, lane, acc);
        #pragma unroll
        for (int r = 0; r < 8; r++) {
            const int row = w*8 + r;
            float lo0, hi0, lo1, hi1;
            unpack2(acc[r][0], lo0, hi0); unpack2(acc[r][1], lo1, hi1);
            const float* q = sm + SMB_Q + (row & 7)*DM + col;
            const float* bpc = sm + SMB_CB + col;
            float* dst = sm + SMB_X + row*TS + col;
            dst[0] = q[0] + bpc[0] + lo0;
            dst[1] = q[1] + bpc[1] + hi0;
            dst[2] = q[2] + bpc[2] + lo1;
            dst[3] = q[3] + bpc[3] + hi1;
        }
    }
    __syncthreads();

    // LN -> s_n ; restage W <- Wf1T
    {
        #pragma unroll
        for (int r = 0; r < 8; r++) {
            const int row = w*8 + r;
            const float* xr = sm + SMB_X + row*TS + col;
            float v0 = xr[0], v1 = xr[1], v2 = xr[2], v3 = xr[3];
            float sum = v0+v1+v2+v3;
            float sq  = v0*v0+v1*v1+v2*v2+v3*v3;
            #pragma unroll
            for (int o = 16; o > 0; o >>= 1) {
                sum += __shfl_xor_sync(0xffffffffu, sum, o);
                sq  += __shfl_xor_sync(0xffffffffu, sq,  o);
            }
            float m   = sum * (1.f/DM);
            float var = sq * (1.f/DM) - m*m;
            float rs  = rsqrtf(var + 1e-5f);
            float* nr = sm + SMB_N + row*TS + col;
            const float* g2c = sm + SMB_CB + 128 + col;
            const float* b2c = sm + SMB_CB + 256 + col;
            nr[0] = (v0 - m)*rs*g2c[0] + b2c[0];
            nr[1] = (v1 - m)*rs*g2c[1] + b2c[1];
            nr[2] = (v2 - m)*rs*g2c[2] + b2c[2];
            nr[3] = (v3 - m)*rs*g2c[3] + b2c[3];
        }
        const float4* wsrc = (const float4*)g_Wf1T;
        float4* wdst = (float4*)(sm + SMB_W);
        #pragma unroll
        for (int k = 0; k < 16; k++) wdst[tid + k*256] = wsrc[tid + k*256];
    }
    __syncthreads();

    // GEMM2: h = gelu(xn @ Wf1T + bf1)
    {
        ull acc[8][2] = {};
        gemm64(sm + SMB_N, sm + SMB_W, w, lane, acc);
        __syncthreads();
        #pragma unroll
        for (int r = 0; r < 8; r++) {
            const int row = w*8 + r;
            float z[4];
            unpack2(acc[r][0], z[0], z[1]); unpack2(acc[r][1], z[2], z[3]);
            float* nr = sm + SMB_N + row*TS + col;
            const float* bc = sm + SMB_CB + 384 + col;
            #pragma unroll
            for (int k = 0; k < 4; k++) {
                float zz = z[k] + bc[k];
                nr[k] = 0.5f * zz * (1.f + erff(zz * 0.7071067811865476f));
            }
        }
        const float4* wsrc = (const float4*)g_Wf2T;
        float4* wdst = (float4*)(sm + SMB_W);
        #pragma unroll
        for (int k = 0; k < 16; k++) wdst[tid + k*256] = wsrc[tid + k*256];
    }
    __syncthreads();

    // GEMM3: out = x + h @ Wf2T + bf2
    {
        ull acc[8][2] = {};
        gemm64(sm + SMB_N, sm + SMB_W, w, lane, acc);
        #pragma unroll
        for (int r = 0; r < 8; r++) {
            const int row = w*8 + r;
            if (row >= rows_valid) continue;
            float lo0, hi0, lo1, hi1;
            unpack2(acc[r][0], lo0, hi0); unpack2(acc[r][1], lo1, hi1);
            const float* xr = sm + SMB_X + row*TS + col;
            const float* bc = sm + SMB_CB + 512 + col;
            float4 res;
            res.x = xr[0] + bc[0] + lo0;
            res.y = xr[1] + bc[1] + hi0;
            res.z = xr[2] + bc[2] + lo1;
            res.w = xr[3] + bc[3] + hi1;
            *(float4*)(out + ((size_t)b0*8 + row)*DM + col) = res;
        }
    }
}

// =====================================================================
extern "C" void kernel_launch(void* const* d_in, const int* in_sizes, int n_in,
                              void* d_out, int out_size)
{
    const float* query = (const float*)d_in[0];
    const float* tgt   = (const float*)d_in[1];
    const float* g1    = (const float*)d_in[2];
    const float* b1    = (const float*)d_in[3];
    const float* Wq    = (const float*)d_in[4];
    const float* bq    = (const float*)d_in[5];
    const float* Wk    = (const float*)d_in[6];
    // d_in[7] = bk: drops out (softmax shift invariance)
    const float* Wv    = (const float*)d_in[8];
    const float* bv    = (const float*)d_in[9];
    const float* Wp    = (const float*)d_in[10];
    const float* bp    = (const float*)d_in[11];
    const float* g2    = (const float*)d_in[12];
    const float* b2    = (const float*)d_in[13];
    const float* Wf1   = (const float*)d_in[14];
    const float* bf1   = (const float*)d_in[15];
    const float* Wf2   = (const float*)d_in[16];
    const float* bf2   = (const float*)d_in[17];

    const int B = in_sizes[1] / (NTOK * DM);

    cudaFuncSetAttribute(k_attn, cudaFuncAttributeMaxDynamicSharedMemorySize, A_SMEM_BYTES);
    cudaFuncSetAttribute(k_ffn,  cudaFuncAttributeMaxDynamicSharedMemorySize, B_SMEM_BYTES);

    k_pre<<<5, 256>>>(query, g1, b1, Wq, bq, Wk, Wv, Wp, Wf1, Wf2);
    k_attn<<<B, 256, A_SMEM_BYTES>>>(tgt, bv);
    k_ffn<<<(B + GB - 1)/GB, 256, B_SMEM_BYTES>>>(query, bp, g2, b2, bf1, bf2,
                                                  (float*)d_out, B);
}

// round 5
// speedup vs baseline: 1.6855x; 1.6855x over previous
#include <cuda_runtime.h>

typedef unsigned long long ull;

#define NTOK 48
#define DM   128
#define TS   132
#define SS   49

// ---- kernel A smem (floats): vproj overlays tgt ----
#define SM_TGT  0            // 48*132 = 6336 (tgt, then vproj)
#define SM_P    6336         // 64*49  = 3136
#define A_SMEM_FLOATS 9472
#define A_SMEM_BYTES  (A_SMEM_FLOATS*4)   // 37888

// ---- kernel B smem (floats) ----
#define GB 8
#define BROWS 64
#define SMB_XA  0            // 64*132 = 8448
#define SMB_X   8448
#define SMB_N   16896
#define SMB_W   25344        // 128*128 = 16384
#define SMB_Q   41728        // 8*128 = 1024
#define SMB_CB  42752        // 5*128 = 640
#define B_SMEM_FLOATS 43392
#define B_SMEM_BYTES  (B_SMEM_FLOATS*4)   // 173568

#define MAXB 16384

// ---------------- device-global precomputed / scratch --------
__device__ __align__(16) float g_weff[64 * DM];
__device__ __align__(16) float g_WvT [DM * DM];
__device__ __align__(16) float g_WpT [DM * DM];
__device__ __align__(16) float g_Wf1T[DM * DM];
__device__ __align__(16) float g_Wf2T[DM * DM];
__device__ __align__(16) float g_xatt[(size_t)MAXB * 8 * DM];

// ---------------- packed fp32x2 helpers ----------------
__device__ __forceinline__ void ffma2(ull& d, ull a, ull b) {
    asm("fma.rn.f32x2 %0, %1, %2, %0;" : "+l"(d) : "l"(a), "l"(b));
}
__device__ __forceinline__ ull dup2(float x) {
    ull r; asm("mov.b64 %0, {%1, %1};" : "=l"(r) : "f"(x)); return r;
}
__device__ __forceinline__ void unpack2(ull v, float& lo, float& hi) {
    asm("mov.b64 {%0, %1}, %2;" : "=f"(lo), "=f"(hi) : "l"(v));
}
__device__ __forceinline__ float hsum2(ull v) {
    float lo, hi; unpack2(v, lo, hi); return lo + hi;
}

// =====================================================================
// Prologue, 5 blocks: block 0 = LN->q0->weff; blocks 1-4 = transposes.
// =====================================================================
__global__ void k_pre(const float* __restrict__ q, const float* __restrict__ g1,
                      const float* __restrict__ b1, const float* __restrict__ Wq,
                      const float* __restrict__ bq, const float* __restrict__ Wk,
                      const float* __restrict__ Wv, const float* __restrict__ Wp,
                      const float* __restrict__ Wf1, const float* __restrict__ Wf2)
{
    const int tid = threadIdx.x;
    if (blockIdx.x == 0) {
        __shared__ float qn[8][DM];
        __shared__ float q0s[8][DM];
        const int w = tid >> 5, lane = tid & 31;

        {
            float4 v = *(const float4*)(q + w*DM + lane*4);
            float s  = v.x + v.y + v.z + v.w;
            float sq = v.x*v.x + v.y*v.y + v.z*v.z + v.w*v.w;
            #pragma unroll
            for (int o = 16; o > 0; o >>= 1) {
                s  += __shfl_xor_sync(0xffffffffu, s,  o);
                sq += __shfl_xor_sync(0xffffffffu, sq, o);
            }
            float m  = s * (1.f/DM);
            float var = sq * (1.f/DM) - m*m;
            float rs = rsqrtf(var + 1e-5f);
            const int c = lane*4;
            qn[w][c+0] = (v.x - m)*rs*g1[c+0] + b1[c+0];
            qn[w][c+1] = (v.y - m)*rs*g1[c+1] + b1[c+1];
            qn[w][c+2] = (v.z - m)*rs*g1[c+2] + b1[c+2];
            qn[w][c+3] = (v.w - m)*rs*g1[c+3] + b1[c+3];
        }
        __syncthreads();

        for (int o = tid; o < 8*DM; o += 256) {
            int r = o >> 7, c = o & 127;
            float a = bq[c];
            const float4* wr = (const float4*)(Wq + c*DM);
            #pragma unroll 8
            for (int t4 = 0; t4 < 32; t4++) {
                float4 ww = wr[t4];
                a += qn[r][t4*4+0]*ww.x + qn[r][t4*4+1]*ww.y
                   + qn[r][t4*4+2]*ww.z + qn[r][t4*4+3]*ww.w;
            }
            q0s[r][c] = a;
        }
        __syncthreads();

        for (int o = tid; o < 64*DM; o += 256) {
            int p = o >> 7, t = o & 127;
            int r = p >> 3, h = p & 7;
            float a = 0.f;
            #pragma unroll
            for (int d = 0; d < 16; d++)
                a += q0s[r][h*16 + d] * Wk[(h*16 + d)*DM + t];
            g_weff[o] = 0.25f * a;
        }
    } else {
        const float* src; float* dst;
        switch (blockIdx.x) {
            case 1: src = Wv;  dst = g_WvT;  break;
            case 2: src = Wp;  dst = g_WpT;  break;
            case 3: src = Wf1; dst = g_Wf1T; break;
            default: src = Wf2; dst = g_Wf2T; break;
        }
        __shared__ float tile[32][33];
        const int tx = tid & 31, ty0 = tid >> 5;
        for (int t = 0; t < 16; t++) {
            const int ti = t >> 2, tj = t & 3;
            #pragma unroll
            for (int k = 0; k < 4; k++) {
                int ty = ty0 + k*8;
                tile[ty][tx] = src[(ti*32+ty)*DM + tj*32 + tx];
            }
            __syncthreads();
            #pragma unroll
            for (int k = 0; k < 4; k++) {
                int ty = ty0 + k*8;
                dst[(tj*32+ty)*DM + ti*32 + tx] = tile[tx][ty];
            }
            __syncthreads();
        }
    }
}

// =====================================================================
// Kernel A: one CTA per batch. scores -> softmax -> vproj (overlay) -> x_att.
// =====================================================================
__global__ __launch_bounds__(256, 3)
void k_attn(const float* __restrict__ tgt, const float* __restrict__ bv)
{
    extern __shared__ float sm[];
    const int tid = threadIdx.x;
    const int b   = blockIdx.x;

    // -------- stage tgt[b] --------
    {
        const float4* t4 = (const float4*)(tgt + (size_t)b * (NTOK*DM));
        #pragma unroll
        for (int k = 0; k < 6; k++) {
            int i = tid + k*256;
            float4 v = t4[i];
            int r = i >> 5, c = (i & 31) << 2;
            *(float4*)(sm + SM_TGT + r*TS + c) = v;
        }
    }
    __syncthreads();

    // -------- scores (windowed) --------
    if (tid < 128) {
        const int pa = (tid >> 4) * 2;
        const int jt = (tid & 15) * 3;
        const ulonglong2* w0 = (const ulonglong2*)(g_weff + pa*DM);
        const ulonglong2* w1 = (const ulonglong2*)(g_weff + (pa+1)*DM);
        const ulonglong2* t0 = (const ulonglong2*)(sm + SM_TGT + (jt+0)*TS);
        const ulonglong2* t1 = (const ulonglong2*)(sm + SM_TGT + (jt+1)*TS);
        const ulonglong2* t2 = (const ulonglong2*)(sm + SM_TGT + (jt+2)*TS);
        ull acc[2][3] = {};
        #pragma unroll 4
        for (int d = 0; d < 32; d++) {
            ulonglong2 a0 = w0[d], a1 = w1[d];
            ulonglong2 c0 = t0[d], c1 = t1[d], c2 = t2[d];
            ffma2(acc[0][0], a0.x, c0.x); ffma2(acc[0][0], a0.y, c0.y);
            ffma2(acc[0][1], a0.x, c1.x); ffma2(acc[0][1], a0.y, c1.y);
            ffma2(acc[0][2], a0.x, c2.x); ffma2(acc[0][2], a0.y, c2.y);
            ffma2(acc[1][0], a1.x, c0.x); ffma2(acc[1][0], a1.y, c0.y);
            ffma2(acc[1][1], a1.x, c1.x); ffma2(acc[1][1], a1.y, c1.y);
            ffma2(acc[1][2], a1.x, c2.x); ffma2(acc[1][2], a1.y, c2.y);
        }
        #pragma unroll
        for (int a = 0; a < 2; a++)
            #pragma unroll
            for (int c = 0; c < 3; c++)
                sm[SM_P + (pa+a)*SS + jt + c] = hsum2(acc[a][c]);
    } else if (tid < 224) {
        const int t2i = tid - 128;
        const int p   = 16 + (t2i >> 2) * 2;
        const int mg  = t2i & 3;
        const int r   = p >> 3, wi = r - 2;
        const int hw  = (wi/3)*4, ww = (wi%3)*2;
        const int m0  = mg*2;
        const int j0  = (hw + mg)*6 + ww;
        const ulonglong2* w0 = (const ulonglong2*)(g_weff + p*DM);
        const ulonglong2* w1 = (const ulonglong2*)(g_weff + (p+1)*DM);
        const ulonglong2* t0 = (const ulonglong2*)(sm + SM_TGT + (j0+0)*TS);
        const ulonglong2* t1 = (const ulonglong2*)(sm + SM_TGT + (j0+1)*TS);
        ull acc[2][2] = {};
        #pragma unroll 4
        for (int d = 0; d < 32; d++) {
            ulonglong2 a0 = w0[d], a1 = w1[d];
            ulonglong2 c0 = t0[d], c1 = t1[d];
            ffma2(acc[0][0], a0.x, c0.x); ffma2(acc[0][0], a0.y, c0.y);
            ffma2(acc[0][1], a0.x, c1.x); ffma2(acc[0][1], a0.y, c1.y);
            ffma2(acc[1][0], a1.x, c0.x); ffma2(acc[1][0], a1.y, c0.y);
            ffma2(acc[1][1], a1.x, c1.x); ffma2(acc[1][1], a1.y, c1.y);
        }
        sm[SM_P + p*SS     + m0    ] = hsum2(acc[0][0]);
        sm[SM_P + p*SS     + m0 + 1] = hsum2(acc[0][1]);
        sm[SM_P + (p+1)*SS + m0    ] = hsum2(acc[1][0]);
        sm[SM_P + (p+1)*SS + m0 + 1] = hsum2(acc[1][1]);
    }
    __syncthreads();

    // -------- softmax per pair (compact rows); non-softmax warps fall through --------
    if (tid < 64) {
        const int n = (tid < 16) ? 48 : 8;
        float* row = sm + SM_P + tid*SS;
        float mx = -1e30f;
        for (int j = 0; j < n; j++) mx = fmaxf(mx, row[j]);
        float sum = 0.f;
        for (int j = 0; j < n; j++) { float e = expf(row[j] - mx); row[j] = e; sum += e; }
        float inv = 1.f / sum;
        for (int j = 0; j < n; j++) row[j] *= inv;
    }

    // -------- vproj[j] = tgt[j] @ WvT + bv, accumulate in regs, overlay onto tgt --------
    // Each warp reads ONLY its own 6 rows and writes those same 6 rows: no sync needed.
    {
        const int w    = tid >> 5;
        const int lane = tid & 31;
        const int j0   = w * 6;
        const int col  = lane * 4;
        ull acc[6][2] = {};
        for (int k4 = 0; k4 < 32; k4++) {
            float4 a[6];
            #pragma unroll
            for (int r = 0; r < 6; r++)
                a[r] = *(const float4*)(sm + SM_TGT + (j0+r)*TS + k4*4);
            ulonglong2 b0 = *(const ulonglong2*)(g_WvT + (k4*4+0)*DM + col);
            ulonglong2 b1 = *(const ulonglong2*)(g_WvT + (k4*4+1)*DM + col);
            ulonglong2 b2 = *(const ulonglong2*)(g_WvT + (k4*4+2)*DM + col);
            ulonglong2 b3 = *(const ulonglong2*)(g_WvT + (k4*4+3)*DM + col);
            #pragma unroll
            for (int r = 0; r < 6; r++) {
                ffma2(acc[r][0], dup2(a[r].x), b0.x); ffma2(acc[r][1], dup2(a[r].x), b0.y);
                ffma2(acc[r][0], dup2(a[r].y), b1.x); ffma2(acc[r][1], dup2(a[r].y), b1.y);
                ffma2(acc[r][0], dup2(a[r].z), b2.x); ffma2(acc[r][1], dup2(a[r].z), b2.y);
                ffma2(acc[r][0], dup2(a[r].w), b3.x); ffma2(acc[r][1], dup2(a[r].w), b3.y);
            }
        }
        float4 bv4 = *(const float4*)(bv + col);
        #pragma unroll
        for (int r = 0; r < 6; r++) {
            float lo0, hi0, lo1, hi1;
            unpack2(acc[r][0], lo0, hi0); unpack2(acc[r][1], lo1, hi1);
            float* dst = sm + SM_TGT + (j0+r)*TS + col;
            dst[0] = lo0 + bv4.x; dst[1] = hi0 + bv4.y;
            dst[2] = lo1 + bv4.z; dst[3] = hi1 + bv4.w;
        }
    }
    __syncthreads();

    // -------- x_att[r] = P[r,h(c)] @ vproj -> scratch --------
    {
        const int r    = tid >> 5;
        const int lane = tid & 31;
        const int col  = lane * 4;
        const int h    = lane >> 2;
        const int p    = r*8 + h;
        ull a01 = 0ull, a23 = 0ull;
        if (r < 2) {
            const float* pr = sm + SM_P + p*SS;
            for (int j = 0; j < NTOK; j++) {
                ull f = dup2(pr[j]);
                ulonglong2 v2 = *(const ulonglong2*)(sm + SM_TGT + j*TS + col);
                ffma2(a01, f, v2.x); ffma2(a23, f, v2.y);
            }
        } else {
            const int wi = r - 2;
            const int hw = (wi/3)*4, ww = (wi%3)*2;
            const float* pr = sm + SM_P + p*SS;
            #pragma unroll
            for (int m = 0; m < 8; m++) {
                const int j = (hw + (m>>1))*6 + ww + (m&1);
                ull f = dup2(pr[m]);
                ulonglong2 v2 = *(const ulonglong2*)(sm + SM_TGT + j*TS + col);
                ffma2(a01, f, v2.x); ffma2(a23, f, v2.y);
            }
        }
        float4 o;
        unpack2(a01, o.x, o.y); unpack2(a23, o.z, o.w);
        *(float4*)(g_xatt + ((size_t)b*8 + r)*DM + col) = o;
    }
}

// =====================================================================
// Kernel B: GB batches per CTA. Wp + residual + LN + FFN.
// =====================================================================
__device__ __forceinline__ void gemm64(const float* __restrict__ A,
                                       const float* __restrict__ W,
                                       int w, int lane, ull acc[8][2])
{
    const int r0  = w * 8;
    const int col = lane * 4;
    for (int k4 = 0; k4 < 32; k4++) {
        float4 a[8];
        #pragma unroll
        for (int r = 0; r < 8; r++)
            a[r] = *(const float4*)(A + (r0+r)*TS + k4*4);
        ulonglong2 b0 = *(const ulonglong2*)(W + (k4*4+0)*DM + col);
        ulonglong2 b1 = *(const ulonglong2*)(W + (k4*4+1)*DM + col);
        ulonglong2 b2 = *(const ulonglong2*)(W + (k4*4+2)*DM + col);
        ulonglong2 b3 = *(const ulonglong2*)(W + (k4*4+3)*DM + col);
        #pragma unroll
        for (int r = 0; r < 8; r++) {
            ffma2(acc[r][0], dup2(a[r].x), b0.x); ffma2(acc[r][1], dup2(a[r].x), b0.y);
            ffma2(acc[r][0], dup2(a[r].y), b1.x); ffma2(acc[r][1], dup2(a[r].y), b1.y);
            ffma2(acc[r][0], dup2(a[r].z), b2.x); ffma2(acc[r][1], dup2(a[r].z), b2.y);
            ffma2(acc[r][0], dup2(a[r].w), b3.x); ffma2(acc[r][1], dup2(a[r].w), b3.y);
        }
    }
}

__global__ __launch_bounds__(256, 1)
void k_ffn(const float* __restrict__ query, const float* __restrict__ bp,
           const float* __restrict__ g2, const float* __restrict__ b2,
           const float* __restrict__ bf1, const float* __restrict__ bf2,
           float* __restrict__ out, int Bn)
{
    extern __shared__ float sm[];
    const int tid  = threadIdx.x;
    const int w    = tid >> 5;
    const int lane = tid & 31;
    const int col  = lane * 4;
    const int b0   = blockIdx.x * GB;
    const int rows_valid = (Bn - b0 >= GB) ? BROWS : (Bn - b0) * 8;

    {
        const float4* src = (const float4*)(g_xatt + (size_t)b0 * 8 * DM);
        #pragma unroll
        for (int k = 0; k < 8; k++) {
            int i = tid + k*256;
            int r = i >> 5, c4 = (i & 31) << 2;
            float4 v = (r < rows_valid) ? src[i] : make_float4(0.f,0.f,0.f,0.f);
            *(float4*)(sm + SMB_XA + r*TS + c4) = v;
        }
        const float4* wsrc = (const float4*)g_WpT;
        float4* wdst = (float4*)(sm + SMB_W);
        #pragma unroll
        for (int k = 0; k < 16; k++) wdst[tid + k*256] = wsrc[tid + k*256];
        ((float4*)(sm + SMB_Q))[tid] = ((const float4*)query)[tid];
        if (tid < 128) {
            sm[SMB_CB +       tid] = bp [tid];
            sm[SMB_CB + 128 + tid] = g2 [tid];
            sm[SMB_CB + 256 + tid] = b2 [tid];
            sm[SMB_CB + 384 + tid] = bf1[tid];
            sm[SMB_CB + 512 + tid] = bf2[tid];
        }
    }
    __syncthreads();

    // GEMM1: x = query + x_att @ WpT + bp
    {
        ull acc[8][2] = {};
        gemm64(sm + SMB_XA, sm + SMB_W, w, lane, acc);
        #pragma unroll
        for (int r = 0; r < 8; r++) {
            const int row = w*8 + r;
            float lo0, hi0, lo1, hi1;
            unpack2(acc[r][0], lo0, hi0); unpack2(acc[r][1], lo1, hi1);
            const float* q = sm + SMB_Q + (row & 7)*DM + col;
            const float* bpc = sm + SMB_CB + col;
            float* dst = sm + SMB_X + row*TS + col;
            dst[0] = q[0] + bpc[0] + lo0;
            dst[1] = q[1] + bpc[1] + hi0;
            dst[2] = q[2] + bpc[2] + lo1;
            dst[3] = q[3] + bpc[3] + hi1;
        }
    }
    __syncthreads();

    // LN -> s_n ; restage W <- Wf1T
    {
        #pragma unroll
        for (int r = 0; r < 8; r++) {
            const int row = w*8 + r;
            const float* xr = sm + SMB_X + row*TS + col;
            float v0 = xr[0], v1 = xr[1], v2 = xr[2], v3 = xr[3];
            float sum = v0+v1+v2+v3;
            float sq  = v0*v0+v1*v1+v2*v2+v3*v3;
            #pragma unroll
            for (int o = 16; o > 0; o >>= 1) {
                sum += __shfl_xor_sync(0xffffffffu, sum, o);
                sq  += __shfl_xor_sync(0xffffffffu, sq,  o);
            }
            float m   = sum * (1.f/DM);
            float var = sq * (1.f/DM) - m*m;
            float rs  = rsqrtf(var + 1e-5f);
            float* nr = sm + SMB_N + row*TS + col;
            const float* g2c = sm + SMB_CB + 128 + col;
            const float* b2c = sm + SMB_CB + 256 + col;
            nr[0] = (v0 - m)*rs*g2c[0] + b2c[0];
            nr[1] = (v1 - m)*rs*g2c[1] + b2c[1];
            nr[2] = (v2 - m)*rs*g2c[2] + b2c[2];
            nr[3] = (v3 - m)*rs*g2c[3] + b2c[3];
        }
        const float4* wsrc = (const float4*)g_Wf1T;
        float4* wdst = (float4*)(sm + SMB_W);
        #pragma unroll
        for (int k = 0; k < 16; k++) wdst[tid + k*256] = wsrc[tid + k*256];
    }
    __syncthreads();

    // GEMM2: h = gelu(xn @ Wf1T + bf1)
    {
        ull acc[8][2] = {};
        gemm64(sm + SMB_N, sm + SMB_W, w, lane, acc);
        __syncthreads();
        #pragma unroll
        for (int r = 0; r < 8; r++) {
            const int row = w*8 + r;
            float z[4];
            unpack2(acc[r][0], z[0], z[1]); unpack2(acc[r][1], z[2], z[3]);
            float* nr = sm + SMB_N + row*TS + col;
            const float* bc = sm + SMB_CB + 384 + col;
            #pragma unroll
            for (int k = 0; k < 4; k++) {
                float zz = z[k] + bc[k];
                nr[k] = 0.5f * zz * (1.f + erff(zz * 0.7071067811865476f));
            }
        }
        const float4* wsrc = (const float4*)g_Wf2T;
        float4* wdst = (float4*)(sm + SMB_W);
        #pragma unroll
        for (int k = 0; k < 16; k++) wdst[tid + k*256] = wsrc[tid + k*256];
    }
    __syncthreads();

    // GEMM3: out = x + h @ Wf2T + bf2
    {
        ull acc[8][2] = {};
        gemm64(sm + SMB_N, sm + SMB_W, w, lane, acc);
        #pragma unroll
        for (int r = 0; r < 8; r++) {
            const int row = w*8 + r;
            if (row >= rows_valid) continue;
            float lo0, hi0, lo1, hi1;
            unpack2(acc[r][0], lo0, hi0); unpack2(acc[r][1], lo1, hi1);
            const float* xr = sm + SMB_X + row*TS + col;
            const float* bc = sm + SMB_CB + 512 + col;
            float4 res;
            res.x = xr[0] + bc[0] + lo0;
            res.y = xr[1] + bc[1] + hi0;
            res.z = xr[2] + bc[2] + lo1;
            res.w = xr[3] + bc[3] + hi1;
            *(float4*)(out + ((size_t)b0*8 + row)*DM + col) = res;
        }
    }
}

// =====================================================================
extern "C" void kernel_launch(void* const* d_in, const int* in_sizes, int n_in,
                              void* d_out, int out_size)
{
    const float* query = (const float*)d_in[0];
    const float* tgt   = (const float*)d_in[1];
    const float* g1    = (const float*)d_in[2];
    const float* b1    = (const float*)d_in[3];
    const float* Wq    = (const float*)d_in[4];
    const float* bq    = (const float*)d_in[5];
    const float* Wk    = (const float*)d_in[6];
    // d_in[7] = bk: drops out (softmax shift invariance)
    const float* Wv    = (const float*)d_in[8];
    const float* bv    = (const float*)d_in[9];
    const float* Wp    = (const float*)d_in[10];
    const float* bp    = (const float*)d_in[11];
    const float* g2    = (const float*)d_in[12];
    const float* b2    = (const float*)d_in[13];
    const float* Wf1   = (const float*)d_in[14];
    const float* bf1   = (const float*)d_in[15];
    const float* Wf2   = (const float*)d_in[16];
    const float* bf2   = (const float*)d_in[17];

    const int B = in_sizes[1] / (NTOK * DM);

    cudaFuncSetAttribute(k_attn, cudaFuncAttributeMaxDynamicSharedMemorySize, A_SMEM_BYTES);
    cudaFuncSetAttribute(k_ffn,  cudaFuncAttributeMaxDynamicSharedMemorySize, B_SMEM_BYTES);

    k_pre<<<5, 256>>>(query, g1, b1, Wq, bq, Wk, Wv, Wp, Wf1, Wf2);
    k_attn<<<B, 256, A_SMEM_BYTES>>>(tgt, bv);
    k_ffn<<<(B + GB - 1)/GB, 256, B_SMEM_BYTES>>>(query, bp, g2, b2, bf1, bf2,
                                                  (float*)d_out, B);
}

// round 6
// speedup vs baseline: 1.7776x; 1.0547x over previous
#include <cuda_runtime.h>

typedef unsigned long long ull;

#define NTOK 48
#define DM   128
#define TS   132
#define SS   49

// ---- kernel A smem (floats): vproj overlays tgt ----
#define SM_TGT  0            // 48*132 = 6336 (tgt, then vproj)
#define SM_P    6336         // 64*49  = 3136
#define A_SMEM_FLOATS 9472
#define A_SMEM_BYTES  (A_SMEM_FLOATS*4)   // 37888

// ---- kernel B smem (floats) ----
#define GB 8
#define BROWS 64
#define SMB_XA  0            // 64*132 = 8448
#define SMB_X   8448
#define SMB_N   16896
#define SMB_W   25344        // 128*128 = 16384
#define SMB_Q   41728        // 8*128 = 1024
#define SMB_CB  42752        // 5*128 = 640
#define B_SMEM_FLOATS 43392
#define B_SMEM_BYTES  (B_SMEM_FLOATS*4)   // 173568

#define MAXB 16384

// ---------------- device-global precomputed / scratch --------
__device__ __align__(16) float g_weff[64 * DM];
__device__ __align__(16) float g_WvT [DM * DM];
__device__ __align__(16) float g_WpT [DM * DM];
__device__ __align__(16) float g_Wf1T[DM * DM];
__device__ __align__(16) float g_Wf2T[DM * DM];
__device__ __align__(16) float g_xatt[(size_t)MAXB * 8 * DM];

// ---------------- packed fp32x2 helpers ----------------
__device__ __forceinline__ void ffma2(ull& d, ull a, ull b) {
    asm("fma.rn.f32x2 %0, %1, %2, %0;" : "+l"(d) : "l"(a), "l"(b));
}
__device__ __forceinline__ ull dup2(float x) {
    ull r; asm("mov.b64 %0, {%1, %1};" : "=l"(r) : "f"(x)); return r;
}
__device__ __forceinline__ void unpack2(ull v, float& lo, float& hi) {
    asm("mov.b64 {%0, %1}, %2;" : "=f"(lo), "=f"(hi) : "l"(v));
}
__device__ __forceinline__ float hsum2(ull v) {
    float lo, hi; unpack2(v, lo, hi); return lo + hi;
}

// =====================================================================
// Prologue, 5 blocks: block 0 = LN->q0->weff; blocks 1-4 = transposes.
// =====================================================================
__global__ void k_pre(const float* __restrict__ q, const float* __restrict__ g1,
                      const float* __restrict__ b1, const float* __restrict__ Wq,
                      const float* __restrict__ bq, const float* __restrict__ Wk,
                      const float* __restrict__ Wv, const float* __restrict__ Wp,
                      const float* __restrict__ Wf1, const float* __restrict__ Wf2)
{
    const int tid = threadIdx.x;
    if (blockIdx.x == 0) {
        __shared__ float qn[8][DM];
        __shared__ float q0s[8][DM];
        const int w = tid >> 5, lane = tid & 31;

        {
            float4 v = *(const float4*)(q + w*DM + lane*4);
            float s  = v.x + v.y + v.z + v.w;
            float sq = v.x*v.x + v.y*v.y + v.z*v.z + v.w*v.w;
            #pragma unroll
            for (int o = 16; o > 0; o >>= 1) {
                s  += __shfl_xor_sync(0xffffffffu, s,  o);
                sq += __shfl_xor_sync(0xffffffffu, sq, o);
            }
            float m  = s * (1.f/DM);
            float var = sq * (1.f/DM) - m*m;
            float rs = rsqrtf(var + 1e-5f);
            const int c = lane*4;
            qn[w][c+0] = (v.x - m)*rs*g1[c+0] + b1[c+0];
            qn[w][c+1] = (v.y - m)*rs*g1[c+1] + b1[c+1];
            qn[w][c+2] = (v.z - m)*rs*g1[c+2] + b1[c+2];
            qn[w][c+3] = (v.w - m)*rs*g1[c+3] + b1[c+3];
        }
        __syncthreads();

        for (int o = tid; o < 8*DM; o += 256) {
            int r = o >> 7, c = o & 127;
            float a = bq[c];
            const float4* wr = (const float4*)(Wq + c*DM);
            #pragma unroll 8
            for (int t4 = 0; t4 < 32; t4++) {
                float4 ww = wr[t4];
                a += qn[r][t4*4+0]*ww.x + qn[r][t4*4+1]*ww.y
                   + qn[r][t4*4+2]*ww.z + qn[r][t4*4+3]*ww.w;
            }
            q0s[r][c] = a;
        }
        __syncthreads();

        for (int o = tid; o < 64*DM; o += 256) {
            int p = o >> 7, t = o & 127;
            int r = p >> 3, h = p & 7;
            float a = 0.f;
            #pragma unroll
            for (int d = 0; d < 16; d++)
                a += q0s[r][h*16 + d] * Wk[(h*16 + d)*DM + t];
            g_weff[o] = 0.25f * a;
        }
    } else {
        const float* src; float* dst;
        switch (blockIdx.x) {
            case 1: src = Wv;  dst = g_WvT;  break;
            case 2: src = Wp;  dst = g_WpT;  break;
            case 3: src = Wf1; dst = g_Wf1T; break;
            default: src = Wf2; dst = g_Wf2T; break;
        }
        __shared__ float tile[32][33];
        const int tx = tid & 31, ty0 = tid >> 5;
        for (int t = 0; t < 16; t++) {
            const int ti = t >> 2, tj = t & 3;
            #pragma unroll
            for (int k = 0; k < 4; k++) {
                int ty = ty0 + k*8;
                tile[ty][tx] = src[(ti*32+ty)*DM + tj*32 + tx];
            }
            __syncthreads();
            #pragma unroll
            for (int k = 0; k < 4; k++) {
                int ty = ty0 + k*8;
                dst[(tj*32+ty)*DM + ti*32 + tx] = tile[tx][ty];
            }
            __syncthreads();
        }
    }
}

// =====================================================================
// Kernel A: one CTA per batch. scores -> softmax -> vproj (overlay) -> x_att.
// =====================================================================
__global__ __launch_bounds__(256, 3)
void k_attn(const float* __restrict__ tgt, const float* __restrict__ bv)
{
    extern __shared__ float sm[];
    const int tid = threadIdx.x;
    const int b   = blockIdx.x;

    // -------- stage tgt[b] --------
    {
        const float4* t4 = (const float4*)(tgt + (size_t)b * (NTOK*DM));
        #pragma unroll
        for (int k = 0; k < 6; k++) {
            int i = tid + k*256;
            float4 v = t4[i];
            int r = i >> 5, c = (i & 31) << 2;
            *(float4*)(sm + SM_TGT + r*TS + c) = v;
        }
    }
    __syncthreads();

    // -------- scores (windowed) --------
    if (tid < 128) {
        const int pa = (tid >> 4) * 2;
        const int jt = (tid & 15) * 3;
        const ulonglong2* w0 = (const ulonglong2*)(g_weff + pa*DM);
        const ulonglong2* w1 = (const ulonglong2*)(g_weff + (pa+1)*DM);
        const ulonglong2* t0 = (const ulonglong2*)(sm + SM_TGT + (jt+0)*TS);
        const ulonglong2* t1 = (const ulonglong2*)(sm + SM_TGT + (jt+1)*TS);
        const ulonglong2* t2 = (const ulonglong2*)(sm + SM_TGT + (jt+2)*TS);
        ull acc[2][3] = {};
        #pragma unroll 4
        for (int d = 0; d < 32; d++) {
            ulonglong2 a0 = w0[d], a1 = w1[d];
            ulonglong2 c0 = t0[d], c1 = t1[d], c2 = t2[d];
            ffma2(acc[0][0], a0.x, c0.x); ffma2(acc[0][0], a0.y, c0.y);
            ffma2(acc[0][1], a0.x, c1.x); ffma2(acc[0][1], a0.y, c1.y);
            ffma2(acc[0][2], a0.x, c2.x); ffma2(acc[0][2], a0.y, c2.y);
            ffma2(acc[1][0], a1.x, c0.x); ffma2(acc[1][0], a1.y, c0.y);
            ffma2(acc[1][1], a1.x, c1.x); ffma2(acc[1][1], a1.y, c1.y);
            ffma2(acc[1][2], a1.x, c2.x); ffma2(acc[1][2], a1.y, c2.y);
        }
        #pragma unroll
        for (int a = 0; a < 2; a++)
            #pragma unroll
            for (int c = 0; c < 3; c++)
                sm[SM_P + (pa+a)*SS + jt + c] = hsum2(acc[a][c]);
    } else if (tid < 224) {
        const int t2i = tid - 128;
        const int p   = 16 + (t2i >> 2) * 2;
        const int mg  = t2i & 3;
        const int r   = p >> 3, wi = r - 2;
        const int hw  = (wi/3)*4, ww = (wi%3)*2;
        const int m0  = mg*2;
        const int j0  = (hw + mg)*6 + ww;
        const ulonglong2* w0 = (const ulonglong2*)(g_weff + p*DM);
        const ulonglong2* w1 = (const ulonglong2*)(g_weff + (p+1)*DM);
        const ulonglong2* t0 = (const ulonglong2*)(sm + SM_TGT + (j0+0)*TS);
        const ulonglong2* t1 = (const ulonglong2*)(sm + SM_TGT + (j0+1)*TS);
        ull acc[2][2] = {};
        #pragma unroll 4
        for (int d = 0; d < 32; d++) {
            ulonglong2 a0 = w0[d], a1 = w1[d];
            ulonglong2 c0 = t0[d], c1 = t1[d];
            ffma2(acc[0][0], a0.x, c0.x); ffma2(acc[0][0], a0.y, c0.y);
            ffma2(acc[0][1], a0.x, c1.x); ffma2(acc[0][1], a0.y, c1.y);
            ffma2(acc[1][0], a1.x, c0.x); ffma2(acc[1][0], a1.y, c0.y);
            ffma2(acc[1][1], a1.x, c1.x); ffma2(acc[1][1], a1.y, c1.y);
        }
        sm[SM_P + p*SS     + m0    ] = hsum2(acc[0][0]);
        sm[SM_P + p*SS     + m0 + 1] = hsum2(acc[0][1]);
        sm[SM_P + (p+1)*SS + m0    ] = hsum2(acc[1][0]);
        sm[SM_P + (p+1)*SS + m0 + 1] = hsum2(acc[1][1]);
    }
    __syncthreads();

    // -------- softmax per pair (compact rows); non-softmax warps fall through --------
    if (tid < 64) {
        const int n = (tid < 16) ? 48 : 8;
        float* row = sm + SM_P + tid*SS;
        float mx = -1e30f;
        for (int j = 0; j < n; j++) mx = fmaxf(mx, row[j]);
        float sum = 0.f;
        for (int j = 0; j < n; j++) { float e = expf(row[j] - mx); row[j] = e; sum += e; }
        float inv = 1.f / sum;
        for (int j = 0; j < n; j++) row[j] *= inv;
    }

    // -------- vproj[j] = tgt[j] @ WvT + bv, accumulate in regs, overlay onto tgt --------
    // Each warp reads ONLY its own 6 rows and writes those same 6 rows: no sync needed.
    {
        const int w    = tid >> 5;
        const int lane = tid & 31;
        const int j0   = w * 6;
        const int col  = lane * 4;
        ull acc[6][2] = {};
        for (int k4 = 0; k4 < 32; k4++) {
            float4 a[6];
            #pragma unroll
            for (int r = 0; r < 6; r++)
                a[r] = *(const float4*)(sm + SM_TGT + (j0+r)*TS + k4*4);
            ulonglong2 b0 = *(const ulonglong2*)(g_WvT + (k4*4+0)*DM + col);
            ulonglong2 b1 = *(const ulonglong2*)(g_WvT + (k4*4+1)*DM + col);
            ulonglong2 b2 = *(const ulonglong2*)(g_WvT + (k4*4+2)*DM + col);
            ulonglong2 b3 = *(const ulonglong2*)(g_WvT + (k4*4+3)*DM + col);
            #pragma unroll
            for (int r = 0; r < 6; r++) {
                ffma2(acc[r][0], dup2(a[r].x), b0.x); ffma2(acc[r][1], dup2(a[r].x), b0.y);
                ffma2(acc[r][0], dup2(a[r].y), b1.x); ffma2(acc[r][1], dup2(a[r].y), b1.y);
                ffma2(acc[r][0], dup2(a[r].z), b2.x); ffma2(acc[r][1], dup2(a[r].z), b2.y);
                ffma2(acc[r][0], dup2(a[r].w), b3.x); ffma2(acc[r][1], dup2(a[r].w), b3.y);
            }
        }
        float4 bv4 = *(const float4*)(bv + col);
        #pragma unroll
        for (int r = 0; r < 6; r++) {
            float lo0, hi0, lo1, hi1;
            unpack2(acc[r][0], lo0, hi0); unpack2(acc[r][1], lo1, hi1);
            float* dst = sm + SM_TGT + (j0+r)*TS + col;
            dst[0] = lo0 + bv4.x; dst[1] = hi0 + bv4.y;
            dst[2] = lo1 + bv4.z; dst[3] = hi1 + bv4.w;
        }
    }
    __syncthreads();

    // -------- x_att[r] = P[r,h(c)] @ vproj -> scratch --------
    {
        const int r    = tid >> 5;
        const int lane = tid & 31;
        const int col  = lane * 4;
        const int h    = lane >> 2;
        const int p    = r*8 + h;
        ull a01 = 0ull, a23 = 0ull;
        if (r < 2) {
            const float* pr = sm + SM_P + p*SS;
            for (int j = 0; j < NTOK; j++) {
                ull f = dup2(pr[j]);
                ulonglong2 v2 = *(const ulonglong2*)(sm + SM_TGT + j*TS + col);
                ffma2(a01, f, v2.x); ffma2(a23, f, v2.y);
            }
        } else {
            const int wi = r - 2;
            const int hw = (wi/3)*4, ww = (wi%3)*2;
            const float* pr = sm + SM_P + p*SS;
            #pragma unroll
            for (int m = 0; m < 8; m++) {
                const int j = (hw + (m>>1))*6 + ww + (m&1);
                ull f = dup2(pr[m]);
                ulonglong2 v2 = *(const ulonglong2*)(sm + SM_TGT + j*TS + col);
                ffma2(a01, f, v2.x); ffma2(a23, f, v2.y);
            }
        }
        float4 o;
        unpack2(a01, o.x, o.y); unpack2(a23, o.z, o.w);
        *(float4*)(g_xatt + ((size_t)b*8 + r)*DM + col) = o;
    }
}

// =====================================================================
// Kernel B: GB batches per CTA. Wp + residual + LN + FFN.
// =====================================================================
__device__ __forceinline__ void gemm64(const float* __restrict__ A,
                                       const float* __restrict__ W,
                                       int w, int lane, ull acc[8][2])
{
    const int r0  = w * 8;
    const int col = lane * 4;
    for (int k4 = 0; k4 < 32; k4++) {
        float4 a[8];
        #pragma unroll
        for (int r = 0; r < 8; r++)
            a[r] = *(const float4*)(A + (r0+r)*TS + k4*4);
        ulonglong2 b0 = *(const ulonglong2*)(W + (k4*4+0)*DM + col);
        ulonglong2 b1 = *(const ulonglong2*)(W + (k4*4+1)*DM + col);
        ulonglong2 b2 = *(const ulonglong2*)(W + (k4*4+2)*DM + col);
        ulonglong2 b3 = *(const ulonglong2*)(W + (k4*4+3)*DM + col);
        #pragma unroll
        for (int r = 0; r < 8; r++) {
            ffma2(acc[r][0], dup2(a[r].x), b0.x); ffma2(acc[r][1], dup2(a[r].x), b0.y);
            ffma2(acc[r][0], dup2(a[r].y), b1.x); ffma2(acc[r][1], dup2(a[r].y), b1.y);
            ffma2(acc[r][0], dup2(a[r].z), b2.x); ffma2(acc[r][1], dup2(a[r].z), b2.y);
            ffma2(acc[r][0], dup2(a[r].w), b3.x); ffma2(acc[r][1], dup2(a[r].w), b3.y);
        }
    }
}

__global__ __launch_bounds__(256, 1)
void k_ffn(const float* __restrict__ query, const float* __restrict__ bp,
           const float* __restrict__ g2, const float* __restrict__ b2,
           const float* __restrict__ bf1, const float* __restrict__ bf2,
           float* __restrict__ out, int Bn)
{
    extern __shared__ float sm[];
    const int tid  = threadIdx.x;
    const int w    = tid >> 5;
    const int lane = tid & 31;
    const int col  = lane * 4;
    const int b0   = blockIdx.x * GB;
    const int rows_valid = (Bn - b0 >= GB) ? BROWS : (Bn - b0) * 8;

    {
        const float4* src = (const float4*)(g_xatt + (size_t)b0 * 8 * DM);
        #pragma unroll
        for (int k = 0; k < 8; k++) {
            int i = tid + k*256;
            int r = i >> 5, c4 = (i & 31) << 2;
            float4 v = (r < rows_valid) ? src[i] : make_float4(0.f,0.f,0.f,0.f);
            *(float4*)(sm + SMB_XA + r*TS + c4) = v;
        }
        const float4* wsrc = (const float4*)g_WpT;
        float4* wdst = (float4*)(sm + SMB_W);
        #pragma unroll
        for (int k = 0; k < 16; k++) wdst[tid + k*256] = wsrc[tid + k*256];
        ((float4*)(sm + SMB_Q))[tid] = ((const float4*)query)[tid];
        if (tid < 128) {
            sm[SMB_CB +       tid] = bp [tid];
            sm[SMB_CB + 128 + tid] = g2 [tid];
            sm[SMB_CB + 256 + tid] = b2 [tid];
            sm[SMB_CB + 384 + tid] = bf1[tid];
            sm[SMB_CB + 512 + tid] = bf2[tid];
        }
    }
    __syncthreads();

    // GEMM1: x = query + x_att @ WpT + bp
    {
        ull acc[8][2] = {};
        gemm64(sm + SMB_XA, sm + SMB_W, w, lane, acc);
        #pragma unroll
        for (int r = 0; r < 8; r++) {
            const int row = w*8 + r;
            float lo0, hi0, lo1, hi1;
            unpack2(acc[r][0], lo0, hi0); unpack2(acc[r][1], lo1, hi1);
            const float* q = sm + SMB_Q + (row & 7)*DM + col;
            const float* bpc = sm + SMB_CB + col;
            float* dst = sm + SMB_X + row*TS + col;
            dst[0] = q[0] + bpc[0] + lo0;
            dst[1] = q[1] + bpc[1] + hi0;
            dst[2] = q[2] + bpc[2] + lo1;
            dst[3] = q[3] + bpc[3] + hi1;
        }
    }
    __syncthreads();

    // LN -> s_n ; restage W <- Wf1T
    {
        #pragma unroll
        for (int r = 0; r < 8; r++) {
            const int row = w*8 + r;
            const float* xr = sm + SMB_X + row*TS + col;
            float v0 = xr[0], v1 = xr[1], v2 = xr[2], v3 = xr[3];
            float sum = v0+v1+v2+v3;
            float sq  = v0*v0+v1*v1+v2*v2+v3*v3;
            #pragma unroll
            for (int o = 16; o > 0; o >>= 1) {
                sum += __shfl_xor_sync(0xffffffffu, sum, o);
                sq  += __shfl_xor_sync(0xffffffffu, sq,  o);
            }
            float m   = sum * (1.f/DM);
            float var = sq * (1.f/DM) - m*m;
            float rs  = rsqrtf(var + 1e-5f);
            float* nr = sm + SMB_N + row*TS + col;
            const float* g2c = sm + SMB_CB + 128 + col;
            const float* b2c = sm + SMB_CB + 256 + col;
            nr[0] = (v0 - m)*rs*g2c[0] + b2c[0];
            nr[1] = (v1 - m)*rs*g2c[1] + b2c[1];
            nr[2] = (v2 - m)*rs*g2c[2] + b2c[2];
            nr[3] = (v3 - m)*rs*g2c[3] + b2c[3];
        }
        const float4* wsrc = (const float4*)g_Wf1T;
        float4* wdst = (float4*)(sm + SMB_W);
        #pragma unroll
        for (int k = 0; k < 16; k++) wdst[tid + k*256] = wsrc[tid + k*256];
    }
    __syncthreads();

    // GEMM2: h = gelu(xn @ Wf1T + bf1)
    {
        ull acc[8][2] = {};
        gemm64(sm + SMB_N, sm + SMB_W, w, lane, acc);
        __syncthreads();
        #pragma unroll
        for (int r = 0; r < 8; r++) {
            const int row = w*8 + r;
            float z[4];
            unpack2(acc[r][0], z[0], z[1]); unpack2(acc[r][1], z[2], z[3]);
            float* nr = sm + SMB_N + row*TS + col;
            const float* bc = sm + SMB_CB + 384 + col;
            #pragma unroll
            for (int k = 0; k < 4; k++) {
                float zz = z[k] + bc[k];
                nr[k] = 0.5f * zz * (1.f + erff(zz * 0.7071067811865476f));
            }
        }
        const float4* wsrc = (const float4*)g_Wf2T;
        float4* wdst = (float4*)(sm + SMB_W);
        #pragma unroll
        for (int k = 0; k < 16; k++) wdst[tid + k*256] = wsrc[tid + k*256];
    }
    __syncthreads();

    // GEMM3: out = x + h @ Wf2T + bf2
    {
        ull acc[8][2] = {};
        gemm64(sm + SMB_N, sm + SMB_W, w, lane, acc);
        #pragma unroll
        for (int r = 0; r < 8; r++) {
            const int row = w*8 + r;
            if (row >= rows_valid) continue;
            float lo0, hi0, lo1, hi1;
            unpack2(acc[r][0], lo0, hi0); unpack2(acc[r][1], lo1, hi1);
            const float* xr = sm + SMB_X + row*TS + col;
            const float* bc = sm + SMB_CB + 512 + col;
            float4 res;
            res.x = xr[0] + bc[0] + lo0;
            res.y = xr[1] + bc[1] + hi0;
            res.z = xr[2] + bc[2] + lo1;
            res.w = xr[3] + bc[3] + hi1;
            *(float4*)(out + ((size_t)b0*8 + row)*DM + col) = res;
        }
    }
}

// =====================================================================
extern "C" void kernel_launch(void* const* d_in, const int* in_sizes, int n_in,
                              void* d_out, int out_size)
{
    const float* query = (const float*)d_in[0];
    const float* tgt   = (const float*)d_in[1];
    const float* g1    = (const float*)d_in[2];
    const float* b1    = (const float*)d_in[3];
    const float* Wq    = (const float*)d_in[4];
    const float* bq    = (const float*)d_in[5];
    const float* Wk    = (const float*)d_in[6];
    // d_in[7] = bk: drops out (softmax shift invariance)
    const float* Wv    = (const float*)d_in[8];
    const float* bv    = (const float*)d_in[9];
    const float* Wp    = (const float*)d_in[10];
    const float* bp    = (const float*)d_in[11];
    const float* g2    = (const float*)d_in[12];
    const float* b2    = (const float*)d_in[13];
    const float* Wf1   = (const float*)d_in[14];
    const float* bf1   = (const float*)d_in[15];
    const float* Wf2   = (const float*)d_in[16];
    const float* bf2   = (const float*)d_in[17];

    const int B = in_sizes[1] / (NTOK * DM);

    cudaFuncSetAttribute(k_attn, cudaFuncAttributeMaxDynamicSharedMemorySize, A_SMEM_BYTES);
    cudaFuncSetAttribute(k_ffn,  cudaFuncAttributeMaxDynamicSharedMemorySize, B_SMEM_BYTES);

    k_pre<<<5, 256>>>(query, g1, b1, Wq, bq, Wk, Wv, Wp, Wf1, Wf2);
    k_attn<<<B, 256, A_SMEM_BYTES>>>(tgt, bv);
    k_ffn<<<(B + GB - 1)/GB, 256, B_SMEM_BYTES>>>(query, bp, g2, b2, bf1, bf2,
                                                  (float*)d_out, B);
}

// round 11
// speedup vs baseline: 2.1242x; 1.1950x over previous
#include <cuda_runtime.h>
#include <cuda_bf16.h>

typedef unsigned long long ull;
typedef unsigned int u32;

#define DM   128
#define NTOK 48
#define TS   132
#define SS   49
#define MAXB 16384

// ---- k_attn_mma smem byte offsets (bf16 rows padded to 272B) ----
#define AT_TGT  0                         // tgt hi   48x272 = 13056
#define AT_TGTL 13056                     // tgt lo   48x272 = 13056
#define AT_WEFF 26112                     // weff hi  64x272 = 17408 ; fp32 P overlay (12544) after MMA
#define AT_WV   43520                     // Wv hi   128x272 = 34816 ; fp32 vproj overlay (25344) after MMA
#define AT_WVL  78336                     // Wv lo   128x272 = 34816
#define AT_SMEM 113152
#define P_F     6528                      // AT_WEFF/4
#define VP_F    10880                     // AT_WV/4, stride 132 floats

// ---- k_ffn smem (floats) ----
#define GB 8
#define BROWS 64
#define SMB_XA  0
#define SMB_X   8448
#define SMB_N   16896
#define SMB_W   25344
#define SMB_Q   41728
#define SMB_CB  42752
#define B_SMEM_BYTES  (43392*4)

// ---------------- globals ----------------
__device__ __align__(16) float g_weff[64 * DM];
__device__ __align__(16) u32 g_wvHi[128 * 68];    // padded-row bf16x2 images
__device__ __align__(16) u32 g_wvLo[128 * 68];
__device__ __align__(16) u32 g_weffHi[64 * 68];
__device__ __align__(16) float g_WpT [DM * DM];
__device__ __align__(16) float g_Wf1T[DM * DM];
__device__ __align__(16) float g_Wf2T[DM * DM];
__device__ __align__(16) float g_xatt[(size_t)MAXB * 8 * DM];

// ---------------- helpers ----------------
__device__ __forceinline__ void ffma2(ull& d, ull a, ull b) {
    asm("fma.rn.f32x2 %0, %1, %2, %0;" : "+l"(d) : "l"(a), "l"(b));
}
__device__ __forceinline__ ull dup2(float x) {
    ull r; asm("mov.b64 %0, {%1, %1};" : "=l"(r) : "f"(x)); return r;
}
__device__ __forceinline__ void unpack2(ull v, float& lo, float& hi) {
    asm("mov.b64 {%0, %1}, %2;" : "=f"(lo), "=f"(hi) : "l"(v));
}
__device__ __forceinline__ u32 smem_u32(const void* p) {
    u32 a; asm("{ .reg .u64 t; cvta.to.shared.u64 t, %1; cvt.u32.u64 %0, t; }" : "=r"(a) : "l"(p));
    return a;
}
__device__ __forceinline__ u32 bf2(float lo, float hi) {   // word: low half=lo, high=hi
    u32 r; asm("cvt.rn.bf16x2.f32 %0, %1, %2;" : "=r"(r) : "f"(hi), "f"(lo)); return r;
}
__device__ __forceinline__ float bfround(float x) {
    return __bfloat162float(__float2bfloat16(x));
}
__device__ __forceinline__ void ldsm_x4(u32* r, u32 addr) {
    asm volatile("ldmatrix.sync.aligned.m8n8.x4.shared.b16 {%0,%1,%2,%3}, [%4];"
        : "=r"(r[0]), "=r"(r[1]), "=r"(r[2]), "=r"(r[3]) : "r"(addr));
}
__device__ __forceinline__ void ldsm_x2(u32* r, u32 addr) {
    asm volatile("ldmatrix.sync.aligned.m8n8.x2.shared.b16 {%0,%1}, [%2];"
        : "=r"(r[0]), "=r"(r[1]) : "r"(addr));
}
__device__ __forceinline__ void mma_bf16(float* d, const u32* a, const u32* b) {
    asm volatile("mma.sync.aligned.m16n8k16.row.col.f32.bf16.bf16.f32 "
        "{%0,%1,%2,%3}, {%4,%5,%6,%7}, {%8,%9}, {%0,%1,%2,%3};"
        : "+f"(d[0]), "+f"(d[1]), "+f"(d[2]), "+f"(d[3])
        : "r"(a[0]), "r"(a[1]), "r"(a[2]), "r"(a[3]), "r"(b[0]), "r"(b[1]));
}

// =====================================================================
// k_pre, 5 blocks: 0 = LN->q0->weff (+weffHi image); 1..3 = transposes;
// 4 = Wv hi/lo images.
// =====================================================================
__global__ void k_pre(const float* __restrict__ q, const float* __restrict__ g1,
                      const float* __restrict__ b1, const float* __restrict__ Wq,
                      const float* __restrict__ bq, const float* __restrict__ Wk,
                      const float* __restrict__ Wv, const float* __restrict__ Wp,
                      const float* __restrict__ Wf1, const float* __restrict__ Wf2)
{
    const int tid = threadIdx.x;
    if (blockIdx.x == 0) {
        __shared__ float qn[8][DM];
        __shared__ float q0s[8][DM];
        const int w = tid >> 5, lane = tid & 31;
        {
            float4 v = *(const float4*)(q + w*DM + lane*4);
            float s  = v.x + v.y + v.z + v.w;
            float sq = v.x*v.x + v.y*v.y + v.z*v.z + v.w*v.w;
            #pragma unroll
            for (int o = 16; o > 0; o >>= 1) {
                s  += __shfl_xor_sync(0xffffffffu, s,  o);
                sq += __shfl_xor_sync(0xffffffffu, sq, o);
            }
            float m = s * (1.f/DM);
            float var = sq * (1.f/DM) - m*m;
            float rs = rsqrtf(var + 1e-5f);
            const int c = lane*4;
            qn[w][c+0] = (v.x - m)*rs*g1[c+0] + b1[c+0];
            qn[w][c+1] = (v.y - m)*rs*g1[c+1] + b1[c+1];
            qn[w][c+2] = (v.z - m)*rs*g1[c+2] + b1[c+2];
            qn[w][c+3] = (v.w - m)*rs*g1[c+3] + b1[c+3];
        }
        __syncthreads();
        for (int o = tid; o < 8*DM; o += 256) {
            int r = o >> 7, c = o & 127;
            float a = bq[c];
            const float4* wr = (const float4*)(Wq + c*DM);
            #pragma unroll 8
            for (int t4 = 0; t4 < 32; t4++) {
                float4 ww = wr[t4];
                a += qn[r][t4*4+0]*ww.x + qn[r][t4*4+1]*ww.y
                   + qn[r][t4*4+2]*ww.z + qn[r][t4*4+3]*ww.w;
            }
            q0s[r][c] = a;
        }
        __syncthreads();
        for (int o = tid; o < 64*DM; o += 256) {
            int p = o >> 7, t = o & 127;
            int r = p >> 3, h = p & 7;
            float a = 0.f;
            #pragma unroll
            for (int d = 0; d < 16; d++)
                a += q0s[r][h*16 + d] * Wk[(h*16 + d)*DM + t];
            g_weff[o] = 0.25f * a;
        }
        __syncthreads();
        // weff hi image (padded rows of 68 u32)
        for (int o = tid; o < 64*64; o += 256) {
            int p = o >> 6, tp = o & 63;
            float x0 = g_weff[p*DM + tp*2], x1 = g_weff[p*DM + tp*2 + 1];
            g_weffHi[p*68 + tp] = bf2(x0, x1);
        }
    } else if (blockIdx.x == 4) {
        // Wv hi/lo images
        for (int o = tid; o < 128*64; o += 256) {
            int r = o >> 6, tp = o & 63;
            float x0 = Wv[r*DM + tp*2], x1 = Wv[r*DM + tp*2 + 1];
            float h0 = bfround(x0), h1 = bfround(x1);
            g_wvHi[r*68 + tp] = bf2(x0, x1);
            g_wvLo[r*68 + tp] = bf2(x0 - h0, x1 - h1);
        }
    } else {
        const float* src; float* dst;
        switch (blockIdx.x) {
            case 1: src = Wp;  dst = g_WpT;  break;
            case 2: src = Wf1; dst = g_Wf1T; break;
            default: src = Wf2; dst = g_Wf2T; break;
        }
        __shared__ float tile[32][33];
        const int tx = tid & 31, ty0 = tid >> 5;
        for (int t = 0; t < 16; t++) {
            const int ti = t >> 2, tj = t & 3;
            #pragma unroll
            for (int k = 0; k < 4; k++) {
                int ty = ty0 + k*8;
                tile[ty][tx] = src[(ti*32+ty)*DM + tj*32 + tx];
            }
            __syncthreads();
            #pragma unroll
            for (int k = 0; k < 4; k++) {
                int ty = ty0 + k*8;
                dst[(tj*32+ty)*DM + ti*32 + tx] = tile[tx][ty];
            }
            __syncthreads();
        }
    }
}

// =====================================================================
// k_attn_mma: 1 batch/CTA. Split-bf16 mma.sync -> softmax -> x_att.
// =====================================================================
__global__ __launch_bounds__(256, 2)
void k_attn_mma(const float* __restrict__ tgt, const float* __restrict__ bv)
{
    extern __shared__ float smf[];
    char* smc = (char*)smf;
    const u32 smb = smem_u32(smf);
    const int tid = threadIdx.x;
    const int wid = tid >> 5, lane = tid & 31;
    const int b = blockIdx.x;

    // -------- stage: tgt -> hi/lo (convert), Wv/weff images (copy) --------
    {
        const float4* src = (const float4*)(tgt + (size_t)b * NTOK * DM);
        #pragma unroll
        for (int k = 0; k < 6; k++) {
            int i = tid + k*256;
            float4 v = src[i];
            int row = i >> 5, c = (i & 31) * 4;
            float hx = bfround(v.x), hy = bfround(v.y);
            float hz = bfround(v.z), hw = bfround(v.w);
            u32 off = row*272 + c*2;
            *(u32*)(smc + AT_TGT  + off)     = bf2(v.x, v.y);
            *(u32*)(smc + AT_TGT  + off + 4) = bf2(v.z, v.w);
            *(u32*)(smc + AT_TGTL + off)     = bf2(v.x - hx, v.y - hy);
            *(u32*)(smc + AT_TGTL + off + 4) = bf2(v.z - hz, v.w - hw);
        }
        const float4* wh = (const float4*)g_wvHi;
        const float4* wl = (const float4*)g_wvLo;
        float4* dH = (float4*)(smc + AT_WV);
        float4* dL = (float4*)(smc + AT_WVL);
        #pragma unroll
        for (int k = 0; k < 9; k++) {
            int i = tid + k*256;
            if (i < 2176) { dH[i] = wh[i]; dL[i] = wl[i]; }
        }
        const float4* we = (const float4*)g_weffHi;
        float4* dE = (float4*)(smc + AT_WEFF);
        #pragma unroll
        for (int k = 0; k < 5; k++) {
            int i = tid + k*256;
            if (i < 1088) dE[i] = we[i];
        }
    }
    __syncthreads();

    // -------- MMA phase (split-bf16) --------
    float accV[8][4];    // vproj warps (0-5)
    float accS[2][6][4]; // score warps (6-7)
    if (wid < 6) {
        const int mt = wid >> 1;          // m-tile (tgt rows mt*16..+15)
        const int nh = wid & 1;           // n-tiles nh*8..nh*8+7
        #pragma unroll
        for (int n = 0; n < 8; n++)
            #pragma unroll
            for (int e = 0; e < 4; e++) accV[n][e] = 0.f;
        const u32 aoff = (mt*16 + (lane & 15))*272 + (lane >> 4)*16;
        const u32 aH = smb + AT_TGT  + aoff;
        const u32 aL = smb + AT_TGTL + aoff;
        const u32 boff = nh*8*2176 + (lane & 7)*272 + ((lane >> 3) & 1)*16;
        const u32 bH = smb + AT_WV  + boff;
        const u32 bL = smb + AT_WVL + boff;
        #pragma unroll
        for (int k = 0; k < 8; k++) {
            u32 ah[4], al[4];
            ldsm_x4(ah, aH + k*32);
            ldsm_x4(al, aL + k*32);
            #pragma unroll
            for (int nt = 0; nt < 8; nt++) {
                u32 bh[2], bl[2];
                ldsm_x2(bh, bH + nt*2176 + k*32);
                ldsm_x2(bl, bL + nt*2176 + k*32);
                mma_bf16(accV[nt], ah, bh);
                mma_bf16(accV[nt], ah, bl);
                mma_bf16(accV[nt], al, bh);
            }
        }
    } else {
        const int wi = wid - 6;           // m-tiles wi*2, wi*2+1 of weff
        #pragma unroll
        for (int i = 0; i < 2; i++)
            #pragma unroll
            for (int n = 0; n < 6; n++)
                #pragma unroll
                for (int e = 0; e < 4; e++) accS[i][n][e] = 0.f;
        const u32 a0 = smb + AT_WEFF + (wi*32 + (lane & 15))*272 + (lane >> 4)*16;
        const u32 a1 = a0 + 16*272;
        const u32 boff = (lane & 7)*272 + ((lane >> 3) & 1)*16;
        const u32 bH = smb + AT_TGT  + boff;
        const u32 bL = smb + AT_TGTL + boff;
        #pragma unroll
        for (int k = 0; k < 8; k++) {
            u32 aA[4], aB[4];
            ldsm_x4(aA, a0 + k*32);
            ldsm_x4(aB, a1 + k*32);
            #pragma unroll
            for (int nt = 0; nt < 6; nt++) {
                u32 bh[2], bl[2];
                ldsm_x2(bh, bH + nt*2176 + k*32);
                ldsm_x2(bl, bL + nt*2176 + k*32);
                mma_bf16(accS[0][nt], aA, bh);
                mma_bf16(accS[0][nt], aA, bl);
                mma_bf16(accS[1][nt], aB, bh);
                mma_bf16(accS[1][nt], aB, bl);
            }
        }
    }
    __syncthreads();   // MMA reads done; safe to overlay P / vproj

    // -------- epilogues --------
    if (wid < 6) {
        const int mt = wid >> 1, nh = wid & 1;
        const int r0 = mt*16 + (lane >> 2);
        const int c0 = nh*64 + (lane & 3)*2;
        #pragma unroll
        for (int nt = 0; nt < 8; nt++) {
            const int c = c0 + nt*8;
            float bv0 = bv[c], bv1 = bv[c+1];
            smf[VP_F + r0*TS + c]       = accV[nt][0] + bv0;
            smf[VP_F + r0*TS + c + 1]   = accV[nt][1] + bv1;
            smf[VP_F + (r0+8)*TS + c]   = accV[nt][2] + bv0;
            smf[VP_F + (r0+8)*TS + c+1] = accV[nt][3] + bv1;
        }
    } else {
        const int wi = wid - 6;
        #pragma unroll
        for (int i = 0; i < 2; i++) {
            const int r0 = (wi*2 + i)*16 + (lane >> 2);
            #pragma unroll
            for (int nt = 0; nt < 6; nt++) {
                const int c = nt*8 + (lane & 3)*2;
                smf[P_F + r0*SS + c]       = accS[i][nt][0];
                smf[P_F + r0*SS + c + 1]   = accS[i][nt][1];
                smf[P_F + (r0+8)*SS + c]   = accS[i][nt][2];
                smf[P_F + (r0+8)*SS + c+1] = accS[i][nt][3];
            }
        }
    }
    __syncthreads();

    // -------- masked softmax per pair (64 threads) --------
    if (tid < 64) {
        const int p = tid, r = p >> 3;
        int h0 = 0, h1 = 8, w0 = 0, w1 = 6;
        if (r >= 2) {
            int wi = r - 2;
            h0 = (wi / 3) * 4; h1 = h0 + 4;
            w0 = (wi % 3) * 2; w1 = w0 + 2;
        }
        float* row = smf + P_F + p*SS;
        float mx = -1e30f;
        for (int j = 0; j < NTOK; j++) {
            int hh = j / 6, ww = j - hh*6;
            if (hh >= h0 && hh < h1 && ww >= w0 && ww < w1)
                mx = fmaxf(mx, row[j]);
        }
        float sum = 0.f;
        for (int j = 0; j < NTOK; j++) {
            int hh = j / 6, ww = j - hh*6;
            if (hh >= h0 && hh < h1 && ww >= w0 && ww < w1) {
                float e = expf(row[j] - mx);
                row[j] = e; sum += e;
            }
        }
        float inv = 1.f / sum;
        for (int j = 0; j < NTOK; j++) row[j] *= inv;
    }
    __syncthreads();

    // -------- x_att[r] = P[r*8+h] @ vproj -> g_xatt --------
    {
        const int r    = tid >> 5;
        const int lane2 = tid & 31;
        const int col  = lane2 * 4;
        const int h    = lane2 >> 2;     // head = col/16 = lane/4  (FIXED)
        const int p    = r*8 + h;
        const float* Pb = smf + P_F + p*SS;
        ull a01 = 0ull, a23 = 0ull;
        if (r < 2) {
            for (int j = 0; j < NTOK; j++) {
                ull f = dup2(Pb[j]);
                ulonglong2 u0 = *(const ulonglong2*)(smf + VP_F + j*TS + col);
                ffma2(a01, f, u0.x); ffma2(a23, f, u0.y);
            }
        } else {
            const int wi = r - 2;
            const int hw = (wi/3)*4, ww = (wi%3)*2;
            #pragma unroll
            for (int m = 0; m < 8; m++) {
                const int j = (hw + (m>>1))*6 + ww + (m&1);
                ull f = dup2(Pb[j]);
                ulonglong2 u0 = *(const ulonglong2*)(smf + VP_F + j*TS + col);
                ffma2(a01, f, u0.x); ffma2(a23, f, u0.y);
            }
        }
        float4 o;
        unpack2(a01, o.x, o.y); unpack2(a23, o.z, o.w);
        *(float4*)(g_xatt + ((size_t)b*8 + r)*DM + col) = o;
    }
}

// =====================================================================
// k_ffn: GB batches per CTA. Wp + residual + LN + FFN. (unchanged, proven)
// =====================================================================
__device__ __forceinline__ void gemm64(const float* __restrict__ A,
                                       const float* __restrict__ W,
                                       int w, int lane, ull acc[8][2])
{
    const int r0  = w * 8;
    const int col = lane * 4;
    for (int k4 = 0; k4 < 32; k4++) {
        float4 a[8];
        #pragma unroll
        for (int r = 0; r < 8; r++)
            a[r] = *(const float4*)(A + (r0+r)*TS + k4*4);
        ulonglong2 b0 = *(const ulonglong2*)(W + (k4*4+0)*DM + col);
        ulonglong2 b1 = *(const ulonglong2*)(W + (k4*4+1)*DM + col);
        ulonglong2 b2 = *(const ulonglong2*)(W + (k4*4+2)*DM + col);
        ulonglong2 b3 = *(const ulonglong2*)(W + (k4*4+3)*DM + col);
        #pragma unroll
        for (int r = 0; r < 8; r++) {
            ffma2(acc[r][0], dup2(a[r].x), b0.x); ffma2(acc[r][1], dup2(a[r].x), b0.y);
            ffma2(acc[r][0], dup2(a[r].y), b1.x); ffma2(acc[r][1], dup2(a[r].y), b1.y);
            ffma2(acc[r][0], dup2(a[r].z), b2.x); ffma2(acc[r][1], dup2(a[r].z), b2.y);
            ffma2(acc[r][0], dup2(a[r].w), b3.x); ffma2(acc[r][1], dup2(a[r].w), b3.y);
        }
    }
}

__global__ __launch_bounds__(256, 1)
void k_ffn(const float* __restrict__ query, const float* __restrict__ bp,
           const float* __restrict__ g2, const float* __restrict__ b2,
           const float* __restrict__ bf1, const float* __restrict__ bf2,
           float* __restrict__ out, int Bn)
{
    extern __shared__ float sm[];
    const int tid  = threadIdx.x;
    const int w    = tid >> 5;
    const int lane = tid & 31;
    const int col  = lane * 4;
    const int b0   = blockIdx.x * GB;
    const int rows_valid = (Bn - b0 >= GB) ? BROWS : (Bn - b0) * 8;

    {
        const float4* src = (const float4*)(g_xatt + (size_t)b0 * 8 * DM);
        #pragma unroll
        for (int k = 0; k < 8; k++) {
            int i = tid + k*256;
            int r = i >> 5, c4 = (i & 31) << 2;
            float4 v = (r < rows_valid) ? src[i] : make_float4(0.f,0.f,0.f,0.f);
            *(float4*)(sm + SMB_XA + r*TS + c4) = v;
        }
        const float4* wsrc = (const float4*)g_WpT;
        float4* wdst = (float4*)(sm + SMB_W);
        #pragma unroll
        for (int k = 0; k < 16; k++) wdst[tid + k*256] = wsrc[tid + k*256];
        ((float4*)(sm + SMB_Q))[tid] = ((const float4*)query)[tid];
        if (tid < 128) {
            sm[SMB_CB +       tid] = bp [tid];
            sm[SMB_CB + 128 + tid] = g2 [tid];
            sm[SMB_CB + 256 + tid] = b2 [tid];
            sm[SMB_CB + 384 + tid] = bf1[tid];
            sm[SMB_CB + 512 + tid] = bf2[tid];
        }
    }
    __syncthreads();

    {
        ull acc[8][2] = {};
        gemm64(sm + SMB_XA, sm + SMB_W, w, lane, acc);
        #pragma unroll
        for (int r = 0; r < 8; r++) {
            const int row = w*8 + r;
            float lo0, hi0, lo1, hi1;
            unpack2(acc[r][0], lo0, hi0); unpack2(acc[r][1], lo1, hi1);
            const float* q = sm + SMB_Q + (row & 7)*DM + col;
            const float* bpc = sm + SMB_CB + col;
            float* dst = sm + SMB_X + row*TS + col;
            dst[0] = q[0] + bpc[0] + lo0;
            dst[1] = q[1] + bpc[1] + hi0;
            dst[2] = q[2] + bpc[2] + lo1;
            dst[3] = q[3] + bpc[3] + hi1;
        }
    }
    __syncthreads();

    {
        #pragma unroll
        for (int r = 0; r < 8; r++) {
            const int row = w*8 + r;
            const float* xr = sm + SMB_X + row*TS + col;
            float v0 = xr[0], v1 = xr[1], v2 = xr[2], v3 = xr[3];
            float sum = v0+v1+v2+v3;
            float sq  = v0*v0+v1*v1+v2*v2+v3*v3;
            #pragma unroll
            for (int o = 16; o > 0; o >>= 1) {
                sum += __shfl_xor_sync(0xffffffffu, sum, o);
                sq  += __shfl_xor_sync(0xffffffffu, sq,  o);
            }
            float m   = sum * (1.f/DM);
            float var = sq * (1.f/DM) - m*m;
            float rs  = rsqrtf(var + 1e-5f);
            float* nr = sm + SMB_N + row*TS + col;
            const float* g2c = sm + SMB_CB + 128 + col;
            const float* b2c = sm + SMB_CB + 256 + col;
            nr[0] = (v0 - m)*rs*g2c[0] + b2c[0];
            nr[1] = (v1 - m)*rs*g2c[1] + b2c[1];
            nr[2] = (v2 - m)*rs*g2c[2] + b2c[2];
            nr[3] = (v3 - m)*rs*g2c[3] + b2c[3];
        }
        const float4* wsrc = (const float4*)g_Wf1T;
        float4* wdst = (float4*)(sm + SMB_W);
        #pragma unroll
        for (int k = 0; k < 16; k++) wdst[tid + k*256] = wsrc[tid + k*256];
    }
    __syncthreads();

    {
        ull acc[8][2] = {};
        gemm64(sm + SMB_N, sm + SMB_W, w, lane, acc);
        __syncthreads();
        #pragma unroll
        for (int r = 0; r < 8; r++) {
            const int row = w*8 + r;
            float z[4];
            unpack2(acc[r][0], z[0], z[1]); unpack2(acc[r][1], z[2], z[3]);
            float* nr = sm + SMB_N + row*TS + col;
            const float* bc = sm + SMB_CB + 384 + col;
            #pragma unroll
            for (int k = 0; k < 4; k++) {
                float zz = z[k] + bc[k];
                nr[k] = 0.5f * zz * (1.f + erff(zz * 0.7071067811865476f));
            }
        }
        const float4* wsrc = (const float4*)g_Wf2T;
        float4* wdst = (float4*)(sm + SMB_W);
        #pragma unroll
        for (int k = 0; k < 16; k++) wdst[tid + k*256] = wsrc[tid + k*256];
    }
    __syncthreads();

    {
        ull acc[8][2] = {};
        gemm64(sm + SMB_N, sm + SMB_W, w, lane, acc);
        #pragma unroll
        for (int r = 0; r < 8; r++) {
            const int row = w*8 + r;
            if (row >= rows_valid) continue;
            float lo0, hi0, lo1, hi1;
            unpack2(acc[r][0], lo0, hi0); unpack2(acc[r][1], lo1, hi1);
            const float* xr = sm + SMB_X + row*TS + col;
            const float* bc = sm + SMB_CB + 512 + col;
            float4 res;
            res.x = xr[0] + bc[0] + lo0;
            res.y = xr[1] + bc[1] + hi0;
            res.z = xr[2] + bc[2] + lo1;
            res.w = xr[3] + bc[3] + hi1;
            *(float4*)(out + ((size_t)b0*8 + row)*DM + col) = res;
        }
    }
}

// =====================================================================
extern "C" void kernel_launch(void* const* d_in, const int* in_sizes, int n_in,
                              void* d_out, int out_size)
{
    const float* query = (const float*)d_in[0];
    const float* tgt   = (const float*)d_in[1];
    const float* g1    = (const float*)d_in[2];
    const float* b1    = (const float*)d_in[3];
    const float* Wq    = (const float*)d_in[4];
    const float* bq    = (const float*)d_in[5];
    const float* Wk    = (const float*)d_in[6];
    // d_in[7] = bk: drops out (softmax shift invariance)
    const float* Wv    = (const float*)d_in[8];
    const float* bv    = (const float*)d_in[9];
    const float* Wp    = (const float*)d_in[10];
    const float* bp    = (const float*)d_in[11];
    const float* g2    = (const float*)d_in[12];
    const float* b2    = (const float*)d_in[13];
    const float* Wf1   = (const float*)d_in[14];
    const float* bf1   = (const float*)d_in[15];
    const float* Wf2   = (const float*)d_in[16];
    const float* bf2   = (const float*)d_in[17];

    const int B = in_sizes[1] / (NTOK * DM);

    cudaFuncSetAttribute(k_attn_mma, cudaFuncAttributeMaxDynamicSharedMemorySize, AT_SMEM);
    cudaFuncSetAttribute(k_ffn,      cudaFuncAttributeMaxDynamicSharedMemorySize, B_SMEM_BYTES);

    k_pre<<<5, 256>>>(query, g1, b1, Wq, bq, Wk, Wv, Wp, Wf1, Wf2);
    k_attn_mma<<<B, 256, AT_SMEM>>>(tgt, bv);
    k_ffn<<<(B + GB - 1)/GB, 256, B_SMEM_BYTES>>>(query, bp, g2, b2, bf1, bf2,
                                                  (float*)d_out, B);
}

// round 12
// speedup vs baseline: 2.8057x; 1.3208x over previous
#include <cuda_runtime.h>
#include <cuda_bf16.h>

typedef unsigned long long ull;
typedef unsigned int u32;

#define DM   128
#define NTOK 48
#define TS   132
#define SS   49
#define MAXB 16384

// ---- k_attn_mma smem byte offsets (bf16 rows padded to 272B) ----
#define AT_TGT  0                         // tgt bf16  48x272 = 13056
#define AT_WEFF 13056                     // weff bf16 64x272 = 17408 ; fp32 P overlay (12544) after MMA
#define AT_WV   30464                     // Wv bf16  128x272 = 34816 ; fp32 vproj overlay (25344) after MMA
#define AT_SMEM 65280
#define P_F     3264                      // AT_WEFF/4
#define VP_F    7616                      // AT_WV/4, stride 132 floats

// ---- k_ffn smem (floats) ----
#define GB 8
#define BROWS 64
#define SMB_XA  0
#define SMB_X   8448
#define SMB_N   16896
#define SMB_W   25344
#define SMB_Q   41728
#define SMB_CB  42752
#define B_SMEM_BYTES  (43392*4)

// ---------------- globals ----------------
__device__ __align__(16) float g_weff[64 * DM];
__device__ __align__(16) u32 g_wvHi[128 * 68];    // padded-row bf16x2 image
__device__ __align__(16) u32 g_weffHi[64 * 68];
__device__ __align__(16) float g_WpT [DM * DM];
__device__ __align__(16) float g_Wf1T[DM * DM];
__device__ __align__(16) float g_Wf2T[DM * DM];
__device__ __align__(16) float g_xatt[(size_t)MAXB * 8 * DM];

// ---------------- helpers ----------------
__device__ __forceinline__ void ffma2(ull& d, ull a, ull b) {
    asm("fma.rn.f32x2 %0, %1, %2, %0;" : "+l"(d) : "l"(a), "l"(b));
}
__device__ __forceinline__ ull dup2(float x) {
    ull r; asm("mov.b64 %0, {%1, %1};" : "=l"(r) : "f"(x)); return r;
}
__device__ __forceinline__ void unpack2(ull v, float& lo, float& hi) {
    asm("mov.b64 {%0, %1}, %2;" : "=f"(lo), "=f"(hi) : "l"(v));
}
__device__ __forceinline__ u32 smem_u32(const void* p) {
    u32 a; asm("{ .reg .u64 t; cvta.to.shared.u64 t, %1; cvt.u32.u64 %0, t; }" : "=r"(a) : "l"(p));
    return a;
}
__device__ __forceinline__ u32 bf2(float lo, float hi) {   // word: low half=lo, high=hi
    u32 r; asm("cvt.rn.bf16x2.f32 %0, %1, %2;" : "=r"(r) : "f"(hi), "f"(lo)); return r;
}
__device__ __forceinline__ void ldsm_x4(u32* r, u32 addr) {
    asm volatile("ldmatrix.sync.aligned.m8n8.x4.shared.b16 {%0,%1,%2,%3}, [%4];"
        : "=r"(r[0]), "=r"(r[1]), "=r"(r[2]), "=r"(r[3]) : "r"(addr));
}
__device__ __forceinline__ void ldsm_x2(u32* r, u32 addr) {
    asm volatile("ldmatrix.sync.aligned.m8n8.x2.shared.b16 {%0,%1}, [%2];"
        : "=r"(r[0]), "=r"(r[1]) : "r"(addr));
}
__device__ __forceinline__ void mma_bf16(float* d, const u32* a, const u32* b) {
    asm volatile("mma.sync.aligned.m16n8k16.row.col.f32.bf16.bf16.f32 "
        "{%0,%1,%2,%3}, {%4,%5,%6,%7}, {%8,%9}, {%0,%1,%2,%3};"
        : "+f"(d[0]), "+f"(d[1]), "+f"(d[2]), "+f"(d[3])
        : "r"(a[0]), "r"(a[1]), "r"(a[2]), "r"(a[3]), "r"(b[0]), "r"(b[1]));
}

// =====================================================================
// k_pre, 5 blocks: 0 = LN->q0->weff (+weffHi image); 1..3 = transposes;
// 4 = Wv bf16 image.
// =====================================================================
__global__ void k_pre(const float* __restrict__ q, const float* __restrict__ g1,
                      const float* __restrict__ b1, const float* __restrict__ Wq,
                      const float* __restrict__ bq, const float* __restrict__ Wk,
                      const float* __restrict__ Wv, const float* __restrict__ Wp,
                      const float* __restrict__ Wf1, const float* __restrict__ Wf2)
{
    const int tid = threadIdx.x;
    if (blockIdx.x == 0) {
        __shared__ float qn[8][DM];
        __shared__ float q0s[8][DM];
        const int w = tid >> 5, lane = tid & 31;
        {
            float4 v = *(const float4*)(q + w*DM + lane*4);
            float s  = v.x + v.y + v.z + v.w;
            float sq = v.x*v.x + v.y*v.y + v.z*v.z + v.w*v.w;
            #pragma unroll
            for (int o = 16; o > 0; o >>= 1) {
                s  += __shfl_xor_sync(0xffffffffu, s,  o);
                sq += __shfl_xor_sync(0xffffffffu, sq, o);
            }
            float m = s * (1.f/DM);
            float var = sq * (1.f/DM) - m*m;
            float rs = rsqrtf(var + 1e-5f);
            const int c = lane*4;
            qn[w][c+0] = (v.x - m)*rs*g1[c+0] + b1[c+0];
            qn[w][c+1] = (v.y - m)*rs*g1[c+1] + b1[c+1];
            qn[w][c+2] = (v.z - m)*rs*g1[c+2] + b1[c+2];
            qn[w][c+3] = (v.w - m)*rs*g1[c+3] + b1[c+3];
        }
        __syncthreads();
        for (int o = tid; o < 8*DM; o += 256) {
            int r = o >> 7, c = o & 127;
            float a = bq[c];
            const float4* wr = (const float4*)(Wq + c*DM);
            #pragma unroll 8
            for (int t4 = 0; t4 < 32; t4++) {
                float4 ww = wr[t4];
                a += qn[r][t4*4+0]*ww.x + qn[r][t4*4+1]*ww.y
                   + qn[r][t4*4+2]*ww.z + qn[r][t4*4+3]*ww.w;
            }
            q0s[r][c] = a;
        }
        __syncthreads();
        for (int o = tid; o < 64*DM; o += 256) {
            int p = o >> 7, t = o & 127;
            int r = p >> 3, h = p & 7;
            float a = 0.f;
            #pragma unroll
            for (int d = 0; d < 16; d++)
                a += q0s[r][h*16 + d] * Wk[(h*16 + d)*DM + t];
            g_weff[o] = 0.25f * a;
        }
        __syncthreads();
        // weff bf16 image (padded rows of 68 u32)
        for (int o = tid; o < 64*64; o += 256) {
            int p = o >> 6, tp = o & 63;
            float x0 = g_weff[p*DM + tp*2], x1 = g_weff[p*DM + tp*2 + 1];
            g_weffHi[p*68 + tp] = bf2(x0, x1);
        }
    } else if (blockIdx.x == 4) {
        // Wv bf16 image
        for (int o = tid; o < 128*64; o += 256) {
            int r = o >> 6, tp = o & 63;
            float x0 = Wv[r*DM + tp*2], x1 = Wv[r*DM + tp*2 + 1];
            g_wvHi[r*68 + tp] = bf2(x0, x1);
        }
    } else {
        const float* src; float* dst;
        switch (blockIdx.x) {
            case 1: src = Wp;  dst = g_WpT;  break;
            case 2: src = Wf1; dst = g_Wf1T; break;
            default: src = Wf2; dst = g_Wf2T; break;
        }
        __shared__ float tile[32][33];
        const int tx = tid & 31, ty0 = tid >> 5;
        for (int t = 0; t < 16; t++) {
            const int ti = t >> 2, tj = t & 3;
            #pragma unroll
            for (int k = 0; k < 4; k++) {
                int ty = ty0 + k*8;
                tile[ty][tx] = src[(ti*32+ty)*DM + tj*32 + tx];
            }
            __syncthreads();
            #pragma unroll
            for (int k = 0; k < 4; k++) {
                int ty = ty0 + k*8;
                dst[(tj*32+ty)*DM + ti*32 + tx] = tile[tx][ty];
            }
            __syncthreads();
        }
    }
}

// =====================================================================
// k_attn_mma: 1 batch/CTA, 3 CTAs/SM. bf16 mma.sync -> softmax -> x_att.
// =====================================================================
__global__ __launch_bounds__(256, 3)
void k_attn_mma(const float* __restrict__ tgt, const float* __restrict__ bv)
{
    extern __shared__ float smf[];
    char* smc = (char*)smf;
    const u32 smb = smem_u32(smf);
    const int tid = threadIdx.x;
    const int wid = tid >> 5, lane = tid & 31;
    const int b = blockIdx.x;

    // -------- stage: tgt -> bf16 (convert), Wv/weff images (copy) --------
    {
        const float4* src = (const float4*)(tgt + (size_t)b * NTOK * DM);
        #pragma unroll
        for (int k = 0; k < 6; k++) {
            int i = tid + k*256;
            float4 v = src[i];
            int row = i >> 5, c = (i & 31) * 4;
            u32 off = row*272 + c*2;
            *(u32*)(smc + AT_TGT + off)     = bf2(v.x, v.y);
            *(u32*)(smc + AT_TGT + off + 4) = bf2(v.z, v.w);
        }
        const float4* wh = (const float4*)g_wvHi;
        float4* dH = (float4*)(smc + AT_WV);
        #pragma unroll
        for (int k = 0; k < 9; k++) {
            int i = tid + k*256;
            if (i < 2176) dH[i] = wh[i];
        }
        const float4* we = (const float4*)g_weffHi;
        float4* dE = (float4*)(smc + AT_WEFF);
        #pragma unroll
        for (int k = 0; k < 5; k++) {
            int i = tid + k*256;
            if (i < 1088) dE[i] = we[i];
        }
    }
    __syncthreads();

    // -------- MMA phase (plain bf16) --------
    float accV[8][4];    // vproj warps (0-5)
    float accS[2][6][4]; // score warps (6-7)
    if (wid < 6) {
        const int mt = wid >> 1;          // m-tile (tgt rows mt*16..+15)
        const int nh = wid & 1;           // n-tiles nh*8..nh*8+7
        #pragma unroll
        for (int n = 0; n < 8; n++)
            #pragma unroll
            for (int e = 0; e < 4; e++) accV[n][e] = 0.f;
        const u32 aH = smb + AT_TGT + (mt*16 + (lane & 15))*272 + (lane >> 4)*16;
        const u32 bH = smb + AT_WV + nh*8*2176 + (lane & 7)*272 + ((lane >> 3) & 1)*16;
        #pragma unroll
        for (int k = 0; k < 8; k++) {
            u32 ah[4];
            ldsm_x4(ah, aH + k*32);
            #pragma unroll
            for (int nt = 0; nt < 8; nt++) {
                u32 bh[2];
                ldsm_x2(bh, bH + nt*2176 + k*32);
                mma_bf16(accV[nt], ah, bh);
            }
        }
    } else {
        const int wi = wid - 6;           // m-tiles wi*2, wi*2+1 of weff
        #pragma unroll
        for (int i = 0; i < 2; i++)
            #pragma unroll
            for (int n = 0; n < 6; n++)
                #pragma unroll
                for (int e = 0; e < 4; e++) accS[i][n][e] = 0.f;
        const u32 a0 = smb + AT_WEFF + (wi*32 + (lane & 15))*272 + (lane >> 4)*16;
        const u32 a1 = a0 + 16*272;
        const u32 bH = smb + AT_TGT + (lane & 7)*272 + ((lane >> 3) & 1)*16;
        #pragma unroll
        for (int k = 0; k < 8; k++) {
            u32 aA[4], aB[4];
            ldsm_x4(aA, a0 + k*32);
            ldsm_x4(aB, a1 + k*32);
            #pragma unroll
            for (int nt = 0; nt < 6; nt++) {
                u32 bh[2];
                ldsm_x2(bh, bH + nt*2176 + k*32);
                mma_bf16(accS[0][nt], aA, bh);
                mma_bf16(accS[1][nt], aB, bh);
            }
        }
    }
    __syncthreads();   // MMA reads done; safe to overlay P / vproj

    // -------- epilogues --------
    if (wid < 6) {
        const int mt = wid >> 1, nh = wid & 1;
        const int r0 = mt*16 + (lane >> 2);
        const int c0 = nh*64 + (lane & 3)*2;
        #pragma unroll
        for (int nt = 0; nt < 8; nt++) {
            const int c = c0 + nt*8;
            float bv0 = bv[c], bv1 = bv[c+1];
            smf[VP_F + r0*TS + c]       = accV[nt][0] + bv0;
            smf[VP_F + r0*TS + c + 1]   = accV[nt][1] + bv1;
            smf[VP_F + (r0+8)*TS + c]   = accV[nt][2] + bv0;
            smf[VP_F + (r0+8)*TS + c+1] = accV[nt][3] + bv1;
        }
    } else {
        const int wi = wid - 6;
        #pragma unroll
        for (int i = 0; i < 2; i++) {
            const int r0 = (wi*2 + i)*16 + (lane >> 2);
            #pragma unroll
            for (int nt = 0; nt < 6; nt++) {
                const int c = nt*8 + (lane & 3)*2;
                smf[P_F + r0*SS + c]       = accS[i][nt][0];
                smf[P_F + r0*SS + c + 1]   = accS[i][nt][1];
                smf[P_F + (r0+8)*SS + c]   = accS[i][nt][2];
                smf[P_F + (r0+8)*SS + c+1] = accS[i][nt][3];
            }
        }
    }
    __syncthreads();

    // -------- masked softmax per pair (64 threads) --------
    if (tid < 64) {
        const int p = tid, r = p >> 3;
        int h0 = 0, h1 = 8, w0 = 0, w1 = 6;
        if (r >= 2) {
            int wi = r - 2;
            h0 = (wi / 3) * 4; h1 = h0 + 4;
            w0 = (wi % 3) * 2; w1 = w0 + 2;
        }
        float* row = smf + P_F + p*SS;
        float mx = -1e30f;
        for (int j = 0; j < NTOK; j++) {
            int hh = j / 6, ww = j - hh*6;
            if (hh >= h0 && hh < h1 && ww >= w0 && ww < w1)
                mx = fmaxf(mx, row[j]);
        }
        float sum = 0.f;
        for (int j = 0; j < NTOK; j++) {
            int hh = j / 6, ww = j - hh*6;
            if (hh >= h0 && hh < h1 && ww >= w0 && ww < w1) {
                float e = expf(row[j] - mx);
                row[j] = e; sum += e;
            }
        }
        float inv = 1.f / sum;
        for (int j = 0; j < NTOK; j++) row[j] *= inv;
    }
    __syncthreads();

    // -------- x_att[r] = P[r*8+h] @ vproj -> g_xatt --------
    {
        const int r     = tid >> 5;
        const int lane2 = tid & 31;
        const int col   = lane2 * 4;
        const int h     = lane2 >> 2;    // head = col/16 = lane/4
        const int p     = r*8 + h;
        const float* Pb = smf + P_F + p*SS;
        ull a01 = 0ull, a23 = 0ull;
        if (r < 2) {
            for (int j = 0; j < NTOK; j++) {
                ull f = dup2(Pb[j]);
                ulonglong2 u0 = *(const ulonglong2*)(smf + VP_F + j*TS + col);
                ffma2(a01, f, u0.x); ffma2(a23, f, u0.y);
            }
        } else {
            const int wi = r - 2;
            const int hw = (wi/3)*4, ww = (wi%3)*2;
            #pragma unroll
            for (int m = 0; m < 8; m++) {
                const int j = (hw + (m>>1))*6 + ww + (m&1);
                ull f = dup2(Pb[j]);
                ulonglong2 u0 = *(const ulonglong2*)(smf + VP_F + j*TS + col);
                ffma2(a01, f, u0.x); ffma2(a23, f, u0.y);
            }
        }
        float4 o;
        unpack2(a01, o.x, o.y); unpack2(a23, o.z, o.w);
        *(float4*)(g_xatt + ((size_t)b*8 + r)*DM + col) = o;
    }
}

// =====================================================================
// k_ffn: GB batches per CTA. Wp + residual + LN + FFN. (unchanged, proven)
// =====================================================================
__device__ __forceinline__ void gemm64(const float* __restrict__ A,
                                       const float* __restrict__ W,
                                       int w, int lane, ull acc[8][2])
{
    const int r0  = w * 8;
    const int col = lane * 4;
    for (int k4 = 0; k4 < 32; k4++) {
        float4 a[8];
        #pragma unroll
        for (int r = 0; r < 8; r++)
            a[r] = *(const float4*)(A + (r0+r)*TS + k4*4);
        ulonglong2 b0 = *(const ulonglong2*)(W + (k4*4+0)*DM + col);
        ulonglong2 b1 = *(const ulonglong2*)(W + (k4*4+1)*DM + col);
        ulonglong2 b2 = *(const ulonglong2*)(W + (k4*4+2)*DM + col);
        ulonglong2 b3 = *(const ulonglong2*)(W + (k4*4+3)*DM + col);
        #pragma unroll
        for (int r = 0; r < 8; r++) {
            ffma2(acc[r][0], dup2(a[r].x), b0.x); ffma2(acc[r][1], dup2(a[r].x), b0.y);
            ffma2(acc[r][0], dup2(a[r].y), b1.x); ffma2(acc[r][1], dup2(a[r].y), b1.y);
            ffma2(acc[r][0], dup2(a[r].z), b2.x); ffma2(acc[r][1], dup2(a[r].z), b2.y);
            ffma2(acc[r][0], dup2(a[r].w), b3.x); ffma2(acc[r][1], dup2(a[r].w), b3.y);
        }
    }
}

__global__ __launch_bounds__(256, 1)
void k_ffn(const float* __restrict__ query, const float* __restrict__ bp,
           const float* __restrict__ g2, const float* __restrict__ b2,
           const float* __restrict__ bf1, const float* __restrict__ bf2,
           float* __restrict__ out, int Bn)
{
    extern __shared__ float sm[];
    const int tid  = threadIdx.x;
    const int w    = tid >> 5;
    const int lane = tid & 31;
    const int col  = lane * 4;
    const int b0   = blockIdx.x * GB;
    const int rows_valid = (Bn - b0 >= GB) ? BROWS : (Bn - b0) * 8;

    {
        const float4* src = (const float4*)(g_xatt + (size_t)b0 * 8 * DM);
        #pragma unroll
        for (int k = 0; k < 8; k++) {
            int i = tid + k*256;
            int r = i >> 5, c4 = (i & 31) << 2;
            float4 v = (r < rows_valid) ? src[i] : make_float4(0.f,0.f,0.f,0.f);
            *(float4*)(sm + SMB_XA + r*TS + c4) = v;
        }
        const float4* wsrc = (const float4*)g_WpT;
        float4* wdst = (float4*)(sm + SMB_W);
        #pragma unroll
        for (int k = 0; k < 16; k++) wdst[tid + k*256] = wsrc[tid + k*256];
        ((float4*)(sm + SMB_Q))[tid] = ((const float4*)query)[tid];
        if (tid < 128) {
            sm[SMB_CB +       tid] = bp [tid];
            sm[SMB_CB + 128 + tid] = g2 [tid];
            sm[SMB_CB + 256 + tid] = b2 [tid];
            sm[SMB_CB + 384 + tid] = bf1[tid];
            sm[SMB_CB + 512 + tid] = bf2[tid];
        }
    }
    __syncthreads();

    {
        ull acc[8][2] = {};
        gemm64(sm + SMB_XA, sm + SMB_W, w, lane, acc);
        #pragma unroll
        for (int r = 0; r < 8; r++) {
            const int row = w*8 + r;
            float lo0, hi0, lo1, hi1;
            unpack2(acc[r][0], lo0, hi0); unpack2(acc[r][1], lo1, hi1);
            const float* q = sm + SMB_Q + (row & 7)*DM + col;
            const float* bpc = sm + SMB_CB + col;
            float* dst = sm + SMB_X + row*TS + col;
            dst[0] = q[0] + bpc[0] + lo0;
            dst[1] = q[1] + bpc[1] + hi0;
            dst[2] = q[2] + bpc[2] + lo1;
            dst[3] = q[3] + bpc[3] + hi1;
        }
    }
    __syncthreads();

    {
        #pragma unroll
        for (int r = 0; r < 8; r++) {
            const int row = w*8 + r;
            const float* xr = sm + SMB_X + row*TS + col;
            float v0 = xr[0], v1 = xr[1], v2 = xr[2], v3 = xr[3];
            float sum = v0+v1+v2+v3;
            float sq  = v0*v0+v1*v1+v2*v2+v3*v3;
            #pragma unroll
            for (int o = 16; o > 0; o >>= 1) {
                sum += __shfl_xor_sync(0xffffffffu, sum, o);
                sq  += __shfl_xor_sync(0xffffffffu, sq,  o);
            }
            float m   = sum * (1.f/DM);
            float var = sq * (1.f/DM) - m*m;
            float rs  = rsqrtf(var + 1e-5f);
            float* nr = sm + SMB_N + row*TS + col;
            const float* g2c = sm + SMB_CB + 128 + col;
            const float* b2c = sm + SMB_CB + 256 + col;
            nr[0] = (v0 - m)*rs*g2c[0] + b2c[0];
            nr[1] = (v1 - m)*rs*g2c[1] + b2c[1];
            nr[2] = (v2 - m)*rs*g2c[2] + b2c[2];
            nr[3] = (v3 - m)*rs*g2c[3] + b2c[3];
        }
        const float4* wsrc = (const float4*)g_Wf1T;
        float4* wdst = (float4*)(sm + SMB_W);
        #pragma unroll
        for (int k = 0; k < 16; k++) wdst[tid + k*256] = wsrc[tid + k*256];
    }
    __syncthreads();

    {
        ull acc[8][2] = {};
        gemm64(sm + SMB_N, sm + SMB_W, w, lane, acc);
        __syncthreads();
        #pragma unroll
        for (int r = 0; r < 8; r++) {
            const int row = w*8 + r;
            float z[4];
            unpack2(acc[r][0], z[0], z[1]); unpack2(acc[r][1], z[2], z[3]);
            float* nr = sm + SMB_N + row*TS + col;
            const float* bc = sm + SMB_CB + 384 + col;
            #pragma unroll
            for (int k = 0; k < 4; k++) {
                float zz = z[k] + bc[k];
                nr[k] = 0.5f * zz * (1.f + erff(zz * 0.7071067811865476f));
            }
        }
        const float4* wsrc = (const float4*)g_Wf2T;
        float4* wdst = (float4*)(sm + SMB_W);
        #pragma unroll
        for (int k = 0; k < 16; k++) wdst[tid + k*256] = wsrc[tid + k*256];
    }
    __syncthreads();

    {
        ull acc[8][2] = {};
        gemm64(sm + SMB_N, sm + SMB_W, w, lane, acc);
        #pragma unroll
        for (int r = 0; r < 8; r++) {
            const int row = w*8 + r;
            if (row >= rows_valid) continue;
            float lo0, hi0, lo1, hi1;
            unpack2(acc[r][0], lo0, hi0); unpack2(acc[r][1], lo1, hi1);
            const float* xr = sm + SMB_X + row*TS + col;
            const float* bc = sm + SMB_CB + 512 + col;
            float4 res;
            res.x = xr[0] + bc[0] + lo0;
            res.y = xr[1] + bc[1] + hi0;
            res.z = xr[2] + bc[2] + lo1;
            res.w = xr[3] + bc[3] + hi1;
            *(float4*)(out + ((size_t)b0*8 + row)*DM + col) = res;
        }
    }
}

// =====================================================================
extern "C" void kernel_launch(void* const* d_in, const int* in_sizes, int n_in,
                              void* d_out, int out_size)
{
    const float* query = (const float*)d_in[0];
    const float* tgt   = (const float*)d_in[1];
    const float* g1    = (const float*)d_in[2];
    const float* b1    = (const float*)d_in[3];
    const float* Wq    = (const float*)d_in[4];
    const float* bq    = (const float*)d_in[5];
    const float* Wk    = (const float*)d_in[6];
    // d_in[7] = bk: drops out (softmax shift invariance)
    const float* Wv    = (const float*)d_in[8];
    const float* bv    = (const float*)d_in[9];
    const float* Wp    = (const float*)d_in[10];
    const float* bp    = (const float*)d_in[11];
    const float* g2    = (const float*)d_in[12];
    const float* b2    = (const float*)d_in[13];
    const float* Wf1   = (const float*)d_in[14];
    const float* bf1   = (const float*)d_in[15];
    const float* Wf2   = (const float*)d_in[16];
    const float* bf2   = (const float*)d_in[17];

    const int B = in_sizes[1] / (NTOK * DM);

    cudaFuncSetAttribute(k_attn_mma, cudaFuncAttributeMaxDynamicSharedMemorySize, AT_SMEM);
    cudaFuncSetAttribute(k_ffn,      cudaFuncAttributeMaxDynamicSharedMemorySize, B_SMEM_BYTES);

    k_pre<<<5, 256>>>(query, g1, b1, Wq, bq, Wk, Wv, Wp, Wf1, Wf2);
    k_attn_mma<<<B, 256, AT_SMEM>>>(tgt, bv);
    k_ffn<<<(B + GB - 1)/GB, 256, B_SMEM_BYTES>>>(query, bp, g2, b2, bf1, bf2,
                                                  (float*)d_out, B);
}

// round 14
// speedup vs baseline: 4.1158x; 1.4669x over previous
#include <cuda_runtime.h>
#include <cuda_bf16.h>

typedef unsigned long long ull;
typedef unsigned int u32;

#define DM   128
#define NTOK 48
#define TS   132
#define SS   49
#define MAXB 16384

// ---- k_attn_mma smem byte offsets (bf16 rows padded to 272B) ----
#define AT_TGT  0                         // tgt bf16  48x272 = 13056
#define AT_WEFF 13056                     // weff bf16 64x272 = 17408 ; fp32 P overlay after MMA
#define AT_WV   30464                     // Wv bf16  128x272 = 34816 ; fp32 vproj overlay after MMA
#define AT_SMEM 65280
#define P_F     3264                      // AT_WEFF/4
#define VP_F    7616                      // AT_WV/4, stride 132 floats

// ---- k_ffn smem byte offsets ----
#define GB 8
#define BROWS 64
#define FB_A   0                          // A bf16 tile 64x272 = 17408 (x_att -> xn -> h)
#define FB_B   17408                      // B bf16 tile 128x272 = 34816 (Wp -> Wf1 -> Wf2)
#define FB_X   52224                      // x fp32 64x132x4 = 33792
#define FB_Q   86016                      // query fp32 8x128x4 = 4096
#define FB_C   90112                      // consts 5x128x4 = 2560
#define FB_SMEM 92672
#define X_F    13056                      // FB_X/4
#define Q_F    21504                      // FB_Q/4
#define C_F    22528                      // FB_C/4

// ---------------- globals ----------------
__device__ __align__(16) float g_weff[64 * DM];
__device__ __align__(16) u32 g_wvHi [128 * 68];   // padded-row bf16x2 images
__device__ __align__(16) u32 g_weffHi[64 * 68];
__device__ __align__(16) u32 g_wpB  [128 * 68];
__device__ __align__(16) u32 g_wf1B [128 * 68];
__device__ __align__(16) u32 g_wf2B [128 * 68];
__device__ __align__(16) float g_xatt[(size_t)MAXB * 8 * DM];

// ---------------- helpers ----------------
__device__ __forceinline__ void ffma2(ull& d, ull a, ull b) {
    asm("fma.rn.f32x2 %0, %1, %2, %0;" : "+l"(d) : "l"(a), "l"(b));
}
__device__ __forceinline__ ull dup2(float x) {
    ull r; asm("mov.b64 %0, {%1, %1};" : "=l"(r) : "f"(x)); return r;
}
__device__ __forceinline__ void unpack2(ull v, float& lo, float& hi) {
    asm("mov.b64 {%0, %1}, %2;" : "=f"(lo), "=f"(hi) : "l"(v));
}
__device__ __forceinline__ u32 smem_u32(const void* p) {
    u32 a; asm("{ .reg .u64 t; cvta.to.shared.u64 t, %1; cvt.u32.u64 %0, t; }" : "=r"(a) : "l"(p));
    return a;
}
__device__ __forceinline__ u32 cvt2(float lo, float hi) {   // bf16x2 word: low half=lo
    u32 r; asm("cvt.rn.bf16x2.f32 %0, %1, %2;" : "=r"(r) : "f"(hi), "f"(lo)); return r;
}
__device__ __forceinline__ void ldsm_x4(u32* r, u32 addr) {
    asm volatile("ldmatrix.sync.aligned.m8n8.x4.shared.b16 {%0,%1,%2,%3}, [%4];"
        : "=r"(r[0]), "=r"(r[1]), "=r"(r[2]), "=r"(r[3]) : "r"(addr));
}
__device__ __forceinline__ void ldsm_x2(u32* r, u32 addr) {
    asm volatile("ldmatrix.sync.aligned.m8n8.x2.shared.b16 {%0,%1}, [%2];"
        : "=r"(r[0]), "=r"(r[1]) : "r"(addr));
}
__device__ __forceinline__ void mma_bf16(float* d, const u32* a, const u32* b) {
    asm volatile("mma.sync.aligned.m16n8k16.row.col.f32.bf16.bf16.f32 "
        "{%0,%1,%2,%3}, {%4,%5,%6,%7}, {%8,%9}, {%0,%1,%2,%3};"
        : "+f"(d[0]), "+f"(d[1]), "+f"(d[2]), "+f"(d[3])
        : "r"(a[0]), "r"(a[1]), "r"(a[2]), "r"(a[3]), "r"(b[0]), "r"(b[1]));
}
// 64x128x128 GEMM slice for one warp: 8 n-tiles, 1 m-tile; acc[nt][e]
__device__ __forceinline__ void gemm_mma(float acc[8][4], u32 aAddr, u32 bAddr) {
    #pragma unroll
    for (int n = 0; n < 8; n++)
        #pragma unroll
        for (int e = 0; e < 4; e++) acc[n][e] = 0.f;
    #pragma unroll
    for (int k = 0; k < 8; k++) {
        u32 a[4];
        ldsm_x4(a, aAddr + k*32);
        #pragma unroll
        for (int nt = 0; nt < 8; nt++) {
            u32 bb[2];
            ldsm_x2(bb, bAddr + nt*2176 + k*32);
            mma_bf16(acc[nt], a, bb);
        }
    }
}

// =====================================================================
// k_pre, 5 blocks: 0 = LN->q0->weff (+weffHi image); 1..3 = Wp/Wf1/Wf2
// bf16 images (original layout); 4 = Wv bf16 image.
// =====================================================================
__global__ void k_pre(const float* __restrict__ q, const float* __restrict__ g1,
                      const float* __restrict__ b1, const float* __restrict__ Wq,
                      const float* __restrict__ bq, const float* __restrict__ Wk,
                      const float* __restrict__ Wv, const float* __restrict__ Wp,
                      const float* __restrict__ Wf1, const float* __restrict__ Wf2)
{
    const int tid = threadIdx.x;
    if (blockIdx.x == 0) {
        __shared__ float qn[8][DM];
        __shared__ float q0s[8][DM];
        const int w = tid >> 5, lane = tid & 31;
        {
            float4 v = *(const float4*)(q + w*DM + lane*4);
            float s  = v.x + v.y + v.z + v.w;
            float sq = v.x*v.x + v.y*v.y + v.z*v.z + v.w*v.w;
            #pragma unroll
            for (int o = 16; o > 0; o >>= 1) {
                s  += __shfl_xor_sync(0xffffffffu, s,  o);
                sq += __shfl_xor_sync(0xffffffffu, sq, o);
            }
            float m = s * (1.f/DM);
            float var = sq * (1.f/DM) - m*m;
            float rs = rsqrtf(var + 1e-5f);
            const int c = lane*4;
            qn[w][c+0] = (v.x - m)*rs*g1[c+0] + b1[c+0];
            qn[w][c+1] = (v.y - m)*rs*g1[c+1] + b1[c+1];
            qn[w][c+2] = (v.z - m)*rs*g1[c+2] + b1[c+2];
            qn[w][c+3] = (v.w - m)*rs*g1[c+3] + b1[c+3];
        }
        __syncthreads();
        for (int o = tid; o < 8*DM; o += 256) {
            int r = o >> 7, c = o & 127;
            float a = bq[c];
            const float4* wr = (const float4*)(Wq + c*DM);
            #pragma unroll 8
            for (int t4 = 0; t4 < 32; t4++) {
                float4 ww = wr[t4];
                a += qn[r][t4*4+0]*ww.x + qn[r][t4*4+1]*ww.y
                   + qn[r][t4*4+2]*ww.z + qn[r][t4*4+3]*ww.w;
            }
            q0s[r][c] = a;
        }
        __syncthreads();
        for (int o = tid; o < 64*DM; o += 256) {
            int p = o >> 7, t = o & 127;
            int r = p >> 3, h = p & 7;
            float a = 0.f;
            #pragma unroll
            for (int d = 0; d < 16; d++)
                a += q0s[r][h*16 + d] * Wk[(h*16 + d)*DM + t];
            g_weff[o] = 0.25f * a;
        }
        __syncthreads();
        for (int o = tid; o < 64*64; o += 256) {
            int p = o >> 6, tp = o & 63;
            g_weffHi[p*68 + tp] = cvt2(g_weff[p*DM + tp*2], g_weff[p*DM + tp*2 + 1]);
        }
    } else {
        const float* src; u32* dst;
        switch (blockIdx.x) {
            case 1: src = Wp;  dst = g_wpB;  break;
            case 2: src = Wf1; dst = g_wf1B; break;
            case 3: src = Wf2; dst = g_wf2B; break;
            default: src = Wv; dst = g_wvHi; break;
        }
        for (int o = tid; o < 128*64; o += 256) {
            int r = o >> 6, tp = o & 63;
            dst[r*68 + tp] = cvt2(src[r*DM + tp*2], src[r*DM + tp*2 + 1]);
        }
    }
}

// =====================================================================
// k_attn_mma: 1 batch/CTA, 3 CTAs/SM. bf16 mma.sync -> softmax -> x_att.
// (unchanged from R12 — passing at rel_err 3.8e-5)
// =====================================================================
__global__ __launch_bounds__(256, 3)
void k_attn_mma(const float* __restrict__ tgt, const float* __restrict__ bv)
{
    extern __shared__ float smf[];
    char* smc = (char*)smf;
    const u32 smb = smem_u32(smf);
    const int tid = threadIdx.x;
    const int wid = tid >> 5, lane = tid & 31;
    const int b = blockIdx.x;

    // -------- stage: tgt -> bf16 (convert), Wv/weff images (copy) --------
    {
        const float4* src = (const float4*)(tgt + (size_t)b * NTOK * DM);
        #pragma unroll
        for (int k = 0; k < 6; k++) {
            int i = tid + k*256;
            float4 v = src[i];
            int row = i >> 5, c = (i & 31) * 4;
            u32 off = row*272 + c*2;
            *(u32*)(smc + AT_TGT + off)     = cvt2(v.x, v.y);
            *(u32*)(smc + AT_TGT + off + 4) = cvt2(v.z, v.w);
        }
        const float4* wh = (const float4*)g_wvHi;
        float4* dH = (float4*)(smc + AT_WV);
        #pragma unroll
        for (int k = 0; k < 9; k++) {
            int i = tid + k*256;
            if (i < 2176) dH[i] = wh[i];
        }
        const float4* we = (const float4*)g_weffHi;
        float4* dE = (float4*)(smc + AT_WEFF);
        #pragma unroll
        for (int k = 0; k < 5; k++) {
            int i = tid + k*256;
            if (i < 1088) dE[i] = we[i];
        }
    }
    __syncthreads();

    // -------- MMA phase --------
    float accV[8][4];    // vproj warps (0-5)
    float accS[2][6][4]; // score warps (6-7)
    if (wid < 6) {
        const int mt = wid >> 1;
        const int nh = wid & 1;
        #pragma unroll
        for (int n = 0; n < 8; n++)
            #pragma unroll
            for (int e = 0; e < 4; e++) accV[n][e] = 0.f;
        const u32 aH = smb + AT_TGT + (mt*16 + (lane & 15))*272 + (lane >> 4)*16;
        const u32 bH = smb + AT_WV + nh*8*2176 + (lane & 7)*272 + ((lane >> 3) & 1)*16;
        #pragma unroll
        for (int k = 0; k < 8; k++) {
            u32 ah[4];
            ldsm_x4(ah, aH + k*32);
            #pragma unroll
            for (int nt = 0; nt < 8; nt++) {
                u32 bh[2];
                ldsm_x2(bh, bH + nt*2176 + k*32);
                mma_bf16(accV[nt], ah, bh);
            }
        }
    } else {
        const int wi = wid - 6;
        #pragma unroll
        for (int i = 0; i < 2; i++)
            #pragma unroll
            for (int n = 0; n < 6; n++)
                #pragma unroll
                for (int e = 0; e < 4; e++) accS[i][n][e] = 0.f;
        const u32 a0 = smb + AT_WEFF + (wi*32 + (lane & 15))*272 + (lane >> 4)*16;
        const u32 a1 = a0 + 16*272;
        const u32 bH = smb + AT_TGT + (lane & 7)*272 + ((lane >> 3) & 1)*16;
        #pragma unroll
        for (int k = 0; k < 8; k++) {
            u32 aA[4], aB[4];
            ldsm_x4(aA, a0 + k*32);
            ldsm_x4(aB, a1 + k*32);
            #pragma unroll
            for (int nt = 0; nt < 6; nt++) {
                u32 bh[2];
                ldsm_x2(bh, bH + nt*2176 + k*32);
                mma_bf16(accS[0][nt], aA, bh);
                mma_bf16(accS[1][nt], aB, bh);
            }
        }
    }
    __syncthreads();

    // -------- epilogues --------
    if (wid < 6) {
        const int mt = wid >> 1, nh = wid & 1;
        const int r0 = mt*16 + (lane >> 2);
        const int c0 = nh*64 + (lane & 3)*2;
        #pragma unroll
        for (int nt = 0; nt < 8; nt++) {
            const int c = c0 + nt*8;
            float bv0 = bv[c], bv1 = bv[c+1];
            smf[VP_F + r0*TS + c]       = accV[nt][0] + bv0;
            smf[VP_F + r0*TS + c + 1]   = accV[nt][1] + bv1;
            smf[VP_F + (r0+8)*TS + c]   = accV[nt][2] + bv0;
            smf[VP_F + (r0+8)*TS + c+1] = accV[nt][3] + bv1;
        }
    } else {
        const int wi = wid - 6;
        #pragma unroll
        for (int i = 0; i < 2; i++) {
            const int r0 = (wi*2 + i)*16 + (lane >> 2);
            #pragma unroll
            for (int nt = 0; nt < 6; nt++) {
                const int c = nt*8 + (lane & 3)*2;
                smf[P_F + r0*SS + c]       = accS[i][nt][0];
                smf[P_F + r0*SS + c + 1]   = accS[i][nt][1];
                smf[P_F + (r0+8)*SS + c]   = accS[i][nt][2];
                smf[P_F + (r0+8)*SS + c+1] = accS[i][nt][3];
            }
        }
    }
    __syncthreads();

    // -------- masked softmax per pair --------
    if (tid < 64) {
        const int p = tid, r = p >> 3;
        int h0 = 0, h1 = 8, w0 = 0, w1 = 6;
        if (r >= 2) {
            int wi = r - 2;
            h0 = (wi / 3) * 4; h1 = h0 + 4;
            w0 = (wi % 3) * 2; w1 = w0 + 2;
        }
        float* row = smf + P_F + p*SS;
        float mx = -1e30f;
        for (int j = 0; j < NTOK; j++) {
            int hh = j / 6, ww = j - hh*6;
            if (hh >= h0 && hh < h1 && ww >= w0 && ww < w1)
                mx = fmaxf(mx, row[j]);
        }
        float sum = 0.f;
        for (int j = 0; j < NTOK; j++) {
            int hh = j / 6, ww = j - hh*6;
            if (hh >= h0 && hh < h1 && ww >= w0 && ww < w1) {
                float e = expf(row[j] - mx);
                row[j] = e; sum += e;
            }
        }
        float inv = 1.f / sum;
        for (int j = 0; j < NTOK; j++) row[j] *= inv;
    }
    __syncthreads();

    // -------- x_att[r] = P[r*8+h] @ vproj -> g_xatt --------
    {
        const int r     = tid >> 5;
        const int lane2 = tid & 31;
        const int col   = lane2 * 4;
        const int h     = lane2 >> 2;
        const int p     = r*8 + h;
        const float* Pb = smf + P_F + p*SS;
        ull a01 = 0ull, a23 = 0ull;
        if (r < 2) {
            for (int j = 0; j < NTOK; j++) {
                ull f = dup2(Pb[j]);
                ulonglong2 u0 = *(const ulonglong2*)(smf + VP_F + j*TS + col);
                ffma2(a01, f, u0.x); ffma2(a23, f, u0.y);
            }
        } else {
            const int wi = r - 2;
            const int hw = (wi/3)*4, ww = (wi%3)*2;
            #pragma unroll
            for (int m = 0; m < 8; m++) {
                const int j = (hw + (m>>1))*6 + ww + (m&1);
                ull f = dup2(Pb[j]);
                ulonglong2 u0 = *(const ulonglong2*)(smf + VP_F + j*TS + col);
                ffma2(a01, f, u0.x); ffma2(a23, f, u0.y);
            }
        }
        float4 o;
        unpack2(a01, o.x, o.y); unpack2(a23, o.z, o.w);
        *(float4*)(g_xatt + ((size_t)b*8 + r)*DM + col) = o;
    }
}

// =====================================================================
// k_ffn: GB=8 batches/CTA, 2 CTAs/SM. Three bf16 mma.sync GEMMs.
// =====================================================================
__global__ __launch_bounds__(256, 2)
void k_ffn(const float* __restrict__ query, const float* __restrict__ bp,
           const float* __restrict__ g2, const float* __restrict__ b2,
           const float* __restrict__ bf1, const float* __restrict__ bf2,
           float* __restrict__ out, int Bn)
{
    extern __shared__ float smf[];
    char* smc = (char*)smf;
    const u32 smb = smem_u32(smf);
    const int tid  = threadIdx.x;
    const int wid  = tid >> 5;
    const int lane = tid & 31;
    const int b0   = blockIdx.x * GB;
    const int rows_valid = (Bn - b0 >= GB) ? BROWS : (Bn - b0) * 8;

    const int mt = wid >> 1, nh = wid & 1;
    const u32 aAddr = smb + FB_A + (mt*16 + (lane & 15))*272 + (lane >> 4)*16;
    const u32 bAddr = smb + FB_B + nh*8*2176 + (lane & 7)*272 + ((lane >> 3) & 1)*16;
    const int r0 = mt*16 + (lane >> 2);
    const int c0 = nh*64 + (lane & 3)*2;

    // -------- stage: x_att -> bf16 A tile; Wp image -> B; query; consts --------
    {
        const float4* src = (const float4*)(g_xatt + (size_t)b0 * 8 * DM);
        #pragma unroll
        for (int k = 0; k < 8; k++) {
            int i = tid + k*256;
            int r = i >> 5, c = (i & 31) * 4;
            float4 v = (r < rows_valid) ? src[i] : make_float4(0.f,0.f,0.f,0.f);
            u32 off = r*272 + c*2;
            *(u32*)(smc + FB_A + off)     = cvt2(v.x, v.y);
            *(u32*)(smc + FB_A + off + 4) = cvt2(v.z, v.w);
        }
        const float4* wb = (const float4*)g_wpB;
        float4* dB = (float4*)(smc + FB_B);
        #pragma unroll
        for (int k = 0; k < 9; k++) {
            int i = tid + k*256;
            if (i < 2176) dB[i] = wb[i];
        }
        ((float4*)(smc + FB_Q))[tid] = ((const float4*)query)[tid];
        if (tid < 128) {
            smf[C_F +       tid] = bp [tid];
            smf[C_F + 128 + tid] = g2 [tid];
            smf[C_F + 256 + tid] = b2 [tid];
            smf[C_F + 384 + tid] = bf1[tid];
            smf[C_F + 512 + tid] = bf2[tid];
        }
    }
    __syncthreads();

    // -------- GEMM1: x = query + x_att @ Wp^T + bp  (fp32 out) --------
    {
        float acc[8][4];
        gemm_mma(acc, aAddr, bAddr);
        #pragma unroll
        for (int nt = 0; nt < 8; nt++) {
            const int c = c0 + nt*8;
            float q0a = smf[Q_F + (r0 & 7)*DM + c];
            float q1a = smf[Q_F + (r0 & 7)*DM + c + 1];
            float q0b = smf[Q_F + ((r0+8) & 7)*DM + c];
            float q1b = smf[Q_F + ((r0+8) & 7)*DM + c + 1];
            float bp0 = smf[C_F + c], bp1 = smf[C_F + c + 1];
            smf[X_F + r0*TS + c]       = q0a + bp0 + acc[nt][0];
            smf[X_F + r0*TS + c + 1]   = q1a + bp1 + acc[nt][1];
            smf[X_F + (r0+8)*TS + c]   = q0b + bp0 + acc[nt][2];
            smf[X_F + (r0+8)*TS + c+1] = q1b + bp1 + acc[nt][3];
        }
    }
    __syncthreads();

    // -------- LN (fp32) -> xn bf16 into A tile; restage B <- Wf1 --------
    {
        #pragma unroll
        for (int r = 0; r < 8; r++) {
            const int row = wid*8 + r;
            const float* xr = smf + X_F + row*TS + lane*4;
            float v0 = xr[0], v1 = xr[1], v2 = xr[2], v3 = xr[3];
            float sum = v0+v1+v2+v3;
            float sq  = v0*v0+v1*v1+v2*v2+v3*v3;
            #pragma unroll
            for (int o = 16; o > 0; o >>= 1) {
                sum += __shfl_xor_sync(0xffffffffu, sum, o);
                sq  += __shfl_xor_sync(0xffffffffu, sq,  o);
            }
            float m   = sum * (1.f/DM);
            float var = sq * (1.f/DM) - m*m;
            float rs  = rsqrtf(var + 1e-5f);
            const int c = lane*4;
            float n0 = (v0 - m)*rs*smf[C_F + 128 + c  ] + smf[C_F + 256 + c  ];
            float n1 = (v1 - m)*rs*smf[C_F + 128 + c+1] + smf[C_F + 256 + c+1];
            float n2 = (v2 - m)*rs*smf[C_F + 128 + c+2] + smf[C_F + 256 + c+2];
            float n3 = (v3 - m)*rs*smf[C_F + 128 + c+3] + smf[C_F + 256 + c+3];
            u32 off = row*272 + c*2;
            *(u32*)(smc + FB_A + off)     = cvt2(n0, n1);
            *(u32*)(smc + FB_A + off + 4) = cvt2(n2, n3);
        }
        const float4* wb = (const float4*)g_wf1B;
        float4* dB = (float4*)(smc + FB_B);
        #pragma unroll
        for (int k = 0; k < 9; k++) {
            int i = tid + k*256;
            if (i < 2176) dB[i] = wb[i];
        }
    }
    __syncthreads();

    // -------- GEMM2: h = gelu(xn @ Wf1^T + bf1) -> bf16 into A tile --------
    {
        float acc[8][4];
        gemm_mma(acc, aAddr, bAddr);
        __syncthreads();          // all reads of xn / Wf1 done
        #pragma unroll
        for (int nt = 0; nt < 8; nt++) {
            const int c = c0 + nt*8;
            float bf1a = smf[C_F + 384 + c], bf1b = smf[C_F + 384 + c + 1];
            float z0 = acc[nt][0] + bf1a;
            float z1 = acc[nt][1] + bf1b;
            float z2 = acc[nt][2] + bf1a;
            float z3 = acc[nt][3] + bf1b;
            float h0 = 0.5f * z0 * (1.f + erff(z0 * 0.7071067811865476f));
            float h1 = 0.5f * z1 * (1.f + erff(z1 * 0.7071067811865476f));
            float h2 = 0.5f * z2 * (1.f + erff(z2 * 0.7071067811865476f));
            float h3 = 0.5f * z3 * (1.f + erff(z3 * 0.7071067811865476f));
            *(u32*)(smc + FB_A + r0*272 + c*2)     = cvt2(h0, h1);
            *(u32*)(smc + FB_A + (r0+8)*272 + c*2) = cvt2(h2, h3);
        }
        const float4* wb = (const float4*)g_wf2B;
        float4* dB = (float4*)(smc + FB_B);
        #pragma unroll
        for (int k = 0; k < 9; k++) {
            int i = tid + k*256;
            if (i < 2176) dB[i] = wb[i];
        }
    }
    __syncthreads();

    // -------- GEMM3: out = x + h @ Wf2^T + bf2 --------
    {
        float acc[8][4];
        gemm_mma(acc, aAddr, bAddr);
        #pragma unroll
        for (int nt = 0; nt < 8; nt++) {
            const int c = c0 + nt*8;
            float bf2a = smf[C_F + 512 + c], bf2b = smf[C_F + 512 + c + 1];
            if (r0 < rows_valid) {
                float2 res;
                res.x = smf[X_F + r0*TS + c]     + bf2a + acc[nt][0];
                res.y = smf[X_F + r0*TS + c + 1] + bf2b + acc[nt][1];
                *(float2*)(out + ((size_t)b0*8 + r0)*DM + c) = res;
            }
            if (r0 + 8 < rows_valid) {
                float2 res;
                res.x = smf[X_F + (r0+8)*TS + c]     + bf2a + acc[nt][2];
                res.y = smf[X_F + (r0+8)*TS + c + 1] + bf2b + acc[nt][3];
                *(float2*)(out + ((size_t)b0*8 + r0 + 8)*DM + c) = res;
            }
        }
    }
}

// =====================================================================
extern "C" void kernel_launch(void* const* d_in, const int* in_sizes, int n_in,
                              void* d_out, int out_size)
{
    const float* query = (const float*)d_in[0];
    const float* tgt   = (const float*)d_in[1];
    const float* g1    = (const float*)d_in[2];
    const float* b1    = (const float*)d_in[3];
    const float* Wq    = (const float*)d_in[4];
    const float* bq    = (const float*)d_in[5];
    const float* Wk    = (const float*)d_in[6];
    // d_in[7] = bk: drops out (softmax shift invariance)
    const float* Wv    = (const float*)d_in[8];
    const float* bv    = (const float*)d_in[9];
    const float* Wp    = (const float*)d_in[10];
    const float* bp    = (const float*)d_in[11];
    const float* g2    = (const float*)d_in[12];
    const float* b2    = (const float*)d_in[13];
    const float* Wf1   = (const float*)d_in[14];
    const float* bf1   = (const float*)d_in[15];
    const float* Wf2   = (const float*)d_in[16];
    const float* bf2   = (const float*)d_in[17];

    const int B = in_sizes[1] / (NTOK * DM);

    cudaFuncSetAttribute(k_attn_mma, cudaFuncAttributeMaxDynamicSharedMemorySize, AT_SMEM);
    cudaFuncSetAttribute(k_ffn,      cudaFuncAttributeMaxDynamicSharedMemorySize, FB_SMEM);

    k_pre<<<5, 256>>>(query, g1, b1, Wq, bq, Wk, Wv, Wp, Wf1, Wf2);
    k_attn_mma<<<B, 256, AT_SMEM>>>(tgt, bv);
    k_ffn<<<(B + GB - 1)/GB, 256, FB_SMEM>>>(query, bp, g2, b2, bf1, bf2,
                                             (float*)d_out, B);
}

// round 15
// speedup vs baseline: 5.1406x; 1.2490x over previous
#include <cuda_runtime.h>
#include <cuda_bf16.h>

typedef unsigned long long ull;
typedef unsigned int u32;

#define DM   128
#define NTOK 48
#define TS   132
#define SS   49
#define MAXB 16384

// ---- k_attn_ws smem byte offsets (bf16 rows padded to 272B) ----
#define WS_WEFF 0                         // weff bf16 64x272  = 17408
#define WS_WV   17408                     // Wv  bf16 128x272  = 34816
#define WS_TGT  52224                     // tgt bf16 4x48x272 = 52224
#define WS_P    104448                    // P fp32 2 x 64x49x4  = 25088
#define WS_VP   129536                    // VP fp32 2 x 48x132x4 = 50688
#define WS_SMEM 180224
// float indices
#define PF(kb)  (26112 + (kb)*3136)
#define VPF(kb) (32384 + (kb)*6336)

// ---- k_ffn smem byte offsets ----
#define GB 8
#define BROWS 64
#define FB_A   0
#define FB_B   17408
#define FB_X   52224
#define FB_Q   86016
#define FB_C   90112
#define FB_SMEM 92672
#define X_F    13056
#define Q_F    21504
#define C_F    22528

// ---------------- globals ----------------
__device__ __align__(16) u32 g_wvHi [128 * 68];
__device__ __align__(16) u32 g_weffHi[64 * 68];
__device__ __align__(16) u32 g_wpB  [128 * 68];
__device__ __align__(16) u32 g_wf1B [128 * 68];
__device__ __align__(16) u32 g_wf2B [128 * 68];
__device__ __align__(16) float g_xatt[(size_t)MAXB * 8 * DM];

// ---------------- helpers ----------------
__device__ __forceinline__ void ffma2(ull& d, ull a, ull b) {
    asm("fma.rn.f32x2 %0, %1, %2, %0;" : "+l"(d) : "l"(a), "l"(b));
}
__device__ __forceinline__ ull dup2(float x) {
    ull r; asm("mov.b64 %0, {%1, %1};" : "=l"(r) : "f"(x)); return r;
}
__device__ __forceinline__ void unpack2(ull v, float& lo, float& hi) {
    asm("mov.b64 {%0, %1}, %2;" : "=f"(lo), "=f"(hi) : "l"(v));
}
__device__ __forceinline__ u32 smem_u32(const void* p) {
    u32 a; asm("{ .reg .u64 t; cvta.to.shared.u64 t, %1; cvt.u32.u64 %0, t; }" : "=r"(a) : "l"(p));
    return a;
}
__device__ __forceinline__ u32 cvt2(float lo, float hi) {
    u32 r; asm("cvt.rn.bf16x2.f32 %0, %1, %2;" : "=r"(r) : "f"(hi), "f"(lo)); return r;
}
__device__ __forceinline__ void ldsm_x4(u32* r, u32 addr) {
    asm volatile("ldmatrix.sync.aligned.m8n8.x4.shared.b16 {%0,%1,%2,%3}, [%4];"
        : "=r"(r[0]), "=r"(r[1]), "=r"(r[2]), "=r"(r[3]) : "r"(addr));
}
__device__ __forceinline__ void ldsm_x2(u32* r, u32 addr) {
    asm volatile("ldmatrix.sync.aligned.m8n8.x2.shared.b16 {%0,%1}, [%2];"
        : "=r"(r[0]), "=r"(r[1]) : "r"(addr));
}
__device__ __forceinline__ void mma_bf16(float* d, const u32* a, const u32* b) {
    asm volatile("mma.sync.aligned.m16n8k16.row.col.f32.bf16.bf16.f32 "
        "{%0,%1,%2,%3}, {%4,%5,%6,%7}, {%8,%9}, {%0,%1,%2,%3};"
        : "+f"(d[0]), "+f"(d[1]), "+f"(d[2]), "+f"(d[3])
        : "r"(a[0]), "r"(a[1]), "r"(a[2]), "r"(a[3]), "r"(b[0]), "r"(b[1]));
}
__device__ __forceinline__ void gemm_mma(float acc[8][4], u32 aAddr, u32 bAddr) {
    #pragma unroll
    for (int n = 0; n < 8; n++)
        #pragma unroll
        for (int e = 0; e < 4; e++) acc[n][e] = 0.f;
    #pragma unroll
    for (int k = 0; k < 8; k++) {
        u32 a[4];
        ldsm_x4(a, aAddr + k*32);
        #pragma unroll
        for (int nt = 0; nt < 8; nt++) {
            u32 bb[2];
            ldsm_x2(bb, bAddr + nt*2176 + k*32);
            mma_bf16(acc[nt], a, bb);
        }
    }
}
#define NB_SYNC(id, cnt)   asm volatile("bar.sync %0, %1;" :: "r"(id), "r"(cnt) : "memory")
#define NB_ARRIVE(id, cnt) asm volatile("bar.arrive %0, %1;" :: "r"(id), "r"(cnt) : "memory")

// =====================================================================
// k_pre, 12 blocks: 0-7 = weff rows bi*8..+7 (each recomputes LN+q0);
// 8-11 = Wp/Wf1/Wf2/Wv bf16 images.
// =====================================================================
__global__ void k_pre(const float* __restrict__ q, const float* __restrict__ g1,
                      const float* __restrict__ b1, const float* __restrict__ Wq,
                      const float* __restrict__ bq, const float* __restrict__ Wk,
                      const float* __restrict__ Wv, const float* __restrict__ Wp,
                      const float* __restrict__ Wf1, const float* __restrict__ Wf2)
{
    const int tid = threadIdx.x;
    const int bi  = blockIdx.x;
    if (bi < 8) {
        __shared__ float qn[8][DM];
        __shared__ float q0s[8][DM];
        const int w = tid >> 5, lane = tid & 31;
        {
            float4 v = *(const float4*)(q + w*DM + lane*4);
            float s  = v.x + v.y + v.z + v.w;
            float sq = v.x*v.x + v.y*v.y + v.z*v.z + v.w*v.w;
            #pragma unroll
            for (int o = 16; o > 0; o >>= 1) {
                s  += __shfl_xor_sync(0xffffffffu, s,  o);
                sq += __shfl_xor_sync(0xffffffffu, sq, o);
            }
            float m = s * (1.f/DM);
            float var = sq * (1.f/DM) - m*m;
            float rs = rsqrtf(var + 1e-5f);
            const int c = lane*4;
            qn[w][c+0] = (v.x - m)*rs*g1[c+0] + b1[c+0];
            qn[w][c+1] = (v.y - m)*rs*g1[c+1] + b1[c+1];
            qn[w][c+2] = (v.z - m)*rs*g1[c+2] + b1[c+2];
            qn[w][c+3] = (v.w - m)*rs*g1[c+3] + b1[c+3];
        }
        __syncthreads();
        for (int o = tid; o < 8*DM; o += 256) {
            int r = o >> 7, c = o & 127;
            float a = bq[c];
            const float4* wr = (const float4*)(Wq + c*DM);
            #pragma unroll 8
            for (int t4 = 0; t4 < 32; t4++) {
                float4 ww = wr[t4];
                a += qn[r][t4*4+0]*ww.x + qn[r][t4*4+1]*ww.y
                   + qn[r][t4*4+2]*ww.z + qn[r][t4*4+3]*ww.w;
            }
            q0s[r][c] = a;
        }
        __syncthreads();
        // weff rows bi*8 .. bi*8+7 -> bf16 image directly
        for (int o = tid; o < 8*64; o += 256) {
            int p  = bi*8 + (o >> 6);
            int tp = o & 63;
            int r = p >> 3, h = p & 7;
            float a0 = 0.f, a1 = 0.f;
            #pragma unroll
            for (int d = 0; d < 16; d++) {
                float qd = q0s[r][h*16 + d];
                a0 += qd * Wk[(h*16 + d)*DM + 2*tp];
                a1 += qd * Wk[(h*16 + d)*DM + 2*tp + 1];
            }
            g_weffHi[p*68 + tp] = cvt2(0.25f*a0, 0.25f*a1);
        }
    } else {
        const float* src; u32* dst;
        switch (bi) {
            case 8:  src = Wp;  dst = g_wpB;  break;
            case 9:  src = Wf1; dst = g_wf1B; break;
            case 10: src = Wf2; dst = g_wf2B; break;
            default: src = Wv;  dst = g_wvHi; break;
        }
        for (int o = tid; o < 128*64; o += 256) {
            int r = o >> 6, tp = o & 63;
            dst[r*68 + tp] = cvt2(src[r*DM + tp*2], src[r*DM + tp*2 + 1]);
        }
    }
}

// =====================================================================
// k_attn_ws: 4 batches/CTA, 512 threads, warp-specialized pipeline.
// Producer warps 8-15: MMA + epilogue -> double-buffered P/VP.
// Consumer warps 0-7: softmax + x_att -> g_xatt.
// =====================================================================
__global__ __launch_bounds__(512, 1)
void k_attn_ws(const float* __restrict__ tgt, const float* __restrict__ bv, int Bn)
{
    extern __shared__ float smf[];
    char* smc = (char*)smf;
    const u32 smb = smem_u32(smf);
    const int tid = threadIdx.x;
    const int wid = tid >> 5, lane = tid & 31;
    const int gb0 = blockIdx.x * 4;

    // -------- stage (all 512 threads): weights + 4 batches of tgt --------
    {
        const float4* we = (const float4*)g_weffHi;
        float4* dE = (float4*)(smc + WS_WEFF);
        #pragma unroll
        for (int kk = 0; kk < 3; kk++) {
            int i = tid + kk*512;
            if (i < 1088) dE[i] = we[i];
        }
        const float4* wh = (const float4*)g_wvHi;
        float4* dH = (float4*)(smc + WS_WV);
        #pragma unroll
        for (int kk = 0; kk < 5; kk++) {
            int i = tid + kk*512;
            if (i < 2176) dH[i] = wh[i];
        }
        const float4* src = (const float4*)(tgt + (size_t)gb0 * NTOK * DM);
        #pragma unroll
        for (int kk = 0; kk < 12; kk++) {
            int i = tid + kk*512;                 // 0..6143
            int b4 = i / 1536;
            int rem = i - b4*1536;
            int row = rem >> 5, c = (rem & 31) * 4;
            float4 v = make_float4(0.f, 0.f, 0.f, 0.f);
            if (gb0 + b4 < Bn) v = src[i];
            u32 off = (u32)(WS_TGT + b4*13056 + row*272 + c*2);
            *(u32*)(smc + off)     = cvt2(v.x, v.y);
            *(u32*)(smc + off + 4) = cvt2(v.z, v.w);
        }
    }
    __syncthreads();

    // barrier ids: full0=1, full1=2, empty0=3, empty1=4, consumer-internal=5
    #pragma unroll 1
    for (int b = 0; b < 4; b++) {
        const int kb = b & 1;
        const int pf  = PF(kb);
        const int vpf = VPF(kb);

        if (wid >= 8) {
            // ================= PRODUCER =================
            const int pw = wid - 8;
            if (pw < 6) {
                const int mt = pw >> 1;
                const int nh = pw & 1;
                float accV[8][4];
                const u32 aH = smb + WS_TGT + b*13056 + (mt*16 + (lane & 15))*272 + (lane >> 4)*16;
                const u32 bH = smb + WS_WV + nh*8*2176 + (lane & 7)*272 + ((lane >> 3) & 1)*16;
                gemm_mma(accV, aH, bH);
                if (b >= 2) NB_SYNC(3 + kb, 512);
                const int r0 = mt*16 + (lane >> 2);
                const int c0 = nh*64 + (lane & 3)*2;
                #pragma unroll
                for (int nt = 0; nt < 8; nt++) {
                    const int c = c0 + nt*8;
                    float bv0 = bv[c], bv1 = bv[c+1];
                    smf[vpf + r0*TS + c]       = accV[nt][0] + bv0;
                    smf[vpf + r0*TS + c + 1]   = accV[nt][1] + bv1;
                    smf[vpf + (r0+8)*TS + c]   = accV[nt][2] + bv0;
                    smf[vpf + (r0+8)*TS + c+1] = accV[nt][3] + bv1;
                }
            } else {
                const int wi = pw - 6;
                float accS[2][6][4];
                #pragma unroll
                for (int i = 0; i < 2; i++)
                    #pragma unroll
                    for (int n = 0; n < 6; n++)
                        #pragma unroll
                        for (int e = 0; e < 4; e++) accS[i][n][e] = 0.f;
                const u32 a0 = smb + WS_WEFF + (wi*32 + (lane & 15))*272 + (lane >> 4)*16;
                const u32 a1 = a0 + 16*272;
                const u32 bH = smb + WS_TGT + b*13056 + (lane & 7)*272 + ((lane >> 3) & 1)*16;
                #pragma unroll
                for (int k = 0; k < 8; k++) {
                    u32 aA[4], aB[4];
                    ldsm_x4(aA, a0 + k*32);
                    ldsm_x4(aB, a1 + k*32);
                    #pragma unroll
                    for (int nt = 0; nt < 6; nt++) {
                        u32 bh[2];
                        ldsm_x2(bh, bH + nt*2176 + k*32);
                        mma_bf16(accS[0][nt], aA, bh);
                        mma_bf16(accS[1][nt], aB, bh);
                    }
                }
                if (b >= 2) NB_SYNC(3 + kb, 512);
                #pragma unroll
                for (int i = 0; i < 2; i++) {
                    const int r0 = (wi*2 + i)*16 + (lane >> 2);
                    #pragma unroll
                    for (int nt = 0; nt < 6; nt++) {
                        const int c = nt*8 + (lane & 3)*2;
                        smf[pf + r0*SS + c]       = accS[i][nt][0];
                        smf[pf + r0*SS + c + 1]   = accS[i][nt][1];
                        smf[pf + (r0+8)*SS + c]   = accS[i][nt][2];
                        smf[pf + (r0+8)*SS + c+1] = accS[i][nt][3];
                    }
                }
            }
            NB_ARRIVE(1 + kb, 512);
        } else {
            // ================= CONSUMER =================
            NB_SYNC(1 + kb, 512);

            // softmax: 4 threads per full pair; window pairs by quarter leader
            {
                const int p = tid >> 2, qq = tid & 3;
                float* row = smf + pf + p*SS;
                if (p < 16) {
                    const int j0 = qq*12;
                    float e[12];
                    float mx = -1e30f;
                    #pragma unroll
                    for (int m = 0; m < 12; m++) { e[m] = row[j0+m]; mx = fmaxf(mx, e[m]); }
                    mx = fmaxf(mx, __shfl_xor_sync(0xffffffffu, mx, 1));
                    mx = fmaxf(mx, __shfl_xor_sync(0xffffffffu, mx, 2));
                    float sum = 0.f;
                    #pragma unroll
                    for (int m = 0; m < 12; m++) { e[m] = expf(e[m]-mx); sum += e[m]; }
                    sum += __shfl_xor_sync(0xffffffffu, sum, 1);
                    sum += __shfl_xor_sync(0xffffffffu, sum, 2);
                    float inv = 1.f / sum;
                    #pragma unroll
                    for (int m = 0; m < 12; m++) row[j0+m] = e[m]*inv;
                } else if (qq == 0) {
                    const int r = p >> 3;
                    const int wi = r - 2;
                    const int hw = (wi/3)*4, ww = (wi%3)*2;
                    float e[8];
                    float mx = -1e30f;
                    #pragma unroll
                    for (int m = 0; m < 8; m++) {
                        const int j = (hw + (m>>1))*6 + ww + (m&1);
                        e[m] = row[j];
                        mx = fmaxf(mx, e[m]);
                    }
                    float sum = 0.f;
                    #pragma unroll
                    for (int m = 0; m < 8; m++) { e[m] = expf(e[m]-mx); sum += e[m]; }
                    float inv = 1.f / sum;
                    #pragma unroll
                    for (int m = 0; m < 8; m++) {
                        const int j = (hw + (m>>1))*6 + ww + (m&1);
                        row[j] = e[m]*inv;
                    }
                }
            }
            NB_SYNC(5, 256);

            // x_att: warp = output row r
            {
                const int r   = wid;
                const int col = lane * 4;
                const int h   = lane >> 2;
                const float* Pb = smf + pf + (r*8 + h)*SS;
                ull a01 = 0ull, a23 = 0ull;
                if (r < 2) {
                    for (int j = 0; j < NTOK; j++) {
                        ull f = dup2(Pb[j]);
                        ulonglong2 u0 = *(const ulonglong2*)(smf + vpf + j*TS + col);
                        ffma2(a01, f, u0.x); ffma2(a23, f, u0.y);
                    }
                } else {
                    const int wi = r - 2;
                    const int hw = (wi/3)*4, ww = (wi%3)*2;
                    #pragma unroll
                    for (int m = 0; m < 8; m++) {
                        const int j = (hw + (m>>1))*6 + ww + (m&1);
                        ull f = dup2(Pb[j]);
                        ulonglong2 u0 = *(const ulonglong2*)(smf + vpf + j*TS + col);
                        ffma2(a01, f, u0.x); ffma2(a23, f, u0.y);
                    }
                }
                if (gb0 + b < Bn) {
                    float4 o;
                    unpack2(a01, o.x, o.y); unpack2(a23, o.z, o.w);
                    *(float4*)(g_xatt + ((size_t)(gb0 + b)*8 + r)*DM + col) = o;
                }
            }
            NB_ARRIVE(3 + kb, 512);
        }
    }
}

// =====================================================================
// k_ffn: GB=8 batches/CTA, 2 CTAs/SM. Three bf16 mma.sync GEMMs.
// (unchanged from R14 — passing)
// =====================================================================
__global__ __launch_bounds__(256, 2)
void k_ffn(const float* __restrict__ query, const float* __restrict__ bp,
           const float* __restrict__ g2, const float* __restrict__ b2,
           const float* __restrict__ bf1, const float* __restrict__ bf2,
           float* __restrict__ out, int Bn)
{
    extern __shared__ float smf[];
    char* smc = (char*)smf;
    const u32 smb = smem_u32(smf);
    const int tid  = threadIdx.x;
    const int wid  = tid >> 5;
    const int lane = tid & 31;
    const int b0   = blockIdx.x * GB;
    const int rows_valid = (Bn - b0 >= GB) ? BROWS : (Bn - b0) * 8;

    const int mt = wid >> 1, nh = wid & 1;
    const u32 aAddr = smb + FB_A + (mt*16 + (lane & 15))*272 + (lane >> 4)*16;
    const u32 bAddr = smb + FB_B + nh*8*2176 + (lane & 7)*272 + ((lane >> 3) & 1)*16;
    const int r0 = mt*16 + (lane >> 2);
    const int c0 = nh*64 + (lane & 3)*2;

    {
        const float4* src = (const float4*)(g_xatt + (size_t)b0 * 8 * DM);
        #pragma unroll
        for (int k = 0; k < 8; k++) {
            int i = tid + k*256;
            int r = i >> 5, c = (i & 31) * 4;
            float4 v = (r < rows_valid) ? src[i] : make_float4(0.f,0.f,0.f,0.f);
            u32 off = r*272 + c*2;
            *(u32*)(smc + FB_A + off)     = cvt2(v.x, v.y);
            *(u32*)(smc + FB_A + off + 4) = cvt2(v.z, v.w);
        }
        const float4* wb = (const float4*)g_wpB;
        float4* dB = (float4*)(smc + FB_B);
        #pragma unroll
        for (int k = 0; k < 9; k++) {
            int i = tid + k*256;
            if (i < 2176) dB[i] = wb[i];
        }
        ((float4*)(smc + FB_Q))[tid] = ((const float4*)query)[tid];
        if (tid < 128) {
            smf[C_F +       tid] = bp [tid];
            smf[C_F + 128 + tid] = g2 [tid];
            smf[C_F + 256 + tid] = b2 [tid];
            smf[C_F + 384 + tid] = bf1[tid];
            smf[C_F + 512 + tid] = bf2[tid];
        }
    }
    __syncthreads();

    {
        float acc[8][4];
        gemm_mma(acc, aAddr, bAddr);
        #pragma unroll
        for (int nt = 0; nt < 8; nt++) {
            const int c = c0 + nt*8;
            float q0a = smf[Q_F + (r0 & 7)*DM + c];
            float q1a = smf[Q_F + (r0 & 7)*DM + c + 1];
            float q0b = smf[Q_F + ((r0+8) & 7)*DM + c];
            float q1b = smf[Q_F + ((r0+8) & 7)*DM + c + 1];
            float bp0 = smf[C_F + c], bp1 = smf[C_F + c + 1];
            smf[X_F + r0*TS + c]       = q0a + bp0 + acc[nt][0];
            smf[X_F + r0*TS + c + 1]   = q1a + bp1 + acc[nt][1];
            smf[X_F + (r0+8)*TS + c]   = q0b + bp0 + acc[nt][2];
            smf[X_F + (r0+8)*TS + c+1] = q1b + bp1 + acc[nt][3];
        }
    }
    __syncthreads();

    {
        #pragma unroll
        for (int r = 0; r < 8; r++) {
            const int row = wid*8 + r;
            const float* xr = smf + X_F + row*TS + lane*4;
            float v0 = xr[0], v1 = xr[1], v2 = xr[2], v3 = xr[3];
            float sum = v0+v1+v2+v3;
            float sq  = v0*v0+v1*v1+v2*v2+v3*v3;
            #pragma unroll
            for (int o = 16; o > 0; o >>= 1) {
                sum += __shfl_xor_sync(0xffffffffu, sum, o);
                sq  += __shfl_xor_sync(0xffffffffu, sq,  o);
            }
            float m   = sum * (1.f/DM);
            float var = sq * (1.f/DM) - m*m;
            float rs  = rsqrtf(var + 1e-5f);
            const int c = lane*4;
            float n0 = (v0 - m)*rs*smf[C_F + 128 + c  ] + smf[C_F + 256 + c  ];
            float n1 = (v1 - m)*rs*smf[C_F + 128 + c+1] + smf[C_F + 256 + c+1];
            float n2 = (v2 - m)*rs*smf[C_F + 128 + c+2] + smf[C_F + 256 + c+2];
            float n3 = (v3 - m)*rs*smf[C_F + 128 + c+3] + smf[C_F + 256 + c+3];
            u32 off = row*272 + c*2;
            *(u32*)(smc + FB_A + off)     = cvt2(n0, n1);
            *(u32*)(smc + FB_A + off + 4) = cvt2(n2, n3);
        }
        const float4* wb = (const float4*)g_wf1B;
        float4* dB = (float4*)(smc + FB_B);
        #pragma unroll
        for (int k = 0; k < 9; k++) {
            int i = tid + k*256;
            if (i < 2176) dB[i] = wb[i];
        }
    }
    __syncthreads();

    {
        float acc[8][4];
        gemm_mma(acc, aAddr, bAddr);
        __syncthreads();
        #pragma unroll
        for (int nt = 0; nt < 8; nt++) {
            const int c = c0 + nt*8;
            float bf1a = smf[C_F + 384 + c], bf1b = smf[C_F + 384 + c + 1];
            float z0 = acc[nt][0] + bf1a;
            float z1 = acc[nt][1] + bf1b;
            float z2 = acc[nt][2] + bf1a;
            float z3 = acc[nt][3] + bf1b;
            float h0 = 0.5f * z0 * (1.f + erff(z0 * 0.7071067811865476f));
            float h1 = 0.5f * z1 * (1.f + erff(z1 * 0.7071067811865476f));
            float h2 = 0.5f * z2 * (1.f + erff(z2 * 0.7071067811865476f));
            float h3 = 0.5f * z3 * (1.f + erff(z3 * 0.7071067811865476f));
            *(u32*)(smc + FB_A + r0*272 + c*2)     = cvt2(h0, h1);
            *(u32*)(smc + FB_A + (r0+8)*272 + c*2) = cvt2(h2, h3);
        }
        const float4* wb = (const float4*)g_wf2B;
        float4* dB = (float4*)(smc + FB_B);
        #pragma unroll
        for (int k = 0; k < 9; k++) {
            int i = tid + k*256;
            if (i < 2176) dB[i] = wb[i];
        }
    }
    __syncthreads();

    {
        float acc[8][4];
        gemm_mma(acc, aAddr, bAddr);
        #pragma unroll
        for (int nt = 0; nt < 8; nt++) {
            const int c = c0 + nt*8;
            float bf2a = smf[C_F + 512 + c], bf2b = smf[C_F + 512 + c + 1];
            if (r0 < rows_valid) {
                float2 res;
                res.x = smf[X_F + r0*TS + c]     + bf2a + acc[nt][0];
                res.y = smf[X_F + r0*TS + c + 1] + bf2b + acc[nt][1];
                *(float2*)(out + ((size_t)b0*8 + r0)*DM + c) = res;
            }
            if (r0 + 8 < rows_valid) {
                float2 res;
                res.x = smf[X_F + (r0+8)*TS + c]     + bf2a + acc[nt][2];
                res.y = smf[X_F + (r0+8)*TS + c + 1] + bf2b + acc[nt][3];
                *(float2*)(out + ((size_t)b0*8 + r0 + 8)*DM + c) = res;
            }
        }
    }
}

// =====================================================================
extern "C" void kernel_launch(void* const* d_in, const int* in_sizes, int n_in,
                              void* d_out, int out_size)
{
    const float* query = (const float*)d_in[0];
    const float* tgt   = (const float*)d_in[1];
    const float* g1    = (const float*)d_in[2];
    const float* b1    = (const float*)d_in[3];
    const float* Wq    = (const float*)d_in[4];
    const float* bq    = (const float*)d_in[5];
    const float* Wk    = (const float*)d_in[6];
    // d_in[7] = bk: drops out (softmax shift invariance)
    const float* Wv    = (const float*)d_in[8];
    const float* bv    = (const float*)d_in[9];
    const float* Wp    = (const float*)d_in[10];
    const float* bp    = (const float*)d_in[11];
    const float* g2    = (const float*)d_in[12];
    const float* b2    = (const float*)d_in[13];
    const float* Wf1   = (const float*)d_in[14];
    const float* bf1   = (const float*)d_in[15];
    const float* Wf2   = (const float*)d_in[16];
    const float* bf2   = (const float*)d_in[17];

    const int B = in_sizes[1] / (NTOK * DM);

    cudaFuncSetAttribute(k_attn_ws, cudaFuncAttributeMaxDynamicSharedMemorySize, WS_SMEM);
    cudaFuncSetAttribute(k_ffn,     cudaFuncAttributeMaxDynamicSharedMemorySize, FB_SMEM);

    k_pre<<<12, 256>>>(query, g1, b1, Wq, bq, Wk, Wv, Wp, Wf1, Wf2);
    k_attn_ws<<<(B + 3)/4, 512, WS_SMEM>>>(tgt, bv, B);
    k_ffn<<<(B + GB - 1)/GB, 256, FB_SMEM>>>(query, bp, g2, b2, bf1, bf2,
                                             (float*)d_out, B);
}

// round 16
// speedup vs baseline: 5.4246x; 1.0553x over previous
#include <cuda_runtime.h>
#include <cuda_bf16.h>

typedef unsigned long long ull;
typedef unsigned int u32;

#define DM   128
#define NTOK 48
#define TS   132
#define SS   49
#define MAXB 16384
#define GBA  6                            // batches per group (attn)

// ---- k_attn_ws smem byte offsets (bf16 rows padded to 272B) ----
#define WS_WEFF 0                         // weff bf16 64x272  = 17408
#define WS_WV   17408                     // Wv  bf16 128x272  = 34816
#define WS_TGT  52224                     // tgt bf16 6x48x272 = 78336
#define WS_P    130560                    // P fp32 2 x 64x49x4  = 25088
#define WS_VP   155648                    // VP fp32 2 x 48x132x4 = 50688
#define WS_SMEM 206336
#define PF(kb)  (32640 + (kb)*3136)       // float index
#define VPF(kb) (38912 + (kb)*6336)

// ---- k_ffn smem byte offsets ----
#define GB 8
#define BROWS 64
#define FB_A   0
#define FB_B   17408
#define FB_X   52224
#define FB_Q   86016
#define FB_C   90112
#define FB_SMEM 92672
#define X_F    13056
#define Q_F    21504
#define C_F    22528

// ---------------- globals ----------------
__device__ __align__(16) u32 g_wvHi [128 * 68];
__device__ __align__(16) u32 g_weffHi[64 * 68];
__device__ __align__(16) u32 g_wpB  [128 * 68];
__device__ __align__(16) u32 g_wf1B [128 * 68];
__device__ __align__(16) u32 g_wf2B [128 * 68];
__device__ __align__(16) float g_xatt[(size_t)MAXB * 8 * DM];

// ---------------- helpers ----------------
__device__ __forceinline__ void ffma2(ull& d, ull a, ull b) {
    asm("fma.rn.f32x2 %0, %1, %2, %0;" : "+l"(d) : "l"(a), "l"(b));
}
__device__ __forceinline__ ull dup2(float x) {
    ull r; asm("mov.b64 %0, {%1, %1};" : "=l"(r) : "f"(x)); return r;
}
__device__ __forceinline__ void unpack2(ull v, float& lo, float& hi) {
    asm("mov.b64 {%0, %1}, %2;" : "=f"(lo), "=f"(hi) : "l"(v));
}
__device__ __forceinline__ u32 smem_u32(const void* p) {
    u32 a; asm("{ .reg .u64 t; cvta.to.shared.u64 t, %1; cvt.u32.u64 %0, t; }" : "=r"(a) : "l"(p));
    return a;
}
__device__ __forceinline__ u32 cvt2(float lo, float hi) {
    u32 r; asm("cvt.rn.bf16x2.f32 %0, %1, %2;" : "=r"(r) : "f"(hi), "f"(lo)); return r;
}
__device__ __forceinline__ void ldsm_x4(u32* r, u32 addr) {
    asm volatile("ldmatrix.sync.aligned.m8n8.x4.shared.b16 {%0,%1,%2,%3}, [%4];"
        : "=r"(r[0]), "=r"(r[1]), "=r"(r[2]), "=r"(r[3]) : "r"(addr));
}
__device__ __forceinline__ void ldsm_x2(u32* r, u32 addr) {
    asm volatile("ldmatrix.sync.aligned.m8n8.x2.shared.b16 {%0,%1}, [%2];"
        : "=r"(r[0]), "=r"(r[1]) : "r"(addr));
}
__device__ __forceinline__ void mma_bf16(float* d, const u32* a, const u32* b) {
    asm volatile("mma.sync.aligned.m16n8k16.row.col.f32.bf16.bf16.f32 "
        "{%0,%1,%2,%3}, {%4,%5,%6,%7}, {%8,%9}, {%0,%1,%2,%3};"
        : "+f"(d[0]), "+f"(d[1]), "+f"(d[2]), "+f"(d[3])
        : "r"(a[0]), "r"(a[1]), "r"(a[2]), "r"(a[3]), "r"(b[0]), "r"(b[1]));
}
__device__ __forceinline__ void gemm_mma(float acc[8][4], u32 aAddr, u32 bAddr) {
    #pragma unroll
    for (int n = 0; n < 8; n++)
        #pragma unroll
        for (int e = 0; e < 4; e++) acc[n][e] = 0.f;
    #pragma unroll
    for (int k = 0; k < 8; k++) {
        u32 a[4];
        ldsm_x4(a, aAddr + k*32);
        #pragma unroll
        for (int nt = 0; nt < 8; nt++) {
            u32 bb[2];
            ldsm_x2(bb, bAddr + nt*2176 + k*32);
            mma_bf16(acc[nt], a, bb);
        }
    }
}
#define NB_SYNC(id, cnt)   asm volatile("bar.sync %0, %1;" :: "r"(id), "r"(cnt) : "memory")
#define NB_ARRIVE(id, cnt) asm volatile("bar.arrive %0, %1;" :: "r"(id), "r"(cnt) : "memory")

// =====================================================================
// k_pre, 12 blocks (unchanged from R15)
// =====================================================================
__global__ void k_pre(const float* __restrict__ q, const float* __restrict__ g1,
                      const float* __restrict__ b1, const float* __restrict__ Wq,
                      const float* __restrict__ bq, const float* __restrict__ Wk,
                      const float* __restrict__ Wv, const float* __restrict__ Wp,
                      const float* __restrict__ Wf1, const float* __restrict__ Wf2)
{
    const int tid = threadIdx.x;
    const int bi  = blockIdx.x;
    if (bi < 8) {
        __shared__ float qn[8][DM];
        __shared__ float q0s[8][DM];
        const int w = tid >> 5, lane = tid & 31;
        {
            float4 v = *(const float4*)(q + w*DM + lane*4);
            float s  = v.x + v.y + v.z + v.w;
            float sq = v.x*v.x + v.y*v.y + v.z*v.z + v.w*v.w;
            #pragma unroll
            for (int o = 16; o > 0; o >>= 1) {
                s  += __shfl_xor_sync(0xffffffffu, s,  o);
                sq += __shfl_xor_sync(0xffffffffu, sq, o);
            }
            float m = s * (1.f/DM);
            float var = sq * (1.f/DM) - m*m;
            float rs = rsqrtf(var + 1e-5f);
            const int c = lane*4;
            qn[w][c+0] = (v.x - m)*rs*g1[c+0] + b1[c+0];
            qn[w][c+1] = (v.y - m)*rs*g1[c+1] + b1[c+1];
            qn[w][c+2] = (v.z - m)*rs*g1[c+2] + b1[c+2];
            qn[w][c+3] = (v.w - m)*rs*g1[c+3] + b1[c+3];
        }
        __syncthreads();
        for (int o = tid; o < 8*DM; o += 256) {
            int r = o >> 7, c = o & 127;
            float a = bq[c];
            const float4* wr = (const float4*)(Wq + c*DM);
            #pragma unroll 8
            for (int t4 = 0; t4 < 32; t4++) {
                float4 ww = wr[t4];
                a += qn[r][t4*4+0]*ww.x + qn[r][t4*4+1]*ww.y
                   + qn[r][t4*4+2]*ww.z + qn[r][t4*4+3]*ww.w;
            }
            q0s[r][c] = a;
        }
        __syncthreads();
        for (int o = tid; o < 8*64; o += 256) {
            int p  = bi*8 + (o >> 6);
            int tp = o & 63;
            int r = p >> 3, h = p & 7;
            float a0 = 0.f, a1 = 0.f;
            #pragma unroll
            for (int d = 0; d < 16; d++) {
                float qd = q0s[r][h*16 + d];
                a0 += qd * Wk[(h*16 + d)*DM + 2*tp];
                a1 += qd * Wk[(h*16 + d)*DM + 2*tp + 1];
            }
            g_weffHi[p*68 + tp] = cvt2(0.25f*a0, 0.25f*a1);
        }
    } else {
        const float* src; u32* dst;
        switch (bi) {
            case 8:  src = Wp;  dst = g_wpB;  break;
            case 9:  src = Wf1; dst = g_wf1B; break;
            case 10: src = Wf2; dst = g_wf2B; break;
            default: src = Wv;  dst = g_wvHi; break;
        }
        for (int o = tid; o < 128*64; o += 256) {
            int r = o >> 6, tp = o & 63;
            dst[r*68 + tp] = cvt2(src[r*DM + tp*2], src[r*DM + tp*2 + 1]);
        }
    }
}

// =====================================================================
// k_attn_ws: persistent, 6 batches/group, warp-specialized pipeline.
// Weights staged ONCE per CTA. Producer warps 8-15: MMA -> double-
// buffered P/VP. Consumer warps 0-7: softmax + x_att.
// =====================================================================
__global__ __launch_bounds__(512, 1)
void k_attn_ws(const float* __restrict__ tgt, const float* __restrict__ bv, int Bn)
{
    extern __shared__ float smf[];
    char* smc = (char*)smf;
    const u32 smb = smem_u32(smf);
    const int tid = threadIdx.x;
    const int wid = tid >> 5, lane = tid & 31;
    const int ngroups = (Bn + GBA - 1) / GBA;

    // -------- stage weights once --------
    {
        const float4* we = (const float4*)g_weffHi;
        float4* dE = (float4*)(smc + WS_WEFF);
        #pragma unroll
        for (int kk = 0; kk < 3; kk++) {
            int i = tid + kk*512;
            if (i < 1088) dE[i] = we[i];
        }
        const float4* wh = (const float4*)g_wvHi;
        float4* dH = (float4*)(smc + WS_WV);
        #pragma unroll
        for (int kk = 0; kk < 5; kk++) {
            int i = tid + kk*512;
            if (i < 2176) dH[i] = wh[i];
        }
    }

    int it = 0;   // global pipeline iteration counter (barrier parity)
    for (int g = blockIdx.x; g < ngroups; g += gridDim.x) {
        const int gb0 = g * GBA;

        // -------- stage tgt for this group (all 512) --------
        __syncthreads();       // prior group fully consumed before overwrite
        {
            const float4* src = (const float4*)(tgt + (size_t)gb0 * NTOK * DM);
            #pragma unroll
            for (int kk = 0; kk < 18; kk++) {
                int i = tid + kk*512;                 // 0..9215
                int b4 = i / 1536;
                int rem = i - b4*1536;
                int row = rem >> 5, c = (rem & 31) * 4;
                float4 v = make_float4(0.f, 0.f, 0.f, 0.f);
                if (gb0 + b4 < Bn) v = src[i];
                u32 off = (u32)(WS_TGT + b4*13056 + row*272 + c*2);
                *(u32*)(smc + off)     = cvt2(v.x, v.y);
                *(u32*)(smc + off + 4) = cvt2(v.z, v.w);
            }
        }
        __syncthreads();

        #pragma unroll 1
        for (int b = 0; b < GBA; b++, it++) {
            const int kb = it & 1;
            const int pf  = PF(kb);
            const int vpf = VPF(kb);

            if (wid >= 8) {
                // ================= PRODUCER =================
                const int pw = wid - 8;
                if (pw < 6) {
                    const int mt = pw >> 1;
                    const int nh = pw & 1;
                    float accV[8][4];
                    const u32 aH = smb + WS_TGT + b*13056 + (mt*16 + (lane & 15))*272 + (lane >> 4)*16;
                    const u32 bH = smb + WS_WV + nh*8*2176 + (lane & 7)*272 + ((lane >> 3) & 1)*16;
                    gemm_mma(accV, aH, bH);
                    if (it >= 2) NB_SYNC(3 + kb, 512);
                    const int r0 = mt*16 + (lane >> 2);
                    const int c0 = nh*64 + (lane & 3)*2;
                    #pragma unroll
                    for (int nt = 0; nt < 8; nt++) {
                        const int c = c0 + nt*8;
                        float bv0 = bv[c], bv1 = bv[c+1];
                        smf[vpf + r0*TS + c]       = accV[nt][0] + bv0;
                        smf[vpf + r0*TS + c + 1]   = accV[nt][1] + bv1;
                        smf[vpf + (r0+8)*TS + c]   = accV[nt][2] + bv0;
                        smf[vpf + (r0+8)*TS + c+1] = accV[nt][3] + bv1;
                    }
                } else {
                    const int wi = pw - 6;
                    float accS[2][6][4];
                    #pragma unroll
                    for (int i = 0; i < 2; i++)
                        #pragma unroll
                        for (int n = 0; n < 6; n++)
                            #pragma unroll
                            for (int e = 0; e < 4; e++) accS[i][n][e] = 0.f;
                    const u32 a0 = smb + WS_WEFF + (wi*32 + (lane & 15))*272 + (lane >> 4)*16;
                    const u32 a1 = a0 + 16*272;
                    const u32 bH = smb + WS_TGT + b*13056 + (lane & 7)*272 + ((lane >> 3) & 1)*16;
                    #pragma unroll
                    for (int k = 0; k < 8; k++) {
                        u32 aA[4], aB[4];
                        ldsm_x4(aA, a0 + k*32);
                        ldsm_x4(aB, a1 + k*32);
                        #pragma unroll
                        for (int nt = 0; nt < 6; nt++) {
                            u32 bh[2];
                            ldsm_x2(bh, bH + nt*2176 + k*32);
                            mma_bf16(accS[0][nt], aA, bh);
                            mma_bf16(accS[1][nt], aB, bh);
                        }
                    }
                    if (it >= 2) NB_SYNC(3 + kb, 512);
                    #pragma unroll
                    for (int i = 0; i < 2; i++) {
                        const int r0 = (wi*2 + i)*16 + (lane >> 2);
                        #pragma unroll
                        for (int nt = 0; nt < 6; nt++) {
                            const int c = nt*8 + (lane & 3)*2;
                            smf[pf + r0*SS + c]       = accS[i][nt][0];
                            smf[pf + r0*SS + c + 1]   = accS[i][nt][1];
                            smf[pf + (r0+8)*SS + c]   = accS[i][nt][2];
                            smf[pf + (r0+8)*SS + c+1] = accS[i][nt][3];
                        }
                    }
                }
                NB_ARRIVE(1 + kb, 512);
            } else {
                // ================= CONSUMER =================
                NB_SYNC(1 + kb, 512);

                // softmax: 4 threads per full pair; window pairs by quarter leader
                {
                    const int p = tid >> 2, qq = tid & 3;
                    float* row = smf + pf + p*SS;
                    if (p < 16) {
                        const int j0 = qq*12;
                        float e[12];
                        float mx = -1e30f;
                        #pragma unroll
                        for (int m = 0; m < 12; m++) { e[m] = row[j0+m]; mx = fmaxf(mx, e[m]); }
                        mx = fmaxf(mx, __shfl_xor_sync(0xffffffffu, mx, 1));
                        mx = fmaxf(mx, __shfl_xor_sync(0xffffffffu, mx, 2));
                        float sum = 0.f;
                        #pragma unroll
                        for (int m = 0; m < 12; m++) { e[m] = __expf(e[m]-mx); sum += e[m]; }
                        sum += __shfl_xor_sync(0xffffffffu, sum, 1);
                        sum += __shfl_xor_sync(0xffffffffu, sum, 2);
                        float inv = 1.f / sum;
                        #pragma unroll
                        for (int m = 0; m < 12; m++) row[j0+m] = e[m]*inv;
                    } else if (qq == 0) {
                        const int r = p >> 3;
                        const int wi = r - 2;
                        const int hw = (wi/3)*4, ww = (wi%3)*2;
                        float e[8];
                        float mx = -1e30f;
                        #pragma unroll
                        for (int m = 0; m < 8; m++) {
                            const int j = (hw + (m>>1))*6 + ww + (m&1);
                            e[m] = row[j];
                            mx = fmaxf(mx, e[m]);
                        }
                        float sum = 0.f;
                        #pragma unroll
                        for (int m = 0; m < 8; m++) { e[m] = __expf(e[m]-mx); sum += e[m]; }
                        float inv = 1.f / sum;
                        #pragma unroll
                        for (int m = 0; m < 8; m++) {
                            const int j = (hw + (m>>1))*6 + ww + (m&1);
                            row[j] = e[m]*inv;
                        }
                    }
                }
                NB_SYNC(5, 256);

                // x_att: warp = output row r; split accumulator chains
                {
                    const int r   = wid;
                    const int col = lane * 4;
                    const int h   = lane >> 2;
                    const float* Pb = smf + pf + (r*8 + h)*SS;
                    ull a01a = 0ull, a23a = 0ull, a01b = 0ull, a23b = 0ull;
                    if (r < 2) {
                        for (int j = 0; j < NTOK; j += 2) {
                            ull f0 = dup2(Pb[j]);
                            ull f1 = dup2(Pb[j+1]);
                            ulonglong2 u0 = *(const ulonglong2*)(smf + vpf + j*TS + col);
                            ulonglong2 u1 = *(const ulonglong2*)(smf + vpf + (j+1)*TS + col);
                            ffma2(a01a, f0, u0.x); ffma2(a23a, f0, u0.y);
                            ffma2(a01b, f1, u1.x); ffma2(a23b, f1, u1.y);
                        }
                    } else {
                        const int wi = r - 2;
                        const int hw = (wi/3)*4, ww = (wi%3)*2;
                        #pragma unroll
                        for (int m = 0; m < 8; m += 2) {
                            const int j0 = (hw + (m>>1))*6 + ww + (m&1);
                            const int j1 = (hw + ((m+1)>>1))*6 + ww + ((m+1)&1);
                            ull f0 = dup2(Pb[j0]);
                            ull f1 = dup2(Pb[j1]);
                            ulonglong2 u0 = *(const ulonglong2*)(smf + vpf + j0*TS + col);
                            ulonglong2 u1 = *(const ulonglong2*)(smf + vpf + j1*TS + col);
                            ffma2(a01a, f0, u0.x); ffma2(a23a, f0, u0.y);
                            ffma2(a01b, f1, u1.x); ffma2(a23b, f1, u1.y);
                        }
                    }
                    if (gb0 + b < Bn) {
                        float l0a, h0a, l1a, h1a, l0b, h0b, l1b, h1b;
                        unpack2(a01a, l0a, h0a); unpack2(a23a, l1a, h1a);
                        unpack2(a01b, l0b, h0b); unpack2(a23b, l1b, h1b);
                        float4 o;
                        o.x = l0a + l0b; o.y = h0a + h0b;
                        o.z = l1a + l1b; o.w = h1a + h1b;
                        *(float4*)(g_xatt + ((size_t)(gb0 + b)*8 + r)*DM + col) = o;
                    }
                }
                NB_ARRIVE(3 + kb, 512);
            }
        }
    }
}

// =====================================================================
// k_ffn: GB=8 batches/CTA, 2 CTAs/SM. Three bf16 mma.sync GEMMs.
// (unchanged from R14/R15 — passing)
// =====================================================================
__global__ __launch_bounds__(256, 2)
void k_ffn(const float* __restrict__ query, const float* __restrict__ bp,
           const float* __restrict__ g2, const float* __restrict__ b2,
           const float* __restrict__ bf1, const float* __restrict__ bf2,
           float* __restrict__ out, int Bn)
{
    extern __shared__ float smf[];
    char* smc = (char*)smf;
    const u32 smb = smem_u32(smf);
    const int tid  = threadIdx.x;
    const int wid  = tid >> 5;
    const int lane = tid & 31;
    const int b0   = blockIdx.x * GB;
    const int rows_valid = (Bn - b0 >= GB) ? BROWS : (Bn - b0) * 8;

    const int mt = wid >> 1, nh = wid & 1;
    const u32 aAddr = smb + FB_A + (mt*16 + (lane & 15))*272 + (lane >> 4)*16;
    const u32 bAddr = smb + FB_B + nh*8*2176 + (lane & 7)*272 + ((lane >> 3) & 1)*16;
    const int r0 = mt*16 + (lane >> 2);
    const int c0 = nh*64 + (lane & 3)*2;

    {
        const float4* src = (const float4*)(g_xatt + (size_t)b0 * 8 * DM);
        #pragma unroll
        for (int k = 0; k < 8; k++) {
            int i = tid + k*256;
            int r = i >> 5, c = (i & 31) * 4;
            float4 v = (r < rows_valid) ? src[i] : make_float4(0.f,0.f,0.f,0.f);
            u32 off = r*272 + c*2;
            *(u32*)(smc + FB_A + off)     = cvt2(v.x, v.y);
            *(u32*)(smc + FB_A + off + 4) = cvt2(v.z, v.w);
        }
        const float4* wb = (const float4*)g_wpB;
        float4* dB = (float4*)(smc + FB_B);
        #pragma unroll
        for (int k = 0; k < 9; k++) {
            int i = tid + k*256;
            if (i < 2176) dB[i] = wb[i];
        }
        ((float4*)(smc + FB_Q))[tid] = ((const float4*)query)[tid];
        if (tid < 128) {
            smf[C_F +       tid] = bp [tid];
            smf[C_F + 128 + tid] = g2 [tid];
            smf[C_F + 256 + tid] = b2 [tid];
            smf[C_F + 384 + tid] = bf1[tid];
            smf[C_F + 512 + tid] = bf2[tid];
        }
    }
    __syncthreads();

    {
        float acc[8][4];
        gemm_mma(acc, aAddr, bAddr);
        #pragma unroll
        for (int nt = 0; nt < 8; nt++) {
            const int c = c0 + nt*8;
            float q0a = smf[Q_F + (r0 & 7)*DM + c];
            float q1a = smf[Q_F + (r0 & 7)*DM + c + 1];
            float q0b = smf[Q_F + ((r0+8) & 7)*DM + c];
            float q1b = smf[Q_F + ((r0+8) & 7)*DM + c + 1];
            float bp0 = smf[C_F + c], bp1 = smf[C_F + c + 1];
            smf[X_F + r0*TS + c]       = q0a + bp0 + acc[nt][0];
            smf[X_F + r0*TS + c + 1]   = q1a + bp1 + acc[nt][1];
            smf[X_F + (r0+8)*TS + c]   = q0b + bp0 + acc[nt][2];
            smf[X_F + (r0+8)*TS + c+1] = q1b + bp1 + acc[nt][3];
        }
    }
    __syncthreads();

    {
        #pragma unroll
        for (int r = 0; r < 8; r++) {
            const int row = wid*8 + r;
            const float* xr = smf + X_F + row*TS + lane*4;
            float v0 = xr[0], v1 = xr[1], v2 = xr[2], v3 = xr[3];
            float sum = v0+v1+v2+v3;
            float sq  = v0*v0+v1*v1+v2*v2+v3*v3;
            #pragma unroll
            for (int o = 16; o > 0; o >>= 1) {
                sum += __shfl_xor_sync(0xffffffffu, sum, o);
                sq  += __shfl_xor_sync(0xffffffffu, sq,  o);
            }
            float m   = sum * (1.f/DM);
            float var = sq * (1.f/DM) - m*m;
            float rs  = rsqrtf(var + 1e-5f);
            const int c = lane*4;
            float n0 = (v0 - m)*rs*smf[C_F + 128 + c  ] + smf[C_F + 256 + c  ];
            float n1 = (v1 - m)*rs*smf[C_F + 128 + c+1] + smf[C_F + 256 + c+1];
            float n2 = (v2 - m)*rs*smf[C_F + 128 + c+2] + smf[C_F + 256 + c+2];
            float n3 = (v3 - m)*rs*smf[C_F + 128 + c+3] + smf[C_F + 256 + c+3];
            u32 off = row*272 + c*2;
            *(u32*)(smc + FB_A + off)     = cvt2(n0, n1);
            *(u32*)(smc + FB_A + off + 4) = cvt2(n2, n3);
        }
        const float4* wb = (const float4*)g_wf1B;
        float4* dB = (float4*)(smc + FB_B);
        #pragma unroll
        for (int k = 0; k < 9; k++) {
            int i = tid + k*256;
            if (i < 2176) dB[i] = wb[i];
        }
    }
    __syncthreads();

    {
        float acc[8][4];
        gemm_mma(acc, aAddr, bAddr);
        __syncthreads();
        #pragma unroll
        for (int nt = 0; nt < 8; nt++) {
            const int c = c0 + nt*8;
            float bf1a = smf[C_F + 384 + c], bf1b = smf[C_F + 384 + c + 1];
            float z0 = acc[nt][0] + bf1a;
            float z1 = acc[nt][1] + bf1b;
            float z2 = acc[nt][2] + bf1a;
            float z3 = acc[nt][3] + bf1b;
            float h0 = 0.5f * z0 * (1.f + erff(z0 * 0.7071067811865476f));
            float h1 = 0.5f * z1 * (1.f + erff(z1 * 0.7071067811865476f));
            float h2 = 0.5f * z2 * (1.f + erff(z2 * 0.7071067811865476f));
            float h3 = 0.5f * z3 * (1.f + erff(z3 * 0.7071067811865476f));
            *(u32*)(smc + FB_A + r0*272 + c*2)     = cvt2(h0, h1);
            *(u32*)(smc + FB_A + (r0+8)*272 + c*2) = cvt2(h2, h3);
        }
        const float4* wb = (const float4*)g_wf2B;
        float4* dB = (float4*)(smc + FB_B);
        #pragma unroll
        for (int k = 0; k < 9; k++) {
            int i = tid + k*256;
            if (i < 2176) dB[i] = wb[i];
        }
    }
    __syncthreads();

    {
        float acc[8][4];
        gemm_mma(acc, aAddr, bAddr);
        #pragma unroll
        for (int nt = 0; nt < 8; nt++) {
            const int c = c0 + nt*8;
            float bf2a = smf[C_F + 512 + c], bf2b = smf[C_F + 512 + c + 1];
            if (r0 < rows_valid) {
                float2 res;
                res.x = smf[X_F + r0*TS + c]     + bf2a + acc[nt][0];
                res.y = smf[X_F + r0*TS + c + 1] + bf2b + acc[nt][1];
                *(float2*)(out + ((size_t)b0*8 + r0)*DM + c) = res;
            }
            if (r0 + 8 < rows_valid) {
                float2 res;
                res.x = smf[X_F + (r0+8)*TS + c]     + bf2a + acc[nt][2];
                res.y = smf[X_F + (r0+8)*TS + c + 1] + bf2b + acc[nt][3];
                *(float2*)(out + ((size_t)b0*8 + r0 + 8)*DM + c) = res;
            }
        }
    }
}

// =====================================================================
extern "C" void kernel_launch(void* const* d_in, const int* in_sizes, int n_in,
                              void* d_out, int out_size)
{
    const float* query = (const float*)d_in[0];
    const float* tgt   = (const float*)d_in[1];
    const float* g1    = (const float*)d_in[2];
    const float* b1    = (const float*)d_in[3];
    const float* Wq    = (const float*)d_in[4];
    const float* bq    = (const float*)d_in[5];
    const float* Wk    = (const float*)d_in[6];
    // d_in[7] = bk: drops out (softmax shift invariance)
    const float* Wv    = (const float*)d_in[8];
    const float* bv    = (const float*)d_in[9];
    const float* Wp    = (const float*)d_in[10];
    const float* bp    = (const float*)d_in[11];
    const float* g2    = (const float*)d_in[12];
    const float* b2    = (const float*)d_in[13];
    const float* Wf1   = (const float*)d_in[14];
    const float* bf1   = (const float*)d_in[15];
    const float* Wf2   = (const float*)d_in[16];
    const float* bf2   = (const float*)d_in[17];

    const int B = in_sizes[1] / (NTOK * DM);
    const int ngroups = (B + GBA - 1) / GBA;

    int nsm = 148;
    cudaDeviceGetAttribute(&nsm, cudaDevAttrMultiProcessorCount, 0);
    int grid = (nsm < ngroups) ? nsm : ngroups;

    cudaFuncSetAttribute(k_attn_ws, cudaFuncAttributeMaxDynamicSharedMemorySize, WS_SMEM);
    cudaFuncSetAttribute(k_ffn,     cudaFuncAttributeMaxDynamicSharedMemorySize, FB_SMEM);

    k_pre<<<12, 256>>>(query, g1, b1, Wq, bq, Wk, Wv, Wp, Wf1, Wf2);
    k_attn_ws<<<grid, 512, WS_SMEM>>>(tgt, bv, B);
    k_ffn<<<(B + GB - 1)/GB, 256, FB_SMEM>>>(query, bp, g2, b2, bf1, bf2,
                                             (float*)d_out, B);
}

// round 17
// speedup vs baseline: 5.5709x; 1.0270x over previous
#include <cuda_runtime.h>
#include <cuda_bf16.h>

typedef unsigned long long ull;
typedef unsigned int u32;

#define DM   128
#define NTOK 48
#define TS   132
#define SS   49
#define MAXB 16384
#define GBA  6                            // batches per group (attn)

// ---- k_attn_ws smem byte offsets (bf16 rows padded to 272B) ----
#define WS_WEFF 0                         // weff bf16 64x272  = 17408
#define WS_WV   17408                     // Wv  bf16 128x272  = 34816
#define WS_TGT  52224                     // tgt bf16 6x48x272 = 78336
#define WS_P    130560                    // P fp32 2 x 64x49x4  = 25088
#define WS_VP   155648                    // VP fp32 2 x 48x132x4 = 50688
#define WS_SMEM 206336
#define PF(kb)  (32640 + (kb)*3136)       // float index
#define VPF(kb) (38912 + (kb)*6336)

// ---- k_ffn smem byte offsets ----
#define GB 8
#define BROWS 64
#define FB_A   0
#define FB_B   17408
#define FB_X   52224
#define FB_Q   86016
#define FB_C   90112
#define FB_SMEM 92672
#define X_F    13056
#define Q_F    21504
#define C_F    22528

// ---------------- globals ----------------
__device__ __align__(16) u32 g_wvHi [128 * 68];
__device__ __align__(16) u32 g_weffHi[64 * 68];
__device__ __align__(16) u32 g_wpB  [128 * 68];
__device__ __align__(16) u32 g_wf1B [128 * 68];
__device__ __align__(16) u32 g_wf2B [128 * 68];
// x_att in bf16 FFN-tile layout: [B/8 groups][64 rows][68 u32 (272B padded)]
__device__ __align__(16) u32 g_xattB[(size_t)(MAXB/GB) * 64 * 68];

// ---------------- helpers ----------------
__device__ __forceinline__ void ffma2(ull& d, ull a, ull b) {
    asm("fma.rn.f32x2 %0, %1, %2, %0;" : "+l"(d) : "l"(a), "l"(b));
}
__device__ __forceinline__ ull dup2(float x) {
    ull r; asm("mov.b64 %0, {%1, %1};" : "=l"(r) : "f"(x)); return r;
}
__device__ __forceinline__ void unpack2(ull v, float& lo, float& hi) {
    asm("mov.b64 {%0, %1}, %2;" : "=f"(lo), "=f"(hi) : "l"(v));
}
__device__ __forceinline__ u32 smem_u32(const void* p) {
    u32 a; asm("{ .reg .u64 t; cvta.to.shared.u64 t, %1; cvt.u32.u64 %0, t; }" : "=r"(a) : "l"(p));
    return a;
}
__device__ __forceinline__ u32 cvt2(float lo, float hi) {
    u32 r; asm("cvt.rn.bf16x2.f32 %0, %1, %2;" : "=r"(r) : "f"(hi), "f"(lo)); return r;
}
__device__ __forceinline__ void ldsm_x4(u32* r, u32 addr) {
    asm volatile("ldmatrix.sync.aligned.m8n8.x4.shared.b16 {%0,%1,%2,%3}, [%4];"
        : "=r"(r[0]), "=r"(r[1]), "=r"(r[2]), "=r"(r[3]) : "r"(addr));
}
__device__ __forceinline__ void ldsm_x2(u32* r, u32 addr) {
    asm volatile("ldmatrix.sync.aligned.m8n8.x2.shared.b16 {%0,%1}, [%2];"
        : "=r"(r[0]), "=r"(r[1]) : "r"(addr));
}
__device__ __forceinline__ void mma_bf16(float* d, const u32* a, const u32* b) {
    asm volatile("mma.sync.aligned.m16n8k16.row.col.f32.bf16.bf16.f32 "
        "{%0,%1,%2,%3}, {%4,%5,%6,%7}, {%8,%9}, {%0,%1,%2,%3};"
        : "+f"(d[0]), "+f"(d[1]), "+f"(d[2]), "+f"(d[3])
        : "r"(a[0]), "r"(a[1]), "r"(a[2]), "r"(a[3]), "r"(b[0]), "r"(b[1]));
}
__device__ __forceinline__ void gemm_mma(float acc[8][4], u32 aAddr, u32 bAddr) {
    #pragma unroll
    for (int n = 0; n < 8; n++)
        #pragma unroll
        for (int e = 0; e < 4; e++) acc[n][e] = 0.f;
    #pragma unroll
    for (int k = 0; k < 8; k++) {
        u32 a[4];
        ldsm_x4(a, aAddr + k*32);
        #pragma unroll
        for (int nt = 0; nt < 8; nt++) {
            u32 bb[2];
            ldsm_x2(bb, bAddr + nt*2176 + k*32);
            mma_bf16(acc[nt], a, bb);
        }
    }
}
#define NB_SYNC(id, cnt)   asm volatile("bar.sync %0, %1;" :: "r"(id), "r"(cnt) : "memory")
#define NB_ARRIVE(id, cnt) asm volatile("bar.arrive %0, %1;" :: "r"(id), "r"(cnt) : "memory")

// =====================================================================
// k_pre, 12 blocks (unchanged from R16)
// =====================================================================
__global__ void k_pre(const float* __restrict__ q, const float* __restrict__ g1,
                      const float* __restrict__ b1, const float* __restrict__ Wq,
                      const float* __restrict__ bq, const float* __restrict__ Wk,
                      const float* __restrict__ Wv, const float* __restrict__ Wp,
                      const float* __restrict__ Wf1, const float* __restrict__ Wf2)
{
    const int tid = threadIdx.x;
    const int bi  = blockIdx.x;
    if (bi < 8) {
        __shared__ float qn[8][DM];
        __shared__ float q0s[8][DM];
        const int w = tid >> 5, lane = tid & 31;
        {
            float4 v = *(const float4*)(q + w*DM + lane*4);
            float s  = v.x + v.y + v.z + v.w;
            float sq = v.x*v.x + v.y*v.y + v.z*v.z + v.w*v.w;
            #pragma unroll
            for (int o = 16; o > 0; o >>= 1) {
                s  += __shfl_xor_sync(0xffffffffu, s,  o);
                sq += __shfl_xor_sync(0xffffffffu, sq, o);
            }
            float m = s * (1.f/DM);
            float var = sq * (1.f/DM) - m*m;
            float rs = rsqrtf(var + 1e-5f);
            const int c = lane*4;
            qn[w][c+0] = (v.x - m)*rs*g1[c+0] + b1[c+0];
            qn[w][c+1] = (v.y - m)*rs*g1[c+1] + b1[c+1];
            qn[w][c+2] = (v.z - m)*rs*g1[c+2] + b1[c+2];
            qn[w][c+3] = (v.w - m)*rs*g1[c+3] + b1[c+3];
        }
        __syncthreads();
        for (int o = tid; o < 8*DM; o += 256) {
            int r = o >> 7, c = o & 127;
            float a = bq[c];
            const float4* wr = (const float4*)(Wq + c*DM);
            #pragma unroll 8
            for (int t4 = 0; t4 < 32; t4++) {
                float4 ww = wr[t4];
                a += qn[r][t4*4+0]*ww.x + qn[r][t4*4+1]*ww.y
                   + qn[r][t4*4+2]*ww.z + qn[r][t4*4+3]*ww.w;
            }
            q0s[r][c] = a;
        }
        __syncthreads();
        for (int o = tid; o < 8*64; o += 256) {
            int p  = bi*8 + (o >> 6);
            int tp = o & 63;
            int r = p >> 3, h = p & 7;
            float a0 = 0.f, a1 = 0.f;
            #pragma unroll
            for (int d = 0; d < 16; d++) {
                float qd = q0s[r][h*16 + d];
                a0 += qd * Wk[(h*16 + d)*DM + 2*tp];
                a1 += qd * Wk[(h*16 + d)*DM + 2*tp + 1];
            }
            g_weffHi[p*68 + tp] = cvt2(0.25f*a0, 0.25f*a1);
        }
    } else {
        const float* src; u32* dst;
        switch (bi) {
            case 8:  src = Wp;  dst = g_wpB;  break;
            case 9:  src = Wf1; dst = g_wf1B; break;
            case 10: src = Wf2; dst = g_wf2B; break;
            default: src = Wv;  dst = g_wvHi; break;
        }
        for (int o = tid; o < 128*64; o += 256) {
            int r = o >> 6, tp = o & 63;
            dst[r*68 + tp] = cvt2(src[r*DM + tp*2], src[r*DM + tp*2 + 1]);
        }
    }
}

// =====================================================================
// k_attn_ws: persistent, 768 threads. Consumers warps 0-7; producer
// team0 = warps 8-15 (even its), team1 = warps 16-23 (odd its).
// Each team owns buffer kb == team. Weights staged once per CTA.
// =====================================================================
__global__ __launch_bounds__(768, 1)
void k_attn_ws(const float* __restrict__ tgt, const float* __restrict__ bv, int Bn)
{
    extern __shared__ float smf[];
    char* smc = (char*)smf;
    const u32 smb = smem_u32(smf);
    const int tid = threadIdx.x;
    const int wid = tid >> 5, lane = tid & 31;
    const int ngroups = (Bn + GBA - 1) / GBA;

    // -------- stage weights once --------
    {
        const float4* we = (const float4*)g_weffHi;
        float4* dE = (float4*)(smc + WS_WEFF);
        #pragma unroll
        for (int kk = 0; kk < 2; kk++) {
            int i = tid + kk*768;
            if (i < 1088) dE[i] = we[i];
        }
        const float4* wh = (const float4*)g_wvHi;
        float4* dH = (float4*)(smc + WS_WV);
        #pragma unroll
        for (int kk = 0; kk < 3; kk++) {
            int i = tid + kk*768;
            if (i < 2176) dH[i] = wh[i];
        }
    }

    const int team = (wid >= 16) ? 1 : 0;     // producer team (wid>=8 only)
    int it = 0;                               // global iteration counter
    int tl = 0;                               // team-local produced count
    for (int g = blockIdx.x; g < ngroups; g += gridDim.x) {
        const int gb0 = g * GBA;

        // -------- stage tgt for this group (all 768) --------
        __syncthreads();
        {
            const float4* src = (const float4*)(tgt + (size_t)gb0 * NTOK * DM);
            #pragma unroll
            for (int kk = 0; kk < 12; kk++) {
                int i = tid + kk*768;                 // 0..9215
                int b4 = i / 1536;
                int rem = i - b4*1536;
                int row = rem >> 5, c = (rem & 31) * 4;
                float4 v = make_float4(0.f, 0.f, 0.f, 0.f);
                if (gb0 + b4 < Bn) v = src[i];
                u32 off = (u32)(WS_TGT + b4*13056 + row*272 + c*2);
                *(u32*)(smc + off)     = cvt2(v.x, v.y);
                *(u32*)(smc + off + 4) = cvt2(v.z, v.w);
            }
        }
        __syncthreads();

        #pragma unroll 1
        for (int b = 0; b < GBA; b++, it++) {
            const int kb = it & 1;
            const int pf  = PF(kb);
            const int vpf = VPF(kb);

            if (wid >= 8) {
                // ================= PRODUCER (acting team only) =================
                if (kb == team) {
                    const int pw = wid & 7;
                    if (pw < 6) {
                        const int mt = pw >> 1;
                        const int nh = pw & 1;
                        float accV[8][4];
                        const u32 aH = smb + WS_TGT + b*13056 + (mt*16 + (lane & 15))*272 + (lane >> 4)*16;
                        const u32 bH = smb + WS_WV + nh*8*2176 + (lane & 7)*272 + ((lane >> 3) & 1)*16;
                        gemm_mma(accV, aH, bH);
                        if (tl >= 1) NB_SYNC(3 + kb, 512);
                        const int r0 = mt*16 + (lane >> 2);
                        const int c0 = nh*64 + (lane & 3)*2;
                        #pragma unroll
                        for (int nt = 0; nt < 8; nt++) {
                            const int c = c0 + nt*8;
                            float bv0 = bv[c], bv1 = bv[c+1];
                            smf[vpf + r0*TS + c]       = accV[nt][0] + bv0;
                            smf[vpf + r0*TS + c + 1]   = accV[nt][1] + bv1;
                            smf[vpf + (r0+8)*TS + c]   = accV[nt][2] + bv0;
                            smf[vpf + (r0+8)*TS + c+1] = accV[nt][3] + bv1;
                        }
                    } else {
                        const int wi = pw - 6;
                        float accS[2][6][4];
                        #pragma unroll
                        for (int i = 0; i < 2; i++)
                            #pragma unroll
                            for (int n = 0; n < 6; n++)
                                #pragma unroll
                                for (int e = 0; e < 4; e++) accS[i][n][e] = 0.f;
                        const u32 a0 = smb + WS_WEFF + (wi*32 + (lane & 15))*272 + (lane >> 4)*16;
                        const u32 a1 = a0 + 16*272;
                        const u32 bH = smb + WS_TGT + b*13056 + (lane & 7)*272 + ((lane >> 3) & 1)*16;
                        #pragma unroll
                        for (int k = 0; k < 8; k++) {
                            u32 aA[4], aB[4];
                            ldsm_x4(aA, a0 + k*32);
                            ldsm_x4(aB, a1 + k*32);
                            #pragma unroll
                            for (int nt = 0; nt < 6; nt++) {
                                u32 bh[2];
                                ldsm_x2(bh, bH + nt*2176 + k*32);
                                mma_bf16(accS[0][nt], aA, bh);
                                mma_bf16(accS[1][nt], aB, bh);
                            }
                        }
                        if (tl >= 1) NB_SYNC(3 + kb, 512);
                        #pragma unroll
                        for (int i = 0; i < 2; i++) {
                            const int r0 = (wi*2 + i)*16 + (lane >> 2);
                            #pragma unroll
                            for (int nt = 0; nt < 6; nt++) {
                                const int c = nt*8 + (lane & 3)*2;
                                smf[pf + r0*SS + c]       = accS[i][nt][0];
                                smf[pf + r0*SS + c + 1]   = accS[i][nt][1];
                                smf[pf + (r0+8)*SS + c]   = accS[i][nt][2];
                                smf[pf + (r0+8)*SS + c+1] = accS[i][nt][3];
                            }
                        }
                    }
                    NB_ARRIVE(1 + kb, 512);
                    tl++;
                }
            } else {
                // ================= CONSUMER =================
                NB_SYNC(1 + kb, 512);

                // softmax
                {
                    const int p = tid >> 2, qq = tid & 3;
                    float* row = smf + pf + p*SS;
                    if (p < 16) {
                        const int j0 = qq*12;
                        float e[12];
                        float mx = -1e30f;
                        #pragma unroll
                        for (int m = 0; m < 12; m++) { e[m] = row[j0+m]; mx = fmaxf(mx, e[m]); }
                        mx = fmaxf(mx, __shfl_xor_sync(0xffffffffu, mx, 1));
                        mx = fmaxf(mx, __shfl_xor_sync(0xffffffffu, mx, 2));
                        float sum = 0.f;
                        #pragma unroll
                        for (int m = 0; m < 12; m++) { e[m] = __expf(e[m]-mx); sum += e[m]; }
                        sum += __shfl_xor_sync(0xffffffffu, sum, 1);
                        sum += __shfl_xor_sync(0xffffffffu, sum, 2);
                        float inv = 1.f / sum;
                        #pragma unroll
                        for (int m = 0; m < 12; m++) row[j0+m] = e[m]*inv;
                    } else if (qq == 0) {
                        const int r = p >> 3;
                        const int wi = r - 2;
                        const int hw = (wi/3)*4, ww = (wi%3)*2;
                        float e[8];
                        float mx = -1e30f;
                        #pragma unroll
                        for (int m = 0; m < 8; m++) {
                            const int j = (hw + (m>>1))*6 + ww + (m&1);
                            e[m] = row[j];
                            mx = fmaxf(mx, e[m]);
                        }
                        float sum = 0.f;
                        #pragma unroll
                        for (int m = 0; m < 8; m++) { e[m] = __expf(e[m]-mx); sum += e[m]; }
                        float inv = 1.f / sum;
                        #pragma unroll
                        for (int m = 0; m < 8; m++) {
                            const int j = (hw + (m>>1))*6 + ww + (m&1);
                            row[j] = e[m]*inv;
                        }
                    }
                }
                NB_SYNC(5, 256);

                // x_att: warp = output row r; split accumulator chains;
                // store bf16 directly into FFN-tile layout.
                {
                    const int r   = wid;
                    const int col = lane * 4;
                    const int h   = lane >> 2;
                    const float* Pb = smf + pf + (r*8 + h)*SS;
                    ull a01a = 0ull, a23a = 0ull, a01b = 0ull, a23b = 0ull;
                    if (r < 2) {
                        for (int j = 0; j < NTOK; j += 2) {
                            ull f0 = dup2(Pb[j]);
                            ull f1 = dup2(Pb[j+1]);
                            ulonglong2 u0 = *(const ulonglong2*)(smf + vpf + j*TS + col);
                            ulonglong2 u1 = *(const ulonglong2*)(smf + vpf + (j+1)*TS + col);
                            ffma2(a01a, f0, u0.x); ffma2(a23a, f0, u0.y);
                            ffma2(a01b, f1, u1.x); ffma2(a23b, f1, u1.y);
                        }
                    } else {
                        const int wi = r - 2;
                        const int hw = (wi/3)*4, ww = (wi%3)*2;
                        #pragma unroll
                        for (int m = 0; m < 8; m += 2) {
                            const int j0 = (hw + (m>>1))*6 + ww + (m&1);
                            const int j1 = (hw + ((m+1)>>1))*6 + ww + ((m+1)&1);
                            ull f0 = dup2(Pb[j0]);
                            ull f1 = dup2(Pb[j1]);
                            ulonglong2 u0 = *(const ulonglong2*)(smf + vpf + j0*TS + col);
                            ulonglong2 u1 = *(const ulonglong2*)(smf + vpf + j1*TS + col);
                            ffma2(a01a, f0, u0.x); ffma2(a23a, f0, u0.y);
                            ffma2(a01b, f1, u1.x); ffma2(a23b, f1, u1.y);
                        }
                    }
                    const int bb = gb0 + b;
                    if (bb < Bn) {
                        float l0a, h0a, l1a, h1a, l0b, h0b, l1b, h1b;
                        unpack2(a01a, l0a, h0a); unpack2(a23a, l1a, h1a);
                        unpack2(a01b, l0b, h0b); unpack2(a23b, l1b, h1b);
                        u32 p0 = cvt2(l0a + l0b, h0a + h0b);
                        u32 p1 = cvt2(l1a + l1b, h1a + h1b);
                        u32* dst = g_xattB + (size_t)(bb >> 3)*4352
                                 + ((bb & 7)*8 + r)*68 + lane*2;
                        dst[0] = p0;
                        dst[1] = p1;
                    }
                }
                NB_ARRIVE(3 + kb, 512);
            }
        }
    }
}

// =====================================================================
// k_ffn: GB=8 batches/CTA, 2 CTAs/SM. Three bf16 mma.sync GEMMs.
// x_att now staged by raw copy (already bf16 tile format).
// =====================================================================
__global__ __launch_bounds__(256, 2)
void k_ffn(const float* __restrict__ query, const float* __restrict__ bp,
           const float* __restrict__ g2, const float* __restrict__ b2,
           const float* __restrict__ bf1, const float* __restrict__ bf2,
           float* __restrict__ out, int Bn)
{
    extern __shared__ float smf[];
    char* smc = (char*)smf;
    const u32 smb = smem_u32(smf);
    const int tid  = threadIdx.x;
    const int wid  = tid >> 5;
    const int lane = tid & 31;
    const int b0   = blockIdx.x * GB;
    const int rows_valid = (Bn - b0 >= GB) ? BROWS : (Bn - b0) * 8;

    const int mt = wid >> 1, nh = wid & 1;
    const u32 aAddr = smb + FB_A + (mt*16 + (lane & 15))*272 + (lane >> 4)*16;
    const u32 bAddr = smb + FB_B + nh*8*2176 + (lane & 7)*272 + ((lane >> 3) & 1)*16;
    const int r0 = mt*16 + (lane >> 2);
    const int c0 = nh*64 + (lane & 3)*2;

    {
        const float4* src = (const float4*)(g_xattB + (size_t)blockIdx.x * 4352);
        float4* dA = (float4*)(smc + FB_A);
        #pragma unroll
        for (int k = 0; k < 5; k++) {
            int i = tid + k*256;
            if (i < 1088) dA[i] = src[i];
        }
        const float4* wb = (const float4*)g_wpB;
        float4* dB = (float4*)(smc + FB_B);
        #pragma unroll
        for (int k = 0; k < 9; k++) {
            int i = tid + k*256;
            if (i < 2176) dB[i] = wb[i];
        }
        ((float4*)(smc + FB_Q))[tid] = ((const float4*)query)[tid];
        if (tid < 128) {
            smf[C_F +       tid] = bp [tid];
            smf[C_F + 128 + tid] = g2 [tid];
            smf[C_F + 256 + tid] = b2 [tid];
            smf[C_F + 384 + tid] = bf1[tid];
            smf[C_F + 512 + tid] = bf2[tid];
        }
    }
    __syncthreads();

    {
        float acc[8][4];
        gemm_mma(acc, aAddr, bAddr);
        #pragma unroll
        for (int nt = 0; nt < 8; nt++) {
            const int c = c0 + nt*8;
            float q0a = smf[Q_F + (r0 & 7)*DM + c];
            float q1a = smf[Q_F + (r0 & 7)*DM + c + 1];
            float q0b = smf[Q_F + ((r0+8) & 7)*DM + c];
            float q1b = smf[Q_F + ((r0+8) & 7)*DM + c + 1];
            float bp0 = smf[C_F + c], bp1 = smf[C_F + c + 1];
            smf[X_F + r0*TS + c]       = q0a + bp0 + acc[nt][0];
            smf[X_F + r0*TS + c + 1]   = q1a + bp1 + acc[nt][1];
            smf[X_F + (r0+8)*TS + c]   = q0b + bp0 + acc[nt][2];
            smf[X_F + (r0+8)*TS + c+1] = q1b + bp1 + acc[nt][3];
        }
    }
    __syncthreads();

    {
        #pragma unroll
        for (int r = 0; r < 8; r++) {
            const int row = wid*8 + r;
            const float* xr = smf + X_F + row*TS + lane*4;
            float v0 = xr[0], v1 = xr[1], v2 = xr[2], v3 = xr[3];
            float sum = v0+v1+v2+v3;
            float sq  = v0*v0+v1*v1+v2*v2+v3*v3;
            #pragma unroll
            for (int o = 16; o > 0; o >>= 1) {
                sum += __shfl_xor_sync(0xffffffffu, sum, o);
                sq  += __shfl_xor_sync(0xffffffffu, sq,  o);
            }
            float m   = sum * (1.f/DM);
            float var = sq * (1.f/DM) - m*m;
            float rs  = rsqrtf(var + 1e-5f);
            const int c = lane*4;
            float n0 = (v0 - m)*rs*smf[C_F + 128 + c  ] + smf[C_F + 256 + c  ];
            float n1 = (v1 - m)*rs*smf[C_F + 128 + c+1] + smf[C_F + 256 + c+1];
            float n2 = (v2 - m)*rs*smf[C_F + 128 + c+2] + smf[C_F + 256 + c+2];
            float n3 = (v3 - m)*rs*smf[C_F + 128 + c+3] + smf[C_F + 256 + c+3];
            u32 off = row*272 + c*2;
            *(u32*)(smc + FB_A + off)     = cvt2(n0, n1);
            *(u32*)(smc + FB_A + off + 4) = cvt2(n2, n3);
        }
        const float4* wb = (const float4*)g_wf1B;
        float4* dB = (float4*)(smc + FB_B);
        #pragma unroll
        for (int k = 0; k < 9; k++) {
            int i = tid + k*256;
            if (i < 2176) dB[i] = wb[i];
        }
    }
    __syncthreads();

    {
        float acc[8][4];
        gemm_mma(acc, aAddr, bAddr);
        __syncthreads();
        #pragma unroll
        for (int nt = 0; nt < 8; nt++) {
            const int c = c0 + nt*8;
            float bf1a = smf[C_F + 384 + c], bf1b = smf[C_F + 384 + c + 1];
            float z0 = acc[nt][0] + bf1a;
            float z1 = acc[nt][1] + bf1b;
            float z2 = acc[nt][2] + bf1a;
            float z3 = acc[nt][3] + bf1b;
            float h0 = 0.5f * z0 * (1.f + erff(z0 * 0.7071067811865476f));
            float h1 = 0.5f * z1 * (1.f + erff(z1 * 0.7071067811865476f));
            float h2 = 0.5f * z2 * (1.f + erff(z2 * 0.7071067811865476f));
            float h3 = 0.5f * z3 * (1.f + erff(z3 * 0.7071067811865476f));
            *(u32*)(smc + FB_A + r0*272 + c*2)     = cvt2(h0, h1);
            *(u32*)(smc + FB_A + (r0+8)*272 + c*2) = cvt2(h2, h3);
        }
        const float4* wb = (const float4*)g_wf2B;
        float4* dB = (float4*)(smc + FB_B);
        #pragma unroll
        for (int k = 0; k < 9; k++) {
            int i = tid + k*256;
            if (i < 2176) dB[i] = wb[i];
        }
    }
    __syncthreads();

    {
        float acc[8][4];
        gemm_mma(acc, aAddr, bAddr);
        #pragma unroll
        for (int nt = 0; nt < 8; nt++) {
            const int c = c0 + nt*8;
            float bf2a = smf[C_F + 512 + c], bf2b = smf[C_F + 512 + c + 1];
            if (r0 < rows_valid) {
                float2 res;
                res.x = smf[X_F + r0*TS + c]     + bf2a + acc[nt][0];
                res.y = smf[X_F + r0*TS + c + 1] + bf2b + acc[nt][1];
                *(float2*)(out + ((size_t)b0*8 + r0)*DM + c) = res;
            }
            if (r0 + 8 < rows_valid) {
                float2 res;
                res.x = smf[X_F + (r0+8)*TS + c]     + bf2a + acc[nt][2];
                res.y = smf[X_F + (r0+8)*TS + c + 1] + bf2b + acc[nt][3];
                *(float2*)(out + ((size_t)b0*8 + r0 + 8)*DM + c) = res;
            }
        }
    }
}

// =====================================================================
extern "C" void kernel_launch(void* const* d_in, const int* in_sizes, int n_in,
                              void* d_out, int out_size)
{
    const float* query = (const float*)d_in[0];
    const float* tgt   = (const float*)d_in[1];
    const float* g1    = (const float*)d_in[2];
    const float* b1    = (const float*)d_in[3];
    const float* Wq    = (const float*)d_in[4];
    const float* bq    = (const float*)d_in[5];
    const float* Wk    = (const float*)d_in[6];
    // d_in[7] = bk: drops out (softmax shift invariance)
    const float* Wv    = (const float*)d_in[8];
    const float* bv    = (const float*)d_in[9];
    const float* Wp    = (const float*)d_in[10];
    const float* bp    = (const float*)d_in[11];
    const float* g2    = (const float*)d_in[12];
    const float* b2    = (const float*)d_in[13];
    const float* Wf1   = (const float*)d_in[14];
    const float* bf1   = (const float*)d_in[15];
    const float* Wf2   = (const float*)d_in[16];
    const float* bf2   = (const float*)d_in[17];

    const int B = in_sizes[1] / (NTOK * DM);
    const int ngroups = (B + GBA - 1) / GBA;

    int nsm = 148;
    cudaDeviceGetAttribute(&nsm, cudaDevAttrMultiProcessorCount, 0);
    int grid = (nsm < ngroups) ? nsm : ngroups;

    cudaFuncSetAttribute(k_attn_ws, cudaFuncAttributeMaxDynamicSharedMemorySize, WS_SMEM);
    cudaFuncSetAttribute(k_ffn,     cudaFuncAttributeMaxDynamicSharedMemorySize, FB_SMEM);

    k_pre<<<12, 256>>>(query, g1, b1, Wq, bq, Wk, Wv, Wp, Wf1, Wf2);
    k_attn_ws<<<grid, 768, WS_SMEM>>>(tgt, bv, B);
    k_ffn<<<(B + GB - 1)/GB, 256, FB_SMEM>>>(query, bp, g2, b2, bf1, bf2,
                                             (float*)d_out, B);
}